// round 3
// baseline (speedup 1.0000x reference)
#include <cuda_runtime.h>

// Problem constants (B=1 fixed)
#define T_SEQ 4096
#define NHEAD 12
#define HD    64
#define CDIM  768   // NHEAD*HD

// Scratch (no cudaMalloc allowed)
__device__ float g_qkv[T_SEQ * 3 * CDIM];      // 37.7 MB
__device__ float g_q[NHEAD * T_SEQ * HD];      // normalized q, [h][t][d]
__device__ float g_k[NHEAD * T_SEQ * HD];      // normalized k
__device__ float g_v[NHEAD * T_SEQ * HD];
__device__ float g_y[T_SEQ * CDIM];            // attention out, [t][c]

// ---------------------------------------------------------------------------
// Generic fp32 GEMM + bias: C[M,N] = A[M,K] @ B[K,N] + bias[N]
// 64x64 block, BK=16, 256 threads, 4x4 per thread. All dims divisible.
// ---------------------------------------------------------------------------
__global__ __launch_bounds__(256) void sgemm_bias(
    const float* __restrict__ A, const float* __restrict__ B,
    const float* __restrict__ bias, float* __restrict__ C,
    int M, int N, int K)
{
  __shared__ float As[64 * 17];   // [m][kk], stride 17 (bank-friendly)
  __shared__ float Bs[16 * 68];   // [kk][n], stride 68 (aligned float4, conflict-free)
  const int tid = threadIdx.x;
  const int tx = tid & 15, ty = tid >> 4;
  const int m0 = blockIdx.y << 6, n0 = blockIdx.x << 6;
  const int am = tid >> 2, ac = (tid & 3) << 2;
  const int br = tid >> 4, bc = (tid & 15) << 2;

  float acc[4][4] = {};

  for (int k0 = 0; k0 < K; k0 += 16) {
    float4 a4 = *(const float4*)&A[(size_t)(m0 + am) * K + k0 + ac];
    float4 b4 = *(const float4*)&B[(size_t)(k0 + br) * N + n0 + bc];
    __syncthreads();
    As[am * 17 + ac + 0] = a4.x;
    As[am * 17 + ac + 1] = a4.y;
    As[am * 17 + ac + 2] = a4.z;
    As[am * 17 + ac + 3] = a4.w;
    *(float4*)&Bs[br * 68 + bc] = b4;
    __syncthreads();
#pragma unroll
    for (int kk = 0; kk < 16; ++kk) {
      float av[4];
#pragma unroll
      for (int i = 0; i < 4; ++i) av[i] = As[(4 * ty + i) * 17 + kk];
      float4 bv = *(float4*)&Bs[kk * 68 + 4 * tx];
#pragma unroll
      for (int i = 0; i < 4; ++i) {
        acc[i][0] = fmaf(av[i], bv.x, acc[i][0]);
        acc[i][1] = fmaf(av[i], bv.y, acc[i][1]);
        acc[i][2] = fmaf(av[i], bv.z, acc[i][2]);
        acc[i][3] = fmaf(av[i], bv.w, acc[i][3]);
      }
    }
  }

  float4 bb = *(const float4*)&bias[n0 + 4 * tx];
#pragma unroll
  for (int i = 0; i < 4; ++i) {
    float4 o = make_float4(acc[i][0] + bb.x, acc[i][1] + bb.y,
                           acc[i][2] + bb.z, acc[i][3] + bb.w);
    *(float4*)&C[(size_t)(m0 + 4 * ty + i) * N + n0 + 4 * tx] = o;
  }
}

// ---------------------------------------------------------------------------
// Normalize q,k rows (per head, 64 dims) + reshape [t][3C] -> [h][t][d]
// One warp per (t,h) row.
// ---------------------------------------------------------------------------
__global__ __launch_bounds__(256) void norm_reshape(
    const float* __restrict__ qkv,
    float* __restrict__ Q, float* __restrict__ K, float* __restrict__ V)
{
  const unsigned FULL = 0xffffffffu;
  int w = (blockIdx.x * 256 + threadIdx.x) >> 5;   // 0 .. 49151
  int lane = threadIdx.x & 31;
  if (w >= NHEAD * T_SEQ) return;
  int t = w / NHEAD, h = w % NHEAD;
  const float* src = qkv + (size_t)t * (3 * CDIM) + h * HD;
  size_t dst = ((size_t)h * T_SEQ + t) * HD + 2 * lane;

  // q
  {
    float2 a = *(const float2*)&src[2 * lane];
    float ss = a.x * a.x + a.y * a.y;
#pragma unroll
    for (int off = 16; off; off >>= 1) ss += __shfl_xor_sync(FULL, ss, off);
    float inv = 1.0f / fmaxf(sqrtf(ss), 1e-12f);
    *(float2*)&Q[dst] = make_float2(a.x * inv, a.y * inv);
  }
  // k
  {
    float2 a = *(const float2*)&src[CDIM + 2 * lane];
    float ss = a.x * a.x + a.y * a.y;
#pragma unroll
    for (int off = 16; off; off >>= 1) ss += __shfl_xor_sync(FULL, ss, off);
    float inv = 1.0f / fmaxf(sqrtf(ss), 1e-12f);
    *(float2*)&K[dst] = make_float2(a.x * inv, a.y * inv);
  }
  // v (plain copy)
  *(float2*)&V[dst] = *(const float2*)&src[2 * CDIM + 2 * lane];
}

// ---------------------------------------------------------------------------
// Fused cumulative linear attention.
// Grid (T/64, H). 256 threads. Per key tile of 64:
//   A : S = Q_tile @ K_tile^T      (4x4 register tiling)
//   B1: per-row warp scan -> denom carry across tiles -> W = S/max(cum,1e-6)
//   B2: Y += W @ V_tile            (4x4 register tiling, Y in registers)
// ---------------------------------------------------------------------------
__global__ __launch_bounds__(256) void attn_kernel(
    const float* __restrict__ Q, const float* __restrict__ K,
    const float* __restrict__ V, float* __restrict__ Y)
{
  extern __shared__ float sm[];
  float* Qs = sm;                  // [64][65] row-major
  float* Ks = sm + 64 * 65;        // [64][65]
  float* Vs = sm + 2 * 64 * 65;    // [64][65]
  float* Ws = sm + 3 * 64 * 65;    // [64][68]  S tile, overwritten by W in B1

  const unsigned FULL = 0xffffffffu;
  const int h = blockIdx.y;
  const int q0 = blockIdx.x << 6;
  const int tid = threadIdx.x;
  const int lane = tid & 31, wid = tid >> 5;
  const int tx = tid & 15, ty = tid >> 4;

  const float* Qh = Q + (size_t)h * T_SEQ * HD;
  const float* Kh = K + (size_t)h * T_SEQ * HD;
  const float* Vh = V + (size_t)h * T_SEQ * HD;

  // Load Q tile once
#pragma unroll
  for (int it = 0; it < 4; ++it) {
    int idx = tid + it * 256;
    int r = idx >> 4;
    int c = (idx & 15) << 2;
    float4 v4 = *(const float4*)&Qh[(size_t)(q0 + r) * HD + c];
    Qs[r * 65 + c + 0] = v4.x;
    Qs[r * 65 + c + 1] = v4.y;
    Qs[r * 65 + c + 2] = v4.z;
    Qs[r * 65 + c + 3] = v4.w;
  }

  float yacc[4][4] = {};
  float carry[8] = {};   // running cumsum per owned row (warp wid owns rows wid*8..wid*8+7)

  for (int k0 = 0; k0 < T_SEQ; k0 += 64) {
    __syncthreads();   // protect Ks/Vs/Ws from previous iteration's readers
    // Load K, V tiles
#pragma unroll
    for (int it = 0; it < 4; ++it) {
      int idx = tid + it * 256;
      int r = idx >> 4;
      int c = (idx & 15) << 2;
      float4 k4 = *(const float4*)&Kh[(size_t)(k0 + r) * HD + c];
      Ks[r * 65 + c + 0] = k4.x;
      Ks[r * 65 + c + 1] = k4.y;
      Ks[r * 65 + c + 2] = k4.z;
      Ks[r * 65 + c + 3] = k4.w;
      float4 v4 = *(const float4*)&Vh[(size_t)(k0 + r) * HD + c];
      Vs[r * 65 + c + 0] = v4.x;
      Vs[r * 65 + c + 1] = v4.y;
      Vs[r * 65 + c + 2] = v4.z;
      Vs[r * 65 + c + 3] = v4.w;
    }
    __syncthreads();

    // Phase A: S = Q K^T
    {
      float sacc[4][4] = {};
#pragma unroll 8
      for (int kk = 0; kk < 64; ++kk) {
        float qv[4], kv[4];
#pragma unroll
        for (int i = 0; i < 4; ++i) qv[i] = Qs[(4 * ty + i) * 65 + kk];
#pragma unroll
        for (int j = 0; j < 4; ++j) kv[j] = Ks[(4 * tx + j) * 65 + kk];
#pragma unroll
        for (int i = 0; i < 4; ++i)
#pragma unroll
          for (int j = 0; j < 4; ++j)
            sacc[i][j] = fmaf(qv[i], kv[j], sacc[i][j]);
      }
#pragma unroll
      for (int i = 0; i < 4; ++i)
        *(float4*)&Ws[(4 * ty + i) * 68 + 4 * tx] =
            make_float4(sacc[i][0], sacc[i][1], sacc[i][2], sacc[i][3]);
    }
    __syncthreads();

    // Phase B1: per-row inclusive scan + divide (W = S / max(cumsum, 1e-6))
#pragma unroll
    for (int rr = 0; rr < 8; ++rr) {
      int qrow = wid * 8 + rr;
      float2 s = *(float2*)&Ws[qrow * 68 + 2 * lane];
      float run = s.x + s.y;
#pragma unroll
      for (int off = 1; off < 32; off <<= 1) {
        float n = __shfl_up_sync(FULL, run, off);
        if (lane >= off) run += n;
      }
      float c1 = carry[rr] + run;       // cumsum through element 2*lane+1
      float c0 = c1 - s.y;              // cumsum through element 2*lane
      float w0 = __fdividef(s.x, fmaxf(c0, 1e-6f));
      float w1 = __fdividef(s.y, fmaxf(c1, 1e-6f));
      carry[rr] += __shfl_sync(FULL, run, 31);
      *(float2*)&Ws[qrow * 68 + 2 * lane] = make_float2(w0, w1);
    }
    __syncthreads();

    // Phase B2: Y += W @ V
#pragma unroll 8
    for (int jj = 0; jj < 64; ++jj) {
      float wv[4], vv[4];
#pragma unroll
      for (int i = 0; i < 4; ++i) wv[i] = Ws[(4 * ty + i) * 68 + jj];
#pragma unroll
      for (int c = 0; c < 4; ++c) vv[c] = Vs[jj * 65 + 4 * tx + c];
#pragma unroll
      for (int i = 0; i < 4; ++i)
#pragma unroll
        for (int c = 0; c < 4; ++c)
          yacc[i][c] = fmaf(wv[i], vv[c], yacc[i][c]);
    }
  }

  // Write Y in [t][C] layout for the projection GEMM
#pragma unroll
  for (int i = 0; i < 4; ++i) {
    *(float4*)&Y[(size_t)(q0 + 4 * ty + i) * CDIM + h * HD + 4 * tx] =
        make_float4(yacc[i][0], yacc[i][1], yacc[i][2], yacc[i][3]);
  }
}

// ---------------------------------------------------------------------------
extern "C" void kernel_launch(void* const* d_in, const int* in_sizes, int n_in,
                              void* d_out, int out_size)
{
  const float* x      = (const float*)d_in[0];
  const float* w_attn = (const float*)d_in[1];
  const float* b_attn = (const float*)d_in[2];
  const float* w_proj = (const float*)d_in[3];
  const float* b_proj = (const float*)d_in[4];
  float* out = (float*)d_out;

  float *qkv, *q, *k, *v, *y;
  cudaGetSymbolAddress((void**)&qkv, g_qkv);
  cudaGetSymbolAddress((void**)&q,   g_q);
  cudaGetSymbolAddress((void**)&k,   g_k);
  cudaGetSymbolAddress((void**)&v,   g_v);
  cudaGetSymbolAddress((void**)&y,   g_y);

  const int ATTN_SMEM = (3 * 64 * 65 + 64 * 68) * 4;   // 67328 bytes
  cudaFuncSetAttribute(attn_kernel,
                       cudaFuncAttributeMaxDynamicSharedMemorySize, ATTN_SMEM);

  // 1) qkv = x @ w_attn + b_attn
  sgemm_bias<<<dim3(3 * CDIM / 64, T_SEQ / 64), 256>>>(
      x, w_attn, b_attn, qkv, T_SEQ, 3 * CDIM, CDIM);

  // 2) normalize q,k per head + reshape to [h][t][d]
  norm_reshape<<<(NHEAD * T_SEQ) / 8, 256>>>(qkv, q, k, v);

  // 3) fused cumulative linear attention
  attn_kernel<<<dim3(T_SEQ / 64, NHEAD), 256, ATTN_SMEM>>>(q, k, v, y);

  // 4) out = y @ w_proj + b_proj
  sgemm_bias<<<dim3(CDIM / 64, T_SEQ / 64), 256>>>(
      y, w_proj, b_proj, out, T_SEQ, CDIM, CDIM);
}

// round 5
// speedup vs baseline: 1.1635x; 1.1635x over previous
#include <cuda_runtime.h>

#define T_SEQ 4096
#define NHEAD 12
#define HD    64
#define CDIM  768

typedef unsigned long long u64;

// ---- packed f32x2 helpers (sm_100+) --------------------------------------
__device__ __forceinline__ u64 dup2(float x) {
  u64 r; asm("mov.b64 %0, {%1, %1};" : "=l"(r) : "f"(x)); return r;
}
__device__ __forceinline__ u64 pack2(float x, float y) {
  u64 r; asm("mov.b64 %0, {%1, %2};" : "=l"(r) : "f"(x), "f"(y)); return r;
}
__device__ __forceinline__ float2 unpack2(u64 v) {
  float2 f; asm("mov.b64 {%0, %1}, %2;" : "=f"(f.x), "=f"(f.y) : "l"(v)); return f;
}
__device__ __forceinline__ u64 add2(u64 a, u64 b) {
  u64 d; asm("add.rn.f32x2 %0, %1, %2;" : "=l"(d) : "l"(a), "l"(b)); return d;
}
__device__ __forceinline__ void ffma2(u64& d, u64 a, u64 b) {
  asm("fma.rn.f32x2 %0, %1, %2, %0;" : "+l"(d) : "l"(a), "l"(b));
}
__device__ __forceinline__ u64 neg2(u64 x) { return x ^ 0x8000000080000000ULL; }

// ---- scratch --------------------------------------------------------------
__device__ float g_qkv[T_SEQ * 3 * CDIM];
__device__ float g_q[NHEAD * HD * T_SEQ];   // [h][d][t]  (transposed, normalized)
__device__ float g_k[NHEAD * HD * T_SEQ];   // [h][d][t]
__device__ float g_v[NHEAD * T_SEQ * HD];   // [h][t][d]
__device__ float g_y[T_SEQ * CDIM];

// ---------------------------------------------------------------------------
// GEMM + bias with packed FFMA2 (pairs over N).
// Tile 64(M) x 128(N), BK=16, 256 threads, thread tile 4M x 8N.
// ---------------------------------------------------------------------------
__global__ __launch_bounds__(256, 2) void sgemm_bias(
    const float* __restrict__ A, const float* __restrict__ B,
    const float* __restrict__ bias, float* __restrict__ C,
    int M, int N, int K)
{
  __shared__ float As[64 * 17];
  __shared__ float Bs[16 * 132];
  const int tid = threadIdx.x;
  const int tx = tid & 15, ty = tid >> 4;
  const int m0 = blockIdx.y << 6, n0 = blockIdx.x << 7;
  const int am = tid >> 2, ac = (tid & 3) << 2;

  u64 yp[4][4];
#pragma unroll
  for (int m = 0; m < 4; ++m)
#pragma unroll
    for (int p = 0; p < 4; ++p) yp[m][p] = 0ULL;

  for (int k0 = 0; k0 < K; k0 += 16) {
    float4 a4 = *(const float4*)&A[(size_t)(m0 + am) * K + k0 + ac];
    float4 b4[2];
#pragma unroll
    for (int i = 0; i < 2; ++i) {
      int idx = tid + i * 256;
      b4[i] = *(const float4*)&B[(size_t)(k0 + (idx >> 5)) * N + n0 + ((idx & 31) << 2)];
    }
    __syncthreads();
    As[am * 17 + ac + 0] = a4.x;
    As[am * 17 + ac + 1] = a4.y;
    As[am * 17 + ac + 2] = a4.z;
    As[am * 17 + ac + 3] = a4.w;
#pragma unroll
    for (int i = 0; i < 2; ++i) {
      int idx = tid + i * 256;
      *(float4*)&Bs[(idx >> 5) * 132 + ((idx & 31) << 2)] = b4[i];
    }
    __syncthreads();
#pragma unroll
    for (int kk = 0; kk < 16; ++kk) {
      ulonglong2 bA = *(ulonglong2*)&Bs[kk * 132 + 8 * tx];
      ulonglong2 bB = *(ulonglong2*)&Bs[kk * 132 + 8 * tx + 4];
      float a0 = As[(4 * ty + 0) * 17 + kk];
      float a1 = As[(4 * ty + 1) * 17 + kk];
      float a2 = As[(4 * ty + 2) * 17 + kk];
      float a3 = As[(4 * ty + 3) * 17 + kk];
      u64 d0 = dup2(a0), d1 = dup2(a1), d2 = dup2(a2), d3 = dup2(a3);
      ffma2(yp[0][0], d0, bA.x); ffma2(yp[0][1], d0, bA.y);
      ffma2(yp[0][2], d0, bB.x); ffma2(yp[0][3], d0, bB.y);
      ffma2(yp[1][0], d1, bA.x); ffma2(yp[1][1], d1, bA.y);
      ffma2(yp[1][2], d1, bB.x); ffma2(yp[1][3], d1, bB.y);
      ffma2(yp[2][0], d2, bA.x); ffma2(yp[2][1], d2, bA.y);
      ffma2(yp[2][2], d2, bB.x); ffma2(yp[2][3], d2, bB.y);
      ffma2(yp[3][0], d3, bA.x); ffma2(yp[3][1], d3, bA.y);
      ffma2(yp[3][2], d3, bB.x); ffma2(yp[3][3], d3, bB.y);
    }
  }

  ulonglong2 bb01 = *(const ulonglong2*)&bias[n0 + 8 * tx];
  ulonglong2 bb23 = *(const ulonglong2*)&bias[n0 + 8 * tx + 4];
#pragma unroll
  for (int m = 0; m < 4; ++m) {
    ulonglong2 s0, s1;
    s0.x = add2(yp[m][0], bb01.x);
    s0.y = add2(yp[m][1], bb01.y);
    s1.x = add2(yp[m][2], bb23.x);
    s1.y = add2(yp[m][3], bb23.y);
    size_t row = (size_t)(m0 + 4 * ty + m) * N + n0 + 8 * tx;
    *(ulonglong2*)&C[row] = s0;
    *(ulonglong2*)&C[row + 4] = s1;
  }
}

// ---------------------------------------------------------------------------
// Normalize q,k + reshape:  qkv[t][3C] -> Q,K [h][d][t] (transposed), V [h][t][d]
// Grid (T/64, H), 256 threads, one 64x64 tile per head.
// ---------------------------------------------------------------------------
__global__ __launch_bounds__(256) void norm_reshape(
    const float* __restrict__ qkv,
    float* __restrict__ Qg, float* __restrict__ Kg, float* __restrict__ Vg)
{
  __shared__ float Qs[64 * 68];
  __shared__ float Ks[64 * 68];
  __shared__ float invq[64], invk[64];
  const unsigned FULL = 0xffffffffu;
  const int h = blockIdx.y;
  const int t0 = blockIdx.x << 6;
  const int tid = threadIdx.x;

#pragma unroll
  for (int it = 0; it < 4; ++it) {
    int idx = tid + it * 256;
    int r = idx >> 4, c4 = (idx & 15) << 2;
    size_t base = (size_t)(t0 + r) * (3 * CDIM) + h * HD + c4;
    float4 q4 = *(const float4*)&qkv[base];
    float4 k4 = *(const float4*)&qkv[base + CDIM];
    float4 v4 = *(const float4*)&qkv[base + 2 * CDIM];
    *(float4*)&Qs[r * 68 + c4] = q4;
    *(float4*)&Ks[r * 68 + c4] = k4;
    *(float4*)&Vg[((size_t)(h << 12) + t0 + r) * HD + c4] = v4;
  }
  __syncthreads();

  {
    int row = tid >> 2, seg = tid & 3;
    float sq = 0.f, sk = 0.f;
#pragma unroll
    for (int i = 0; i < 16; ++i) {
      float a = Qs[row * 68 + seg * 16 + i];
      float b = Ks[row * 68 + seg * 16 + i];
      sq = fmaf(a, a, sq);
      sk = fmaf(b, b, sk);
    }
    sq += __shfl_xor_sync(FULL, sq, 1);
    sq += __shfl_xor_sync(FULL, sq, 2);
    sk += __shfl_xor_sync(FULL, sk, 1);
    sk += __shfl_xor_sync(FULL, sk, 2);
    if (seg == 0) {
      invq[row] = 1.0f / fmaxf(sqrtf(sq), 1e-12f);
      invk[row] = 1.0f / fmaxf(sqrtf(sk), 1e-12f);
    }
  }
  __syncthreads();

  {
    int d = tid >> 2, tseg = (tid & 3) << 4;
    size_t obase = (size_t)(h * HD + d) * T_SEQ + t0 + tseg;
#pragma unroll
    for (int j = 0; j < 4; ++j) {
      float4 oq, ok;
      int t = tseg + 4 * j;
      oq.x = Qs[(t + 0) * 68 + d] * invq[t + 0];
      oq.y = Qs[(t + 1) * 68 + d] * invq[t + 1];
      oq.z = Qs[(t + 2) * 68 + d] * invq[t + 2];
      oq.w = Qs[(t + 3) * 68 + d] * invq[t + 3];
      ok.x = Ks[(t + 0) * 68 + d] * invk[t + 0];
      ok.y = Ks[(t + 1) * 68 + d] * invk[t + 1];
      ok.z = Ks[(t + 2) * 68 + d] * invk[t + 2];
      ok.w = Ks[(t + 3) * 68 + d] * invk[t + 3];
      *(float4*)&Qg[obase + 4 * j] = oq;
      *(float4*)&Kg[obase + 4 * j] = ok;
    }
  }
}

// ---------------------------------------------------------------------------
// Fused cumulative linear attention, packed FFMA2.
// Grid (T/64, H), 128 threads (tx 0..15 over keys x4, ty 0..7 over q-rows x8).
// Per 64-key tile:
//   A : S = Q K^T, acc pairs over q-rows (Qt [d][q] contiguous, K dup'd)
//   scan: in-register f32x2 cumsum (2 rows/pair), carry across tiles
//   B2: Y += W V, acc pairs over q-rows (Wt [key][q] contiguous, V dup'd)
// ---------------------------------------------------------------------------
__global__ __launch_bounds__(128, 3) void attn_kernel(
    const float* __restrict__ Qg, const float* __restrict__ Kg,
    const float* __restrict__ Vg, float* __restrict__ Y)
{
  extern __shared__ float sm[];
  float* Qt = sm;                  // [d=64][q=64] stride 68
  float* Kt = sm + 64 * 68;        // [d=64][k=64] stride 68
  float* Vs = sm + 2 * 64 * 68;    // [k=64][d=64] stride 68
  float* Wt = sm + 3 * 64 * 68;    // [k=64][q=64] stride 68

  const unsigned FULL = 0xffffffffu;
  const int h = blockIdx.y;
  const int q0 = blockIdx.x << 6;
  const int tid = threadIdx.x;
  const int lane = tid & 31;
  const int tx = tid & 15, ty = tid >> 4;

  const float* Qh = Qg + (size_t)h * HD * T_SEQ;   // [d][t]
  const float* Kh = Kg + (size_t)h * HD * T_SEQ;   // [d][t]
  const float* Vh = Vg + (size_t)h * T_SEQ * HD;   // [t][d]

  // Load Q tile transposed-from-gmem (already [d][t]): Qt[d][qrow]
#pragma unroll
  for (int it = 0; it < 8; ++it) {
    int idx = tid + it * 128;
    int r = idx >> 4, c4 = (idx & 15) << 2;
    *(float4*)&Qt[r * 68 + c4] = *(const float4*)&Qh[(size_t)r * T_SEQ + q0 + c4];
  }

  u64 yp[4][4];
#pragma unroll
  for (int i = 0; i < 4; ++i)
#pragma unroll
    for (int c = 0; c < 4; ++c) yp[i][c] = 0ULL;
  u64 carry[4] = {0ULL, 0ULL, 0ULL, 0ULL};

  for (int k0 = 0; k0 < T_SEQ; k0 += 64) {
    __syncthreads();
#pragma unroll
    for (int it = 0; it < 8; ++it) {
      int idx = tid + it * 128;
      int r = idx >> 4, c4 = (idx & 15) << 2;
      *(float4*)&Kt[r * 68 + c4] = *(const float4*)&Kh[(size_t)r * T_SEQ + k0 + c4];
      *(float4*)&Vs[r * 68 + c4] = *(const float4*)&Vh[(size_t)(k0 + r) * HD + c4];
    }
    __syncthreads();

    // Phase A: S = Q K^T  (pairs over q-rows)
    u64 sp[4][4];
#pragma unroll
    for (int i = 0; i < 4; ++i)
#pragma unroll
      for (int j = 0; j < 4; ++j) sp[i][j] = 0ULL;
#pragma unroll 8
    for (int kk = 0; kk < 64; ++kk) {
      ulonglong2 qa = *(ulonglong2*)&Qt[kk * 68 + 8 * ty];
      ulonglong2 qb = *(ulonglong2*)&Qt[kk * 68 + 8 * ty + 4];
      float4 kf = *(float4*)&Kt[kk * 68 + 4 * tx];
      u64 k0d = dup2(kf.x), k1d = dup2(kf.y), k2d = dup2(kf.z), k3d = dup2(kf.w);
      ffma2(sp[0][0], qa.x, k0d); ffma2(sp[0][1], qa.x, k1d);
      ffma2(sp[0][2], qa.x, k2d); ffma2(sp[0][3], qa.x, k3d);
      ffma2(sp[1][0], qa.y, k0d); ffma2(sp[1][1], qa.y, k1d);
      ffma2(sp[1][2], qa.y, k2d); ffma2(sp[1][3], qa.y, k3d);
      ffma2(sp[2][0], qb.x, k0d); ffma2(sp[2][1], qb.x, k1d);
      ffma2(sp[2][2], qb.x, k2d); ffma2(sp[2][3], qb.x, k3d);
      ffma2(sp[3][0], qb.y, k0d); ffma2(sp[3][1], qb.y, k1d);
      ffma2(sp[3][2], qb.y, k2d); ffma2(sp[3][3], qb.y, k3d);
    }

    // Scan (in registers, 2 rows per f32x2 pair). Lanes 0-15 / 16-31 are
    // independent 16-lane segments, each covering the 64 keys in tx order.
#pragma unroll
    for (int i2 = 0; i2 < 4; ++i2) {
      u64 p0 = sp[i2][0];
      u64 p1 = add2(p0, sp[i2][1]);
      u64 p2 = add2(p1, sp[i2][2]);
      u64 p3 = add2(p2, sp[i2][3]);
      u64 run = p3;
#pragma unroll
      for (int off = 1; off < 16; off <<= 1) {
        u64 n = __shfl_up_sync(FULL, run, off, 16);
        if ((lane & 15) >= off) run = add2(run, n);
      }
      u64 base = add2(carry[i2], add2(run, neg2(p3)));   // carry + exclusive
      u64 tot = __shfl_sync(FULL, run, 15, 16);
      carry[i2] = add2(carry[i2], tot);

      u64 cum[4] = {add2(base, p0), add2(base, p1), add2(base, p2), add2(base, p3)};
#pragma unroll
      for (int j = 0; j < 4; ++j) {
        float2 s = unpack2(sp[i2][j]);
        float2 d = unpack2(cum[j]);
        float wlo = __fdividef(s.x, fmaxf(d.x, 1e-6f));
        float whi = __fdividef(s.y, fmaxf(d.y, 1e-6f));
        *(u64*)&Wt[(4 * tx + j) * 68 + 8 * ty + 2 * i2] = pack2(wlo, whi);
      }
    }
    __syncthreads();

    // Phase B2: Y += W V  (pairs over q-rows)
#pragma unroll 8
    for (int jj = 0; jj < 64; ++jj) {
      ulonglong2 wa = *(ulonglong2*)&Wt[jj * 68 + 8 * ty];
      ulonglong2 wb = *(ulonglong2*)&Wt[jj * 68 + 8 * ty + 4];
      float4 vf = *(float4*)&Vs[jj * 68 + 4 * tx];
      u64 v0d = dup2(vf.x), v1d = dup2(vf.y), v2d = dup2(vf.z), v3d = dup2(vf.w);
      ffma2(yp[0][0], wa.x, v0d); ffma2(yp[0][1], wa.x, v1d);
      ffma2(yp[0][2], wa.x, v2d); ffma2(yp[0][3], wa.x, v3d);
      ffma2(yp[1][0], wa.y, v0d); ffma2(yp[1][1], wa.y, v1d);
      ffma2(yp[1][2], wa.y, v2d); ffma2(yp[1][3], wa.y, v3d);
      ffma2(yp[2][0], wb.x, v0d); ffma2(yp[2][1], wb.x, v1d);
      ffma2(yp[2][2], wb.x, v2d); ffma2(yp[2][3], wb.x, v3d);
      ffma2(yp[3][0], wb.y, v0d); ffma2(yp[3][1], wb.y, v1d);
      ffma2(yp[3][2], wb.y, v2d); ffma2(yp[3][3], wb.y, v3d);
    }
  }

  // Write Y in [t][C] layout (row pairs -> two rows)
#pragma unroll
  for (int i2 = 0; i2 < 4; ++i2) {
    float2 u0 = unpack2(yp[i2][0]);
    float2 u1 = unpack2(yp[i2][1]);
    float2 u2 = unpack2(yp[i2][2]);
    float2 u3 = unpack2(yp[i2][3]);
    size_t r0 = (size_t)(q0 + 8 * ty + 2 * i2) * CDIM + h * HD + 4 * tx;
    *(float4*)&Y[r0]        = make_float4(u0.x, u1.x, u2.x, u3.x);
    *(float4*)&Y[r0 + CDIM] = make_float4(u0.y, u1.y, u2.y, u3.y);
  }
}

// ---------------------------------------------------------------------------
extern "C" void kernel_launch(void* const* d_in, const int* in_sizes, int n_in,
                              void* d_out, int out_size)
{
  const float* x      = (const float*)d_in[0];
  const float* w_attn = (const float*)d_in[1];
  const float* b_attn = (const float*)d_in[2];
  const float* w_proj = (const float*)d_in[3];
  const float* b_proj = (const float*)d_in[4];
  float* out = (float*)d_out;

  float *qkv, *q, *k, *v, *y;
  cudaGetSymbolAddress((void**)&qkv, g_qkv);
  cudaGetSymbolAddress((void**)&q,   g_q);
  cudaGetSymbolAddress((void**)&k,   g_k);
  cudaGetSymbolAddress((void**)&v,   g_v);
  cudaGetSymbolAddress((void**)&y,   g_y);

  const int ATTN_SMEM = 4 * 64 * 68 * 4;   // 69632 bytes
  cudaFuncSetAttribute(attn_kernel,
                       cudaFuncAttributeMaxDynamicSharedMemorySize, ATTN_SMEM);

  // 1) qkv = x @ w_attn + b_attn
  sgemm_bias<<<dim3(3 * CDIM / 128, T_SEQ / 64), 256>>>(
      x, w_attn, b_attn, qkv, T_SEQ, 3 * CDIM, CDIM);

  // 2) normalize q,k + transpose to [h][d][t]; v to [h][t][d]
  norm_reshape<<<dim3(T_SEQ / 64, NHEAD), 256>>>(qkv, q, k, v);

  // 3) fused cumulative linear attention
  attn_kernel<<<dim3(T_SEQ / 64, NHEAD), 128, ATTN_SMEM>>>(q, k, v, y);

  // 4) out = y @ w_proj + b_proj
  sgemm_bias<<<dim3(CDIM / 128, T_SEQ / 64), 256>>>(
      y, w_proj, b_proj, out, T_SEQ, CDIM, CDIM);
}

// round 9
// speedup vs baseline: 1.5465x; 1.3292x over previous
#include <cuda_runtime.h>
#include <cuda_bf16.h>
#include <cstdint>

#define T_SEQ 4096
#define NHEAD 12
#define HD    64
#define CDIM  768
#define K3    (3*CDIM)

typedef unsigned long long u64;
typedef unsigned int u32;

// ---- packed f32x2 helpers (sm_100+ base) ----------------------------------
__device__ __forceinline__ u64 dup2(float x) {
  u64 r; asm("mov.b64 %0, {%1, %1};" : "=l"(r) : "f"(x)); return r;
}
__device__ __forceinline__ u64 pack2(float x, float y) {
  u64 r; asm("mov.b64 %0, {%1, %2};" : "=l"(r) : "f"(x), "f"(y)); return r;
}
__device__ __forceinline__ float2 unpack2(u64 v) {
  float2 f; asm("mov.b64 {%0, %1}, %2;" : "=f"(f.x), "=f"(f.y) : "l"(v)); return f;
}
__device__ __forceinline__ u64 add2(u64 a, u64 b) {
  u64 d; asm("add.rn.f32x2 %0, %1, %2;" : "=l"(d) : "l"(a), "l"(b)); return d;
}
__device__ __forceinline__ void ffma2(u64& d, u64 a, u64 b) {
  asm("fma.rn.f32x2 %0, %1, %2, %0;" : "+l"(d) : "l"(a), "l"(b));
}
__device__ __forceinline__ u64 neg2(u64 x) { return x ^ 0x8000000080000000ULL; }

// ---- base-target tensor helpers (sm_80+ PTX, no 'a' suffix needed) --------
__device__ __forceinline__ u32 smem_u32(const void* p) {
  u32 a;
  asm("{ .reg .u64 t; cvta.to.shared.u64 t, %1; cvt.u32.u64 %0, t; }"
      : "=r"(a) : "l"(p));
  return a;
}
__device__ __forceinline__ void cpasync16(u32 dst, const void* src) {
  asm volatile("cp.async.ca.shared.global [%0], [%1], 16;"
               :: "r"(dst), "l"(src) : "memory");
}
#define CP_COMMIT() asm volatile("cp.async.commit_group;" ::: "memory")
#define LDSM4(R, addr)                                                        \
  asm volatile("ldmatrix.sync.aligned.m8n8.x4.shared.b16 {%0,%1,%2,%3}, [%4];"\
               : "=r"((R)[0]), "=r"((R)[1]), "=r"((R)[2]), "=r"((R)[3])       \
               : "r"(addr))
__device__ __forceinline__ void mma16816(float* c, const u32* a, u32 b0, u32 b1) {
  asm volatile(
      "mma.sync.aligned.m16n8k16.row.col.f32.bf16.bf16.f32 "
      "{%0,%1,%2,%3}, {%4,%5,%6,%7}, {%8,%9}, {%0,%1,%2,%3};"
      : "+f"(c[0]), "+f"(c[1]), "+f"(c[2]), "+f"(c[3])
      : "r"(a[0]), "r"(a[1]), "r"(a[2]), "r"(a[3]), "r"(b0), "r"(b1));
}

// ---- scratch --------------------------------------------------------------
__device__ float g_qkv[T_SEQ * K3];
__device__ float g_q[NHEAD * HD * T_SEQ];   // [h][d][t]
__device__ float g_k[NHEAD * HD * T_SEQ];   // [h][d][t]
__device__ float g_v[NHEAD * T_SEQ * HD];   // [h][t][d]
__device__ float g_y[T_SEQ * CDIM];
__device__ __nv_bfloat16 g_xh[T_SEQ * CDIM], g_xl[T_SEQ * CDIM];
__device__ __nv_bfloat16 g_wah[K3 * CDIM],  g_wal[K3 * CDIM];   // [N][K]
__device__ __nv_bfloat16 g_wph[CDIM * CDIM], g_wpl[CDIM * CDIM];
__device__ __nv_bfloat16 g_yh[T_SEQ * CDIM], g_yl[T_SEQ * CDIM];

// ---------------------------------------------------------------------------
// split fp32 -> (hi, lo) bf16
// ---------------------------------------------------------------------------
__global__ __launch_bounds__(256) void split_f32(
    const float* __restrict__ in, __nv_bfloat16* __restrict__ oh,
    __nv_bfloat16* __restrict__ ol, int n4)
{
  int i = blockIdx.x * 256 + threadIdx.x;
  if (i >= n4) return;
  float4 v = ((const float4*)in)[i];
  __nv_bfloat16 h0 = __float2bfloat16(v.x), h1 = __float2bfloat16(v.y);
  __nv_bfloat16 h2 = __float2bfloat16(v.z), h3 = __float2bfloat16(v.w);
  __nv_bfloat16 l0 = __float2bfloat16(v.x - __bfloat162float(h0));
  __nv_bfloat16 l1 = __float2bfloat16(v.y - __bfloat162float(h1));
  __nv_bfloat16 l2 = __float2bfloat16(v.z - __bfloat162float(h2));
  __nv_bfloat16 l3 = __float2bfloat16(v.w - __bfloat162float(h3));
  ((__nv_bfloat162*)oh)[2 * i + 0] = __nv_bfloat162(h0, h1);
  ((__nv_bfloat162*)oh)[2 * i + 1] = __nv_bfloat162(h2, h3);
  ((__nv_bfloat162*)ol)[2 * i + 0] = __nv_bfloat162(l0, l1);
  ((__nv_bfloat162*)ol)[2 * i + 1] = __nv_bfloat162(l2, l3);
}

// ---------------------------------------------------------------------------
// transpose + split: w[K][N] fp32 -> out[N][K] (hi, lo) bf16
// ---------------------------------------------------------------------------
__global__ __launch_bounds__(256) void transpose_split(
    const float* __restrict__ w, __nv_bfloat16* __restrict__ oh,
    __nv_bfloat16* __restrict__ ol, int K, int N)
{
  __shared__ float t[32][33];
  int n0 = blockIdx.x * 32, k0 = blockIdx.y * 32;
  int tx = threadIdx.x, ty = threadIdx.y;
#pragma unroll
  for (int i = ty; i < 32; i += 8)
    t[i][tx] = w[(size_t)(k0 + i) * N + n0 + tx];
  __syncthreads();
#pragma unroll
  for (int i = ty; i < 32; i += 8) {
    float v = t[tx][i];
    __nv_bfloat16 h = __float2bfloat16(v);
    __nv_bfloat16 l = __float2bfloat16(v - __bfloat162float(h));
    oh[(size_t)(n0 + i) * K + k0 + tx] = h;
    ol[(size_t)(n0 + i) * K + k0 + tx] = l;
  }
}

// ---------------------------------------------------------------------------
// Warp-MMA GEMM (mma.sync bf16, 3-term split):
//   C[M,N] = Ah@Bh^T + Ah@Bl^T + Al@Bh^T + bias     (B stored [N][K] K-major)
// CTA 128x128, 8 warps (warp tile 32x64), BK=32, cp.async double buffer.
// smem rows: 32 bf16 + 8 pad = 80B stride (conflict-free ldmatrix).
// ---------------------------------------------------------------------------
#define GSTAGE 40960            // 4 tensors * 128 rows * 80B
#define GEMM_SMEM (2 * GSTAGE)

__global__ __launch_bounds__(256, 1) void gemm_mma(
    const __nv_bfloat16* __restrict__ Ah, const __nv_bfloat16* __restrict__ Al,
    const __nv_bfloat16* __restrict__ Bh, const __nv_bfloat16* __restrict__ Bl,
    const float* __restrict__ bias, float* __restrict__ C,
    int M, int N, int K)
{
  extern __shared__ char smem[];
  const u32 sb = smem_u32(smem);
  const int tid = threadIdx.x, lane = tid & 31, wid = tid >> 5;
  const int m0 = blockIdx.y << 7, n0 = blockIdx.x << 7;
  const int wm = wid >> 1, wn = wid & 1;   // warp grid 4(m) x 2(n)

  const __nv_bfloat16* srcs[4] = {Ah, Al, Bh, Bl};

  float acc[2][8][4];
#pragma unroll
  for (int mt = 0; mt < 2; ++mt)
#pragma unroll
    for (int nt = 0; nt < 8; ++nt)
#pragma unroll
      for (int e = 0; e < 4; ++e) acc[mt][nt][e] = 0.f;

  const int nchunks = K >> 5;

  // stage loader: 2048 16B-units / 256 threads = 8 per thread
  auto load_stage = [&](int st, int k0) {
    u32 base = sb + st * GSTAGE;
#pragma unroll
    for (int i = 0; i < 8; ++i) {
      int idx = tid + (i << 8);
      int ten = idx >> 9, u = idx & 511;
      int row = u >> 2, q = u & 3;
      int gr = (ten < 2 ? m0 : n0) + row;
      cpasync16(base + ten * 10240 + row * 80 + q * 16,
                &srcs[ten][(size_t)gr * K + k0 + q * 8]);
    }
    CP_COMMIT();
  };

  load_stage(0, 0);

  for (int c = 0; c < nchunks; ++c) {
    const bool pf = (c + 1 < nchunks);
    if (pf) load_stage((c + 1) & 1, (c + 1) << 5);
    if (pf) asm volatile("cp.async.wait_group 1;" ::: "memory");
    else    asm volatile("cp.async.wait_group 0;" ::: "memory");
    __syncthreads();

    const u32 base = sb + (c & 1) * GSTAGE;
    const u32 aA = base;              // Ah
    const u32 aAl = base + 10240;     // Al
    const u32 aB = base + 20480;      // Bh
    const u32 aBl = base + 30720;     // Bl

#pragma unroll
    for (int ks = 0; ks < 32; ks += 16) {
      // A fragments: lanes 0-15 rows, lanes 16-31 same rows at k+8
      const int arow = lane & 15, asel = lane >> 4;
      u32 ah[2][4], al[2][4];
#pragma unroll
      for (int mt = 0; mt < 2; ++mt) {
        u32 off = (u32)((wm * 32 + mt * 16 + arow) * 80 + (ks + asel * 8) * 2);
        LDSM4(ah[mt], aA + off);
        LDSM4(al[mt], aAl + off);
      }
      // B fragments: quad layout — n += ((lane>>4)&1)*8, k += ((lane>>3)&1)*8
      const int nrow = (lane & 7) + ((lane >> 4) << 3);
      const int koff = ks + (((lane >> 3) & 1) << 3);
      u32 bh[4][4], bl[4][4];
#pragma unroll
      for (int ng = 0; ng < 4; ++ng) {
        u32 off = (u32)((wn * 64 + ng * 16 + nrow) * 80 + koff * 2);
        LDSM4(bh[ng], aB + off);
        LDSM4(bl[ng], aBl + off);
      }
#pragma unroll
      for (int mt = 0; mt < 2; ++mt)
#pragma unroll
        for (int nt = 0; nt < 8; ++nt) {
          const int ng = nt >> 1, sel = (nt & 1) << 1;
          mma16816(acc[mt][nt], ah[mt], bh[ng][sel], bh[ng][sel + 1]);
          mma16816(acc[mt][nt], ah[mt], bl[ng][sel], bl[ng][sel + 1]);
          mma16816(acc[mt][nt], al[mt], bh[ng][sel], bh[ng][sel + 1]);
        }
    }
    __syncthreads();
  }

  // epilogue: direct gmem store + bias
  const int rbase = m0 + wm * 32 + (lane >> 2);
  const int cbase = n0 + wn * 64 + ((lane & 3) << 1);
#pragma unroll
  for (int mt = 0; mt < 2; ++mt)
#pragma unroll
    for (int nt = 0; nt < 8; ++nt) {
      int row = rbase + mt * 16;
      int col = cbase + nt * 8;
      float b0 = bias[col], b1 = bias[col + 1];
      *(float2*)&C[(size_t)row * N + col] =
          make_float2(acc[mt][nt][0] + b0, acc[mt][nt][1] + b1);
      *(float2*)&C[(size_t)(row + 8) * N + col] =
          make_float2(acc[mt][nt][2] + b0, acc[mt][nt][3] + b1);
    }
}

// ---------------------------------------------------------------------------
// Normalize q,k + reshape:  qkv[t][3C] -> Q,K [h][d][t], V [h][t][d]
// ---------------------------------------------------------------------------
__global__ __launch_bounds__(256) void norm_reshape(
    const float* __restrict__ qkv,
    float* __restrict__ Qg, float* __restrict__ Kg, float* __restrict__ Vg)
{
  __shared__ float Qs[64 * 68];
  __shared__ float Ks[64 * 68];
  __shared__ float invq[64], invk[64];
  const unsigned FULL = 0xffffffffu;
  const int h = blockIdx.y;
  const int t0 = blockIdx.x << 6;
  const int tid = threadIdx.x;

#pragma unroll
  for (int it = 0; it < 4; ++it) {
    int idx = tid + it * 256;
    int r = idx >> 4, c4 = (idx & 15) << 2;
    size_t base = (size_t)(t0 + r) * K3 + h * HD + c4;
    float4 q4 = *(const float4*)&qkv[base];
    float4 k4 = *(const float4*)&qkv[base + CDIM];
    float4 v4 = *(const float4*)&qkv[base + 2 * CDIM];
    *(float4*)&Qs[r * 68 + c4] = q4;
    *(float4*)&Ks[r * 68 + c4] = k4;
    *(float4*)&Vg[((size_t)(h << 12) + t0 + r) * HD + c4] = v4;
  }
  __syncthreads();

  {
    int row = tid >> 2, seg = tid & 3;
    float sq = 0.f, sk = 0.f;
#pragma unroll
    for (int i = 0; i < 16; ++i) {
      float a = Qs[row * 68 + seg * 16 + i];
      float b = Ks[row * 68 + seg * 16 + i];
      sq = fmaf(a, a, sq);
      sk = fmaf(b, b, sk);
    }
    sq += __shfl_xor_sync(FULL, sq, 1);
    sq += __shfl_xor_sync(FULL, sq, 2);
    sk += __shfl_xor_sync(FULL, sk, 1);
    sk += __shfl_xor_sync(FULL, sk, 2);
    if (seg == 0) {
      invq[row] = 1.0f / fmaxf(sqrtf(sq), 1e-12f);
      invk[row] = 1.0f / fmaxf(sqrtf(sk), 1e-12f);
    }
  }
  __syncthreads();

  {
    int d = tid >> 2, tseg = (tid & 3) << 4;
    size_t obase = (size_t)(h * HD + d) * T_SEQ + t0 + tseg;
#pragma unroll
    for (int j = 0; j < 4; ++j) {
      float4 oq, ok;
      int t = tseg + 4 * j;
      oq.x = Qs[(t + 0) * 68 + d] * invq[t + 0];
      oq.y = Qs[(t + 1) * 68 + d] * invq[t + 1];
      oq.z = Qs[(t + 2) * 68 + d] * invq[t + 2];
      oq.w = Qs[(t + 3) * 68 + d] * invq[t + 3];
      ok.x = Ks[(t + 0) * 68 + d] * invk[t + 0];
      ok.y = Ks[(t + 1) * 68 + d] * invk[t + 1];
      ok.z = Ks[(t + 2) * 68 + d] * invk[t + 2];
      ok.w = Ks[(t + 3) * 68 + d] * invk[t + 3];
      *(float4*)&Qg[obase + 4 * j] = oq;
      *(float4*)&Kg[obase + 4 * j] = ok;
    }
  }
}

// ---------------------------------------------------------------------------
// Fused cumulative linear attention, packed FFMA2 (unchanged, passing).
// ---------------------------------------------------------------------------
__global__ __launch_bounds__(128, 3) void attn_kernel(
    const float* __restrict__ Qg, const float* __restrict__ Kg,
    const float* __restrict__ Vg, float* __restrict__ Y)
{
  extern __shared__ float sm[];
  float* Qt = sm;
  float* Kt = sm + 64 * 68;
  float* Vs = sm + 2 * 64 * 68;
  float* Wt = sm + 3 * 64 * 68;

  const unsigned FULL = 0xffffffffu;
  const int h = blockIdx.y;
  const int q0 = blockIdx.x << 6;
  const int tid = threadIdx.x;
  const int lane = tid & 31;
  const int tx = tid & 15, ty = tid >> 4;

  const float* Qh = Qg + (size_t)h * HD * T_SEQ;
  const float* Kh = Kg + (size_t)h * HD * T_SEQ;
  const float* Vh = Vg + (size_t)h * T_SEQ * HD;

#pragma unroll
  for (int it = 0; it < 8; ++it) {
    int idx = tid + it * 128;
    int r = idx >> 4, c4 = (idx & 15) << 2;
    *(float4*)&Qt[r * 68 + c4] = *(const float4*)&Qh[(size_t)r * T_SEQ + q0 + c4];
  }

  u64 yp[4][4];
#pragma unroll
  for (int i = 0; i < 4; ++i)
#pragma unroll
    for (int c = 0; c < 4; ++c) yp[i][c] = 0ULL;
  u64 carry[4] = {0ULL, 0ULL, 0ULL, 0ULL};

  for (int k0 = 0; k0 < T_SEQ; k0 += 64) {
    __syncthreads();
#pragma unroll
    for (int it = 0; it < 8; ++it) {
      int idx = tid + it * 128;
      int r = idx >> 4, c4 = (idx & 15) << 2;
      *(float4*)&Kt[r * 68 + c4] = *(const float4*)&Kh[(size_t)r * T_SEQ + k0 + c4];
      *(float4*)&Vs[r * 68 + c4] = *(const float4*)&Vh[(size_t)(k0 + r) * HD + c4];
    }
    __syncthreads();

    u64 sp[4][4];
#pragma unroll
    for (int i = 0; i < 4; ++i)
#pragma unroll
      for (int j = 0; j < 4; ++j) sp[i][j] = 0ULL;
#pragma unroll 8
    for (int kk = 0; kk < 64; ++kk) {
      ulonglong2 qa = *(ulonglong2*)&Qt[kk * 68 + 8 * ty];
      ulonglong2 qb = *(ulonglong2*)&Qt[kk * 68 + 8 * ty + 4];
      float4 kf = *(float4*)&Kt[kk * 68 + 4 * tx];
      u64 k0d = dup2(kf.x), k1d = dup2(kf.y), k2d = dup2(kf.z), k3d = dup2(kf.w);
      ffma2(sp[0][0], qa.x, k0d); ffma2(sp[0][1], qa.x, k1d);
      ffma2(sp[0][2], qa.x, k2d); ffma2(sp[0][3], qa.x, k3d);
      ffma2(sp[1][0], qa.y, k0d); ffma2(sp[1][1], qa.y, k1d);
      ffma2(sp[1][2], qa.y, k2d); ffma2(sp[1][3], qa.y, k3d);
      ffma2(sp[2][0], qb.x, k0d); ffma2(sp[2][1], qb.x, k1d);
      ffma2(sp[2][2], qb.x, k2d); ffma2(sp[2][3], qb.x, k3d);
      ffma2(sp[3][0], qb.y, k0d); ffma2(sp[3][1], qb.y, k1d);
      ffma2(sp[3][2], qb.y, k2d); ffma2(sp[3][3], qb.y, k3d);
    }

#pragma unroll
    for (int i2 = 0; i2 < 4; ++i2) {
      u64 p0 = sp[i2][0];
      u64 p1 = add2(p0, sp[i2][1]);
      u64 p2 = add2(p1, sp[i2][2]);
      u64 p3 = add2(p2, sp[i2][3]);
      u64 run = p3;
#pragma unroll
      for (int off = 1; off < 16; off <<= 1) {
        u64 n = __shfl_up_sync(FULL, run, off, 16);
        if ((lane & 15) >= off) run = add2(run, n);
      }
      u64 base = add2(carry[i2], add2(run, neg2(p3)));
      u64 tot = __shfl_sync(FULL, run, 15, 16);
      carry[i2] = add2(carry[i2], tot);

      u64 cum[4] = {add2(base, p0), add2(base, p1), add2(base, p2), add2(base, p3)};
#pragma unroll
      for (int j = 0; j < 4; ++j) {
        float2 s = unpack2(sp[i2][j]);
        float2 d = unpack2(cum[j]);
        float wlo = __fdividef(s.x, fmaxf(d.x, 1e-6f));
        float whi = __fdividef(s.y, fmaxf(d.y, 1e-6f));
        *(u64*)&Wt[(4 * tx + j) * 68 + 8 * ty + 2 * i2] = pack2(wlo, whi);
      }
    }
    __syncthreads();

#pragma unroll 8
    for (int jj = 0; jj < 64; ++jj) {
      ulonglong2 wa = *(ulonglong2*)&Wt[jj * 68 + 8 * ty];
      ulonglong2 wb = *(ulonglong2*)&Wt[jj * 68 + 8 * ty + 4];
      float4 vf = *(float4*)&Vs[jj * 68 + 4 * tx];
      u64 v0d = dup2(vf.x), v1d = dup2(vf.y), v2d = dup2(vf.z), v3d = dup2(vf.w);
      ffma2(yp[0][0], wa.x, v0d); ffma2(yp[0][1], wa.x, v1d);
      ffma2(yp[0][2], wa.x, v2d); ffma2(yp[0][3], wa.x, v3d);
      ffma2(yp[1][0], wa.y, v0d); ffma2(yp[1][1], wa.y, v1d);
      ffma2(yp[1][2], wa.y, v2d); ffma2(yp[1][3], wa.y, v3d);
      ffma2(yp[2][0], wb.x, v0d); ffma2(yp[2][1], wb.x, v1d);
      ffma2(yp[2][2], wb.x, v2d); ffma2(yp[2][3], wb.x, v3d);
      ffma2(yp[3][0], wb.y, v0d); ffma2(yp[3][1], wb.y, v1d);
      ffma2(yp[3][2], wb.y, v2d); ffma2(yp[3][3], wb.y, v3d);
    }
  }

#pragma unroll
  for (int i2 = 0; i2 < 4; ++i2) {
    float2 u0 = unpack2(yp[i2][0]);
    float2 u1 = unpack2(yp[i2][1]);
    float2 u2 = unpack2(yp[i2][2]);
    float2 u3 = unpack2(yp[i2][3]);
    size_t r0 = (size_t)(q0 + 8 * ty + 2 * i2) * CDIM + h * HD + 4 * tx;
    *(float4*)&Y[r0]        = make_float4(u0.x, u1.x, u2.x, u3.x);
    *(float4*)&Y[r0 + CDIM] = make_float4(u0.y, u1.y, u2.y, u3.y);
  }
}

// ---------------------------------------------------------------------------
extern "C" void kernel_launch(void* const* d_in, const int* in_sizes, int n_in,
                              void* d_out, int out_size)
{
  const float* x      = (const float*)d_in[0];
  const float* w_attn = (const float*)d_in[1];
  const float* b_attn = (const float*)d_in[2];
  const float* w_proj = (const float*)d_in[3];
  const float* b_proj = (const float*)d_in[4];
  float* out = (float*)d_out;

  float *qkv, *q, *k, *v, *y;
  __nv_bfloat16 *xh, *xl, *wah, *wal, *wph, *wpl, *yh, *yl;
  cudaGetSymbolAddress((void**)&qkv, g_qkv);
  cudaGetSymbolAddress((void**)&q,   g_q);
  cudaGetSymbolAddress((void**)&k,   g_k);
  cudaGetSymbolAddress((void**)&v,   g_v);
  cudaGetSymbolAddress((void**)&y,   g_y);
  cudaGetSymbolAddress((void**)&xh,  g_xh);
  cudaGetSymbolAddress((void**)&xl,  g_xl);
  cudaGetSymbolAddress((void**)&wah, g_wah);
  cudaGetSymbolAddress((void**)&wal, g_wal);
  cudaGetSymbolAddress((void**)&wph, g_wph);
  cudaGetSymbolAddress((void**)&wpl, g_wpl);
  cudaGetSymbolAddress((void**)&yh,  g_yh);
  cudaGetSymbolAddress((void**)&yl,  g_yl);

  const int ATTN_SMEM = 4 * 64 * 68 * 4;
  cudaFuncSetAttribute(attn_kernel,
                       cudaFuncAttributeMaxDynamicSharedMemorySize, ATTN_SMEM);
  cudaFuncSetAttribute(gemm_mma,
                       cudaFuncAttributeMaxDynamicSharedMemorySize, GEMM_SMEM);

  const int n4 = T_SEQ * CDIM / 4;

  // 0) input conversions
  split_f32<<<(n4 + 255) / 256, 256>>>(x, xh, xl, n4);
  transpose_split<<<dim3(K3 / 32, CDIM / 32), dim3(32, 8)>>>(w_attn, wah, wal, CDIM, K3);
  transpose_split<<<dim3(CDIM / 32, CDIM / 32), dim3(32, 8)>>>(w_proj, wph, wpl, CDIM, CDIM);

  // 1) qkv = x @ w_attn + b_attn   (warp-MMA, 3-term bf16 split)
  gemm_mma<<<dim3(K3 / 128, T_SEQ / 128), 256, GEMM_SMEM>>>(
      xh, xl, wah, wal, b_attn, qkv, T_SEQ, K3, CDIM);

  // 2) normalize q,k + transpose to [h][d][t]; v to [h][t][d]
  norm_reshape<<<dim3(T_SEQ / 64, NHEAD), 256>>>(qkv, q, k, v);

  // 3) fused cumulative linear attention
  attn_kernel<<<dim3(T_SEQ / 64, NHEAD), 128, ATTN_SMEM>>>(q, k, v, y);

  // 4) out = y @ w_proj + b_proj   (warp-MMA)
  split_f32<<<(n4 + 255) / 256, 256>>>(y, yh, yl, n4);
  gemm_mma<<<dim3(CDIM / 128, T_SEQ / 128), 256, GEMM_SMEM>>>(
      yh, yl, wph, wpl, b_proj, out, T_SEQ, CDIM, CDIM);
}

// round 10
// speedup vs baseline: 1.5480x; 1.0010x over previous
#include <cuda_runtime.h>
#include <cuda_bf16.h>
#include <cstdint>

#define T_SEQ 4096
#define NHEAD 12
#define HD    64
#define CDIM  768
#define K3    (3*CDIM)

typedef unsigned long long u64;
typedef unsigned int u32;

// ---- packed f32x2 helpers (sm_100+ base) ----------------------------------
__device__ __forceinline__ u64 dup2(float x) {
  u64 r; asm("mov.b64 %0, {%1, %1};" : "=l"(r) : "f"(x)); return r;
}
__device__ __forceinline__ u64 pack2(float x, float y) {
  u64 r; asm("mov.b64 %0, {%1, %2};" : "=l"(r) : "f"(x), "f"(y)); return r;
}
__device__ __forceinline__ float2 unpack2(u64 v) {
  float2 f; asm("mov.b64 {%0, %1}, %2;" : "=f"(f.x), "=f"(f.y) : "l"(v)); return f;
}
__device__ __forceinline__ u64 add2(u64 a, u64 b) {
  u64 d; asm("add.rn.f32x2 %0, %1, %2;" : "=l"(d) : "l"(a), "l"(b)); return d;
}
__device__ __forceinline__ void ffma2(u64& d, u64 a, u64 b) {
  asm("fma.rn.f32x2 %0, %1, %2, %0;" : "+l"(d) : "l"(a), "l"(b));
}
__device__ __forceinline__ u64 neg2(u64 x) { return x ^ 0x8000000080000000ULL; }

// ---- base-target tensor helpers (sm_80+ PTX, no 'a' suffix needed) --------
__device__ __forceinline__ u32 smem_u32(const void* p) {
  u32 a;
  asm("{ .reg .u64 t; cvta.to.shared.u64 t, %1; cvt.u32.u64 %0, t; }"
      : "=r"(a) : "l"(p));
  return a;
}
__device__ __forceinline__ void cpasync16(u32 dst, const void* src) {
  asm volatile("cp.async.ca.shared.global [%0], [%1], 16;"
               :: "r"(dst), "l"(src) : "memory");
}
#define CP_COMMIT() asm volatile("cp.async.commit_group;" ::: "memory")
#define LDSM4(R, addr)                                                        \
  asm volatile("ldmatrix.sync.aligned.m8n8.x4.shared.b16 {%0,%1,%2,%3}, [%4];"\
               : "=r"((R)[0]), "=r"((R)[1]), "=r"((R)[2]), "=r"((R)[3])       \
               : "r"(addr))
__device__ __forceinline__ void mma16816(float* c, const u32* a, u32 b0, u32 b1) {
  asm volatile(
      "mma.sync.aligned.m16n8k16.row.col.f32.bf16.bf16.f32 "
      "{%0,%1,%2,%3}, {%4,%5,%6,%7}, {%8,%9}, {%0,%1,%2,%3};"
      : "+f"(c[0]), "+f"(c[1]), "+f"(c[2]), "+f"(c[3])
      : "r"(a[0]), "r"(a[1]), "r"(a[2]), "r"(a[3]), "r"(b0), "r"(b1));
}

// ---- scratch --------------------------------------------------------------
__device__ float g_qkv[T_SEQ * K3];
__device__ float g_q[NHEAD * HD * T_SEQ];   // [h][d][t]
__device__ float g_k[NHEAD * HD * T_SEQ];   // [h][d][t]
__device__ float g_v[NHEAD * T_SEQ * HD];   // [h][t][d]
__device__ float g_y[T_SEQ * CDIM];
__device__ __nv_bfloat16 g_xh[T_SEQ * CDIM], g_xl[T_SEQ * CDIM];
__device__ __nv_bfloat16 g_wah[K3 * CDIM],  g_wal[K3 * CDIM];   // [N][K]
__device__ __nv_bfloat16 g_wph[CDIM * CDIM], g_wpl[CDIM * CDIM];
__device__ __nv_bfloat16 g_yh[T_SEQ * CDIM], g_yl[T_SEQ * CDIM];

// ---------------------------------------------------------------------------
// split fp32 -> (hi, lo) bf16
// ---------------------------------------------------------------------------
__global__ __launch_bounds__(256) void split_f32(
    const float* __restrict__ in, __nv_bfloat16* __restrict__ oh,
    __nv_bfloat16* __restrict__ ol, int n4)
{
  int i = blockIdx.x * 256 + threadIdx.x;
  if (i >= n4) return;
  float4 v = ((const float4*)in)[i];
  __nv_bfloat16 h0 = __float2bfloat16(v.x), h1 = __float2bfloat16(v.y);
  __nv_bfloat16 h2 = __float2bfloat16(v.z), h3 = __float2bfloat16(v.w);
  __nv_bfloat16 l0 = __float2bfloat16(v.x - __bfloat162float(h0));
  __nv_bfloat16 l1 = __float2bfloat16(v.y - __bfloat162float(h1));
  __nv_bfloat16 l2 = __float2bfloat16(v.z - __bfloat162float(h2));
  __nv_bfloat16 l3 = __float2bfloat16(v.w - __bfloat162float(h3));
  ((__nv_bfloat162*)oh)[2 * i + 0] = __nv_bfloat162(h0, h1);
  ((__nv_bfloat162*)oh)[2 * i + 1] = __nv_bfloat162(h2, h3);
  ((__nv_bfloat162*)ol)[2 * i + 0] = __nv_bfloat162(l0, l1);
  ((__nv_bfloat162*)ol)[2 * i + 1] = __nv_bfloat162(l2, l3);
}

// ---------------------------------------------------------------------------
// transpose + split: w[K][N] fp32 -> out[N][K] (hi, lo) bf16
// ---------------------------------------------------------------------------
__global__ __launch_bounds__(256) void transpose_split(
    const float* __restrict__ w, __nv_bfloat16* __restrict__ oh,
    __nv_bfloat16* __restrict__ ol, int K, int N)
{
  __shared__ float t[32][33];
  int n0 = blockIdx.x * 32, k0 = blockIdx.y * 32;
  int tx = threadIdx.x, ty = threadIdx.y;
#pragma unroll
  for (int i = ty; i < 32; i += 8)
    t[i][tx] = w[(size_t)(k0 + i) * N + n0 + tx];
  __syncthreads();
#pragma unroll
  for (int i = ty; i < 32; i += 8) {
    float v = t[tx][i];
    __nv_bfloat16 h = __float2bfloat16(v);
    __nv_bfloat16 l = __float2bfloat16(v - __bfloat162float(h));
    oh[(size_t)(n0 + i) * K + k0 + tx] = h;
    ol[(size_t)(n0 + i) * K + k0 + tx] = l;
  }
}

// ---------------------------------------------------------------------------
// Warp-MMA GEMM (mma.sync bf16, 3-term split):
//   C[M,N] = Ah@Bh^T + Ah@Bl^T + Al@Bh^T + bias     (B stored [N][K] K-major)
// CTA 128x128, 8 warps (warp tile 32x64), BK=32, cp.async double buffer.
// smem rows: 32 bf16 + 8 pad = 80B stride (conflict-free ldmatrix).
// ---------------------------------------------------------------------------
#define GSTAGE 40960            // 4 tensors * 128 rows * 80B
#define GEMM_SMEM (2 * GSTAGE)

__global__ __launch_bounds__(256, 1) void gemm_mma(
    const __nv_bfloat16* __restrict__ Ah, const __nv_bfloat16* __restrict__ Al,
    const __nv_bfloat16* __restrict__ Bh, const __nv_bfloat16* __restrict__ Bl,
    const float* __restrict__ bias, float* __restrict__ C,
    int M, int N, int K)
{
  extern __shared__ char smem[];
  const u32 sb = smem_u32(smem);
  const int tid = threadIdx.x, lane = tid & 31, wid = tid >> 5;
  const int m0 = blockIdx.y << 7, n0 = blockIdx.x << 7;
  const int wm = wid >> 1, wn = wid & 1;   // warp grid 4(m) x 2(n)

  const __nv_bfloat16* srcs[4] = {Ah, Al, Bh, Bl};

  float acc[2][8][4];
#pragma unroll
  for (int mt = 0; mt < 2; ++mt)
#pragma unroll
    for (int nt = 0; nt < 8; ++nt)
#pragma unroll
      for (int e = 0; e < 4; ++e) acc[mt][nt][e] = 0.f;

  const int nchunks = K >> 5;

  // stage loader: 2048 16B-units / 256 threads = 8 per thread
  auto load_stage = [&](int st, int k0) {
    u32 base = sb + st * GSTAGE;
#pragma unroll
    for (int i = 0; i < 8; ++i) {
      int idx = tid + (i << 8);
      int ten = idx >> 9, u = idx & 511;
      int row = u >> 2, q = u & 3;
      int gr = (ten < 2 ? m0 : n0) + row;
      cpasync16(base + ten * 10240 + row * 80 + q * 16,
                &srcs[ten][(size_t)gr * K + k0 + q * 8]);
    }
    CP_COMMIT();
  };

  load_stage(0, 0);

  for (int c = 0; c < nchunks; ++c) {
    const bool pf = (c + 1 < nchunks);
    if (pf) load_stage((c + 1) & 1, (c + 1) << 5);
    if (pf) asm volatile("cp.async.wait_group 1;" ::: "memory");
    else    asm volatile("cp.async.wait_group 0;" ::: "memory");
    __syncthreads();

    const u32 base = sb + (c & 1) * GSTAGE;
    const u32 aA = base;              // Ah
    const u32 aAl = base + 10240;     // Al
    const u32 aB = base + 20480;      // Bh
    const u32 aBl = base + 30720;     // Bl

#pragma unroll
    for (int ks = 0; ks < 32; ks += 16) {
      // A fragments: lanes 0-15 rows, lanes 16-31 same rows at k+8
      const int arow = lane & 15, asel = lane >> 4;
      u32 ah[2][4], al[2][4];
#pragma unroll
      for (int mt = 0; mt < 2; ++mt) {
        u32 off = (u32)((wm * 32 + mt * 16 + arow) * 80 + (ks + asel * 8) * 2);
        LDSM4(ah[mt], aA + off);
        LDSM4(al[mt], aAl + off);
      }
      // B fragments: quad layout — n += ((lane>>4)&1)*8, k += ((lane>>3)&1)*8
      const int nrow = (lane & 7) + ((lane >> 4) << 3);
      const int koff = ks + (((lane >> 3) & 1) << 3);
      u32 bh[4][4], bl[4][4];
#pragma unroll
      for (int ng = 0; ng < 4; ++ng) {
        u32 off = (u32)((wn * 64 + ng * 16 + nrow) * 80 + koff * 2);
        LDSM4(bh[ng], aB + off);
        LDSM4(bl[ng], aBl + off);
      }
#pragma unroll
      for (int mt = 0; mt < 2; ++mt)
#pragma unroll
        for (int nt = 0; nt < 8; ++nt) {
          const int ng = nt >> 1, sel = (nt & 1) << 1;
          mma16816(acc[mt][nt], ah[mt], bh[ng][sel], bh[ng][sel + 1]);
          mma16816(acc[mt][nt], ah[mt], bl[ng][sel], bl[ng][sel + 1]);
          mma16816(acc[mt][nt], al[mt], bh[ng][sel], bh[ng][sel + 1]);
        }
    }
    __syncthreads();
  }

  // epilogue: direct gmem store + bias
  const int rbase = m0 + wm * 32 + (lane >> 2);
  const int cbase = n0 + wn * 64 + ((lane & 3) << 1);
#pragma unroll
  for (int mt = 0; mt < 2; ++mt)
#pragma unroll
    for (int nt = 0; nt < 8; ++nt) {
      int row = rbase + mt * 16;
      int col = cbase + nt * 8;
      float b0 = bias[col], b1 = bias[col + 1];
      *(float2*)&C[(size_t)row * N + col] =
          make_float2(acc[mt][nt][0] + b0, acc[mt][nt][1] + b1);
      *(float2*)&C[(size_t)(row + 8) * N + col] =
          make_float2(acc[mt][nt][2] + b0, acc[mt][nt][3] + b1);
    }
}

// ---------------------------------------------------------------------------
// Normalize q,k + reshape:  qkv[t][3C] -> Q,K [h][d][t], V [h][t][d]
// ---------------------------------------------------------------------------
__global__ __launch_bounds__(256) void norm_reshape(
    const float* __restrict__ qkv,
    float* __restrict__ Qg, float* __restrict__ Kg, float* __restrict__ Vg)
{
  __shared__ float Qs[64 * 68];
  __shared__ float Ks[64 * 68];
  __shared__ float invq[64], invk[64];
  const unsigned FULL = 0xffffffffu;
  const int h = blockIdx.y;
  const int t0 = blockIdx.x << 6;
  const int tid = threadIdx.x;

#pragma unroll
  for (int it = 0; it < 4; ++it) {
    int idx = tid + it * 256;
    int r = idx >> 4, c4 = (idx & 15) << 2;
    size_t base = (size_t)(t0 + r) * K3 + h * HD + c4;
    float4 q4 = *(const float4*)&qkv[base];
    float4 k4 = *(const float4*)&qkv[base + CDIM];
    float4 v4 = *(const float4*)&qkv[base + 2 * CDIM];
    *(float4*)&Qs[r * 68 + c4] = q4;
    *(float4*)&Ks[r * 68 + c4] = k4;
    *(float4*)&Vg[((size_t)(h << 12) + t0 + r) * HD + c4] = v4;
  }
  __syncthreads();

  {
    int row = tid >> 2, seg = tid & 3;
    float sq = 0.f, sk = 0.f;
#pragma unroll
    for (int i = 0; i < 16; ++i) {
      float a = Qs[row * 68 + seg * 16 + i];
      float b = Ks[row * 68 + seg * 16 + i];
      sq = fmaf(a, a, sq);
      sk = fmaf(b, b, sk);
    }
    sq += __shfl_xor_sync(FULL, sq, 1);
    sq += __shfl_xor_sync(FULL, sq, 2);
    sk += __shfl_xor_sync(FULL, sk, 1);
    sk += __shfl_xor_sync(FULL, sk, 2);
    if (seg == 0) {
      invq[row] = 1.0f / fmaxf(sqrtf(sq), 1e-12f);
      invk[row] = 1.0f / fmaxf(sqrtf(sk), 1e-12f);
    }
  }
  __syncthreads();

  {
    int d = tid >> 2, tseg = (tid & 3) << 4;
    size_t obase = (size_t)(h * HD + d) * T_SEQ + t0 + tseg;
#pragma unroll
    for (int j = 0; j < 4; ++j) {
      float4 oq, ok;
      int t = tseg + 4 * j;
      oq.x = Qs[(t + 0) * 68 + d] * invq[t + 0];
      oq.y = Qs[(t + 1) * 68 + d] * invq[t + 1];
      oq.z = Qs[(t + 2) * 68 + d] * invq[t + 2];
      oq.w = Qs[(t + 3) * 68 + d] * invq[t + 3];
      ok.x = Ks[(t + 0) * 68 + d] * invk[t + 0];
      ok.y = Ks[(t + 1) * 68 + d] * invk[t + 1];
      ok.z = Ks[(t + 2) * 68 + d] * invk[t + 2];
      ok.w = Ks[(t + 3) * 68 + d] * invk[t + 3];
      *(float4*)&Qg[obase + 4 * j] = oq;
      *(float4*)&Kg[obase + 4 * j] = ok;
    }
  }
}

// ---------------------------------------------------------------------------
// Fused cumulative linear attention, packed FFMA2 (unchanged, passing).
// ---------------------------------------------------------------------------
__global__ __launch_bounds__(128, 3) void attn_kernel(
    const float* __restrict__ Qg, const float* __restrict__ Kg,
    const float* __restrict__ Vg, float* __restrict__ Y)
{
  extern __shared__ float sm[];
  float* Qt = sm;
  float* Kt = sm + 64 * 68;
  float* Vs = sm + 2 * 64 * 68;
  float* Wt = sm + 3 * 64 * 68;

  const unsigned FULL = 0xffffffffu;
  const int h = blockIdx.y;
  const int q0 = blockIdx.x << 6;
  const int tid = threadIdx.x;
  const int lane = tid & 31;
  const int tx = tid & 15, ty = tid >> 4;

  const float* Qh = Qg + (size_t)h * HD * T_SEQ;
  const float* Kh = Kg + (size_t)h * HD * T_SEQ;
  const float* Vh = Vg + (size_t)h * T_SEQ * HD;

#pragma unroll
  for (int it = 0; it < 8; ++it) {
    int idx = tid + it * 128;
    int r = idx >> 4, c4 = (idx & 15) << 2;
    *(float4*)&Qt[r * 68 + c4] = *(const float4*)&Qh[(size_t)r * T_SEQ + q0 + c4];
  }

  u64 yp[4][4];
#pragma unroll
  for (int i = 0; i < 4; ++i)
#pragma unroll
    for (int c = 0; c < 4; ++c) yp[i][c] = 0ULL;
  u64 carry[4] = {0ULL, 0ULL, 0ULL, 0ULL};

  for (int k0 = 0; k0 < T_SEQ; k0 += 64) {
    __syncthreads();
#pragma unroll
    for (int it = 0; it < 8; ++it) {
      int idx = tid + it * 128;
      int r = idx >> 4, c4 = (idx & 15) << 2;
      *(float4*)&Kt[r * 68 + c4] = *(const float4*)&Kh[(size_t)r * T_SEQ + k0 + c4];
      *(float4*)&Vs[r * 68 + c4] = *(const float4*)&Vh[(size_t)(k0 + r) * HD + c4];
    }
    __syncthreads();

    u64 sp[4][4];
#pragma unroll
    for (int i = 0; i < 4; ++i)
#pragma unroll
      for (int j = 0; j < 4; ++j) sp[i][j] = 0ULL;
#pragma unroll 8
    for (int kk = 0; kk < 64; ++kk) {
      ulonglong2 qa = *(ulonglong2*)&Qt[kk * 68 + 8 * ty];
      ulonglong2 qb = *(ulonglong2*)&Qt[kk * 68 + 8 * ty + 4];
      float4 kf = *(float4*)&Kt[kk * 68 + 4 * tx];
      u64 k0d = dup2(kf.x), k1d = dup2(kf.y), k2d = dup2(kf.z), k3d = dup2(kf.w);
      ffma2(sp[0][0], qa.x, k0d); ffma2(sp[0][1], qa.x, k1d);
      ffma2(sp[0][2], qa.x, k2d); ffma2(sp[0][3], qa.x, k3d);
      ffma2(sp[1][0], qa.y, k0d); ffma2(sp[1][1], qa.y, k1d);
      ffma2(sp[1][2], qa.y, k2d); ffma2(sp[1][3], qa.y, k3d);
      ffma2(sp[2][0], qb.x, k0d); ffma2(sp[2][1], qb.x, k1d);
      ffma2(sp[2][2], qb.x, k2d); ffma2(sp[2][3], qb.x, k3d);
      ffma2(sp[3][0], qb.y, k0d); ffma2(sp[3][1], qb.y, k1d);
      ffma2(sp[3][2], qb.y, k2d); ffma2(sp[3][3], qb.y, k3d);
    }

#pragma unroll
    for (int i2 = 0; i2 < 4; ++i2) {
      u64 p0 = sp[i2][0];
      u64 p1 = add2(p0, sp[i2][1]);
      u64 p2 = add2(p1, sp[i2][2]);
      u64 p3 = add2(p2, sp[i2][3]);
      u64 run = p3;
#pragma unroll
      for (int off = 1; off < 16; off <<= 1) {
        u64 n = __shfl_up_sync(FULL, run, off, 16);
        if ((lane & 15) >= off) run = add2(run, n);
      }
      u64 base = add2(carry[i2], add2(run, neg2(p3)));
      u64 tot = __shfl_sync(FULL, run, 15, 16);
      carry[i2] = add2(carry[i2], tot);

      u64 cum[4] = {add2(base, p0), add2(base, p1), add2(base, p2), add2(base, p3)};
#pragma unroll
      for (int j = 0; j < 4; ++j) {
        float2 s = unpack2(sp[i2][j]);
        float2 d = unpack2(cum[j]);
        float wlo = __fdividef(s.x, fmaxf(d.x, 1e-6f));
        float whi = __fdividef(s.y, fmaxf(d.y, 1e-6f));
        *(u64*)&Wt[(4 * tx + j) * 68 + 8 * ty + 2 * i2] = pack2(wlo, whi);
      }
    }
    __syncthreads();

#pragma unroll 8
    for (int jj = 0; jj < 64; ++jj) {
      ulonglong2 wa = *(ulonglong2*)&Wt[jj * 68 + 8 * ty];
      ulonglong2 wb = *(ulonglong2*)&Wt[jj * 68 + 8 * ty + 4];
      float4 vf = *(float4*)&Vs[jj * 68 + 4 * tx];
      u64 v0d = dup2(vf.x), v1d = dup2(vf.y), v2d = dup2(vf.z), v3d = dup2(vf.w);
      ffma2(yp[0][0], wa.x, v0d); ffma2(yp[0][1], wa.x, v1d);
      ffma2(yp[0][2], wa.x, v2d); ffma2(yp[0][3], wa.x, v3d);
      ffma2(yp[1][0], wa.y, v0d); ffma2(yp[1][1], wa.y, v1d);
      ffma2(yp[1][2], wa.y, v2d); ffma2(yp[1][3], wa.y, v3d);
      ffma2(yp[2][0], wb.x, v0d); ffma2(yp[2][1], wb.x, v1d);
      ffma2(yp[2][2], wb.x, v2d); ffma2(yp[2][3], wb.x, v3d);
      ffma2(yp[3][0], wb.y, v0d); ffma2(yp[3][1], wb.y, v1d);
      ffma2(yp[3][2], wb.y, v2d); ffma2(yp[3][3], wb.y, v3d);
    }
  }

#pragma unroll
  for (int i2 = 0; i2 < 4; ++i2) {
    float2 u0 = unpack2(yp[i2][0]);
    float2 u1 = unpack2(yp[i2][1]);
    float2 u2 = unpack2(yp[i2][2]);
    float2 u3 = unpack2(yp[i2][3]);
    size_t r0 = (size_t)(q0 + 8 * ty + 2 * i2) * CDIM + h * HD + 4 * tx;
    *(float4*)&Y[r0]        = make_float4(u0.x, u1.x, u2.x, u3.x);
    *(float4*)&Y[r0 + CDIM] = make_float4(u0.y, u1.y, u2.y, u3.y);
  }
}

// ---------------------------------------------------------------------------
extern "C" void kernel_launch(void* const* d_in, const int* in_sizes, int n_in,
                              void* d_out, int out_size)
{
  const float* x      = (const float*)d_in[0];
  const float* w_attn = (const float*)d_in[1];
  const float* b_attn = (const float*)d_in[2];
  const float* w_proj = (const float*)d_in[3];
  const float* b_proj = (const float*)d_in[4];
  float* out = (float*)d_out;

  float *qkv, *q, *k, *v, *y;
  __nv_bfloat16 *xh, *xl, *wah, *wal, *wph, *wpl, *yh, *yl;
  cudaGetSymbolAddress((void**)&qkv, g_qkv);
  cudaGetSymbolAddress((void**)&q,   g_q);
  cudaGetSymbolAddress((void**)&k,   g_k);
  cudaGetSymbolAddress((void**)&v,   g_v);
  cudaGetSymbolAddress((void**)&y,   g_y);
  cudaGetSymbolAddress((void**)&xh,  g_xh);
  cudaGetSymbolAddress((void**)&xl,  g_xl);
  cudaGetSymbolAddress((void**)&wah, g_wah);
  cudaGetSymbolAddress((void**)&wal, g_wal);
  cudaGetSymbolAddress((void**)&wph, g_wph);
  cudaGetSymbolAddress((void**)&wpl, g_wpl);
  cudaGetSymbolAddress((void**)&yh,  g_yh);
  cudaGetSymbolAddress((void**)&yl,  g_yl);

  const int ATTN_SMEM = 4 * 64 * 68 * 4;
  cudaFuncSetAttribute(attn_kernel,
                       cudaFuncAttributeMaxDynamicSharedMemorySize, ATTN_SMEM);
  cudaFuncSetAttribute(gemm_mma,
                       cudaFuncAttributeMaxDynamicSharedMemorySize, GEMM_SMEM);

  const int n4 = T_SEQ * CDIM / 4;

  // 0) input conversions
  split_f32<<<(n4 + 255) / 256, 256>>>(x, xh, xl, n4);
  transpose_split<<<dim3(K3 / 32, CDIM / 32), dim3(32, 8)>>>(w_attn, wah, wal, CDIM, K3);
  transpose_split<<<dim3(CDIM / 32, CDIM / 32), dim3(32, 8)>>>(w_proj, wph, wpl, CDIM, CDIM);

  // 1) qkv = x @ w_attn + b_attn   (warp-MMA, 3-term bf16 split)
  gemm_mma<<<dim3(K3 / 128, T_SEQ / 128), 256, GEMM_SMEM>>>(
      xh, xl, wah, wal, b_attn, qkv, T_SEQ, K3, CDIM);

  // 2) normalize q,k + transpose to [h][d][t]; v to [h][t][d]
  norm_reshape<<<dim3(T_SEQ / 64, NHEAD), 256>>>(qkv, q, k, v);

  // 3) fused cumulative linear attention
  attn_kernel<<<dim3(T_SEQ / 64, NHEAD), 128, ATTN_SMEM>>>(q, k, v, y);

  // 4) out = y @ w_proj + b_proj   (warp-MMA)
  split_f32<<<(n4 + 255) / 256, 256>>>(y, yh, yl, n4);
  gemm_mma<<<dim3(CDIM / 128, T_SEQ / 128), 256, GEMM_SMEM>>>(
      yh, yl, wph, wpl, b_proj, out, T_SEQ, CDIM, CDIM);
}

// round 11
// speedup vs baseline: 2.2277x; 1.4390x over previous
#include <cuda_runtime.h>
#include <cuda_bf16.h>
#include <cstdint>

#define T_SEQ 4096
#define NHEAD 12
#define HD    64
#define CDIM  768
#define K3    (3*CDIM)

typedef unsigned long long u64;
typedef unsigned int u32;

// ---- base-target helpers (sm_80+ PTX, no 'a' suffix) ----------------------
__device__ __forceinline__ u32 smem_u32(const void* p) {
  u32 a;
  asm("{ .reg .u64 t; cvta.to.shared.u64 t, %1; cvt.u32.u64 %0, t; }"
      : "=r"(a) : "l"(p));
  return a;
}
__device__ __forceinline__ void cpasync16(u32 dst, const void* src) {
  asm volatile("cp.async.ca.shared.global [%0], [%1], 16;"
               :: "r"(dst), "l"(src) : "memory");
}
#define CP_COMMIT() asm volatile("cp.async.commit_group;" ::: "memory")
#define LDSM4(R, addr)                                                        \
  asm volatile("ldmatrix.sync.aligned.m8n8.x4.shared.b16 {%0,%1,%2,%3}, [%4];"\
               : "=r"((R)[0]), "=r"((R)[1]), "=r"((R)[2]), "=r"((R)[3])       \
               : "r"(addr))
__device__ __forceinline__ void mma16816(float* c, const u32* a, u32 b0, u32 b1) {
  asm volatile(
      "mma.sync.aligned.m16n8k16.row.col.f32.bf16.bf16.f32 "
      "{%0,%1,%2,%3}, {%4,%5,%6,%7}, {%8,%9}, {%0,%1,%2,%3};"
      : "+f"(c[0]), "+f"(c[1]), "+f"(c[2]), "+f"(c[3])
      : "r"(a[0]), "r"(a[1]), "r"(a[2]), "r"(a[3]), "r"(b0), "r"(b1));
}
__device__ __forceinline__ void mma_tf32(float* c, const u32* a, u32 b0, u32 b1) {
  asm volatile(
      "mma.sync.aligned.m16n8k8.row.col.f32.tf32.tf32.f32 "
      "{%0,%1,%2,%3}, {%4,%5,%6,%7}, {%8,%9}, {%0,%1,%2,%3};"
      : "+f"(c[0]), "+f"(c[1]), "+f"(c[2]), "+f"(c[3])
      : "r"(a[0]), "r"(a[1]), "r"(a[2]), "r"(a[3]), "r"(b0), "r"(b1));
}
__device__ __forceinline__ float tf32r(float x) {
  u32 r; asm("cvt.rna.tf32.f32 %0, %1;" : "=r"(r) : "f"(x));
  return __uint_as_float(r);
}
__device__ __forceinline__ void split1(float v, float& h, float& l) {
  h = tf32r(v); l = tf32r(v - h);
}

// ---- scratch --------------------------------------------------------------
__device__ float g_qkv[T_SEQ * K3];
__device__ float g_xh[T_SEQ * CDIM], g_xl[T_SEQ * CDIM];
__device__ float g_wah[K3 * CDIM],  g_wal[K3 * CDIM];     // [N][K] fp32(tf32)
__device__ __nv_bfloat16 g_wph[CDIM * CDIM], g_wpl[CDIM * CDIM];  // [N][K] bf16
__device__ float g_qh[NHEAD * T_SEQ * HD], g_ql[NHEAD * T_SEQ * HD];  // [h][t][d]
__device__ float g_kh[NHEAD * T_SEQ * HD], g_kl[NHEAD * T_SEQ * HD];  // [h][t][d]
__device__ __nv_bfloat16 g_vbh[NHEAD * HD * T_SEQ], g_vbl[NHEAD * HD * T_SEQ]; // [h][d][t]
__device__ __nv_bfloat16 g_yh[T_SEQ * CDIM], g_yl[T_SEQ * CDIM];

// ---------------------------------------------------------------------------
// split fp32 -> (hi, lo) tf32-in-fp32
// ---------------------------------------------------------------------------
__global__ __launch_bounds__(256) void split_pair(
    const float* __restrict__ in, float* __restrict__ oh,
    float* __restrict__ ol, int n4)
{
  int i = blockIdx.x * 256 + threadIdx.x;
  if (i >= n4) return;
  float4 v = ((const float4*)in)[i];
  float4 h, l;
  split1(v.x, h.x, l.x); split1(v.y, h.y, l.y);
  split1(v.z, h.z, l.z); split1(v.w, h.w, l.w);
  ((float4*)oh)[i] = h;
  ((float4*)ol)[i] = l;
}

// ---------------------------------------------------------------------------
// transpose + split tf32: w[K][N] -> out[N][K] (hi, lo) fp32
// ---------------------------------------------------------------------------
__global__ __launch_bounds__(256) void transpose_split_pair(
    const float* __restrict__ w, float* __restrict__ oh,
    float* __restrict__ ol, int K, int N)
{
  __shared__ float t[32][33];
  int n0 = blockIdx.x * 32, k0 = blockIdx.y * 32;
  int tx = threadIdx.x, ty = threadIdx.y;
#pragma unroll
  for (int i = ty; i < 32; i += 8)
    t[i][tx] = w[(size_t)(k0 + i) * N + n0 + tx];
  __syncthreads();
#pragma unroll
  for (int i = ty; i < 32; i += 8) {
    float v = t[tx][i], h, l;
    split1(v, h, l);
    oh[(size_t)(n0 + i) * K + k0 + tx] = h;
    ol[(size_t)(n0 + i) * K + k0 + tx] = l;
  }
}

// ---------------------------------------------------------------------------
// transpose + split bf16: w[K][N] -> out[N][K] (hi, lo) bf16
// ---------------------------------------------------------------------------
__global__ __launch_bounds__(256) void transpose_split_bf16(
    const float* __restrict__ w, __nv_bfloat16* __restrict__ oh,
    __nv_bfloat16* __restrict__ ol, int K, int N)
{
  __shared__ float t[32][33];
  int n0 = blockIdx.x * 32, k0 = blockIdx.y * 32;
  int tx = threadIdx.x, ty = threadIdx.y;
#pragma unroll
  for (int i = ty; i < 32; i += 8)
    t[i][tx] = w[(size_t)(k0 + i) * N + n0 + tx];
  __syncthreads();
#pragma unroll
  for (int i = ty; i < 32; i += 8) {
    float v = t[tx][i];
    __nv_bfloat16 h = __float2bfloat16(v);
    __nv_bfloat16 l = __float2bfloat16(v - __bfloat162float(h));
    oh[(size_t)(n0 + i) * K + k0 + tx] = h;
    ol[(size_t)(n0 + i) * K + k0 + tx] = l;
  }
}

// ---------------------------------------------------------------------------
// 3xTF32 GEMM: C[M,N] = Ah@Bh^T + Ah@Bl^T + Al@Bh^T + bias   (B is [N][K])
// CTA 128x128, 8 warps (32x64), BK=32, cp.async double buffer.
// fp32 rows staged at 144B stride (32 floats + 4 pad); LDSM b16-view trick.
// ---------------------------------------------------------------------------
#define TSTAGE 73728          // 4 tensors * 128 rows * 144B
#define TG_SMEM (2 * TSTAGE)

__global__ __launch_bounds__(256, 1) void gemm_tf32(
    const float* __restrict__ Ah, const float* __restrict__ Al,
    const float* __restrict__ Bh, const float* __restrict__ Bl,
    const float* __restrict__ bias, float* __restrict__ C,
    int M, int N, int K)
{
  extern __shared__ char smem[];
  const u32 sb = smem_u32(smem);
  const int tid = threadIdx.x, lane = tid & 31, wid = tid >> 5;
  const int m0 = blockIdx.y << 7, n0 = blockIdx.x << 7;
  const int wm = wid >> 1, wn = wid & 1;
  const float* srcs[4] = {Ah, Al, Bh, Bl};

  float acc[2][8][4] = {};

  auto load_stage = [&](int st, int k0) {
    u32 base = sb + st * TSTAGE;
#pragma unroll
    for (int i = 0; i < 16; ++i) {
      int idx = tid + (i << 8);
      int ten = idx >> 10, u = idx & 1023;
      int row = u >> 3, seg = u & 7;
      int gr = (ten < 2 ? m0 : n0) + row;
      cpasync16(base + ten * 18432 + row * 144 + seg * 16,
                &srcs[ten][(size_t)gr * K + k0 + seg * 4]);
    }
    CP_COMMIT();
  };
  load_stage(0, 0);

  const int nch = K >> 5;
  const u32 a_off = (u32)((wm * 32 + (lane & 7) + ((lane >> 3) & 1) * 8) * 144
                          + (lane >> 4) * 16);
  const u32 b_off = (u32)((wn * 64 + (lane & 7) + ((lane >> 4) & 1) * 8) * 144
                          + ((lane >> 3) & 1) * 16);

  for (int c = 0; c < nch; ++c) {
    if (c + 1 < nch) {
      load_stage((c + 1) & 1, (c + 1) << 5);
      asm volatile("cp.async.wait_group 1;" ::: "memory");
    } else {
      asm volatile("cp.async.wait_group 0;" ::: "memory");
    }
    __syncthreads();

    u32 base = sb + (c & 1) * TSTAGE;
    u32 aH = base + a_off;
    u32 aL = aH + 18432;
    u32 bH = base + 36864 + b_off;
    u32 bL = bH + 18432;

#pragma unroll
    for (int ks = 0; ks < 4; ++ks) {
      u32 ah[2][4], al[2][4];
      LDSM4(ah[0], aH + ks * 32);
      LDSM4(ah[1], aH + ks * 32 + 16 * 144);
      LDSM4(al[0], aL + ks * 32);
      LDSM4(al[1], aL + ks * 32 + 16 * 144);
      u32 bh[4][4], bl[4][4];
#pragma unroll
      for (int ng = 0; ng < 4; ++ng) {
        LDSM4(bh[ng], bH + ng * 16 * 144 + ks * 32);
        LDSM4(bl[ng], bL + ng * 16 * 144 + ks * 32);
      }
#pragma unroll
      for (int mt = 0; mt < 2; ++mt)
#pragma unroll
        for (int nf = 0; nf < 8; ++nf) {
          int ng = nf >> 1, sel = (nf & 1) << 1;
          mma_tf32(acc[mt][nf], ah[mt], bh[ng][sel], bh[ng][sel + 1]);
          mma_tf32(acc[mt][nf], ah[mt], bl[ng][sel], bl[ng][sel + 1]);
          mma_tf32(acc[mt][nf], al[mt], bh[ng][sel], bh[ng][sel + 1]);
        }
    }
    __syncthreads();
  }

  const int rbase = m0 + wm * 32 + (lane >> 2);
  const int cbase = n0 + wn * 64 + ((lane & 3) << 1);
#pragma unroll
  for (int mt = 0; mt < 2; ++mt)
#pragma unroll
    for (int nf = 0; nf < 8; ++nf) {
      int row = rbase + mt * 16;
      int col = cbase + nf * 8;
      float b0 = bias[col], b1 = bias[col + 1];
      *(float2*)&C[(size_t)row * N + col] =
          make_float2(acc[mt][nf][0] + b0, acc[mt][nf][1] + b1);
      *(float2*)&C[(size_t)(row + 8) * N + col] =
          make_float2(acc[mt][nf][2] + b0, acc[mt][nf][3] + b1);
    }
}

// ---------------------------------------------------------------------------
// bf16x3 GEMM (unchanged from R9, passing): for the output projection.
// ---------------------------------------------------------------------------
#define GSTAGE 40960
#define GEMM_SMEM (2 * GSTAGE)

__global__ __launch_bounds__(256, 1) void gemm_mma(
    const __nv_bfloat16* __restrict__ Ah, const __nv_bfloat16* __restrict__ Al,
    const __nv_bfloat16* __restrict__ Bh, const __nv_bfloat16* __restrict__ Bl,
    const float* __restrict__ bias, float* __restrict__ C,
    int M, int N, int K)
{
  extern __shared__ char smem[];
  const u32 sb = smem_u32(smem);
  const int tid = threadIdx.x, lane = tid & 31, wid = tid >> 5;
  const int m0 = blockIdx.y << 7, n0 = blockIdx.x << 7;
  const int wm = wid >> 1, wn = wid & 1;
  const __nv_bfloat16* srcs[4] = {Ah, Al, Bh, Bl};

  float acc[2][8][4] = {};
  const int nchunks = K >> 5;

  auto load_stage = [&](int st, int k0) {
    u32 base = sb + st * GSTAGE;
#pragma unroll
    for (int i = 0; i < 8; ++i) {
      int idx = tid + (i << 8);
      int ten = idx >> 9, u = idx & 511;
      int row = u >> 2, q = u & 3;
      int gr = (ten < 2 ? m0 : n0) + row;
      cpasync16(base + ten * 10240 + row * 80 + q * 16,
                &srcs[ten][(size_t)gr * K + k0 + q * 8]);
    }
    CP_COMMIT();
  };
  load_stage(0, 0);

  for (int c = 0; c < nchunks; ++c) {
    const bool pf = (c + 1 < nchunks);
    if (pf) load_stage((c + 1) & 1, (c + 1) << 5);
    if (pf) asm volatile("cp.async.wait_group 1;" ::: "memory");
    else    asm volatile("cp.async.wait_group 0;" ::: "memory");
    __syncthreads();

    const u32 base = sb + (c & 1) * GSTAGE;
    const u32 aA = base, aAl = base + 10240, aB = base + 20480, aBl = base + 30720;

#pragma unroll
    for (int ks = 0; ks < 32; ks += 16) {
      const int arow = lane & 15, asel = lane >> 4;
      u32 ah[2][4], al[2][4];
#pragma unroll
      for (int mt = 0; mt < 2; ++mt) {
        u32 off = (u32)((wm * 32 + mt * 16 + arow) * 80 + (ks + asel * 8) * 2);
        LDSM4(ah[mt], aA + off);
        LDSM4(al[mt], aAl + off);
      }
      const int nrow = (lane & 7) + ((lane >> 4) << 3);
      const int koff = ks + (((lane >> 3) & 1) << 3);
      u32 bh[4][4], bl[4][4];
#pragma unroll
      for (int ng = 0; ng < 4; ++ng) {
        u32 off = (u32)((wn * 64 + ng * 16 + nrow) * 80 + koff * 2);
        LDSM4(bh[ng], aB + off);
        LDSM4(bl[ng], aBl + off);
      }
#pragma unroll
      for (int mt = 0; mt < 2; ++mt)
#pragma unroll
        for (int nt = 0; nt < 8; ++nt) {
          const int ng = nt >> 1, sel = (nt & 1) << 1;
          mma16816(acc[mt][nt], ah[mt], bh[ng][sel], bh[ng][sel + 1]);
          mma16816(acc[mt][nt], ah[mt], bl[ng][sel], bl[ng][sel + 1]);
          mma16816(acc[mt][nt], al[mt], bh[ng][sel], bh[ng][sel + 1]);
        }
    }
    __syncthreads();
  }

  const int rbase = m0 + wm * 32 + (lane >> 2);
  const int cbase = n0 + wn * 64 + ((lane & 3) << 1);
#pragma unroll
  for (int mt = 0; mt < 2; ++mt)
#pragma unroll
    for (int nt = 0; nt < 8; ++nt) {
      int row = rbase + mt * 16;
      int col = cbase + nt * 8;
      float b0 = bias[col], b1 = bias[col + 1];
      *(float2*)&C[(size_t)row * N + col] =
          make_float2(acc[mt][nt][0] + b0, acc[mt][nt][1] + b1);
      *(float2*)&C[(size_t)(row + 8) * N + col] =
          make_float2(acc[mt][nt][2] + b0, acc[mt][nt][3] + b1);
    }
}

// ---------------------------------------------------------------------------
// Normalize q,k + split:
//   qkv[t][3C] -> Qh/Ql, Kh/Kl [h][t][d] fp32(tf32); Vbh/Vbl [h][d][t] bf16
// ---------------------------------------------------------------------------
__global__ __launch_bounds__(256) void norm_split(
    const float* __restrict__ qkv,
    float* __restrict__ Qh, float* __restrict__ Ql,
    float* __restrict__ Kh, float* __restrict__ Kl,
    __nv_bfloat16* __restrict__ Vbh, __nv_bfloat16* __restrict__ Vbl)
{
  __shared__ float Qs[64 * 68];
  __shared__ float Ks[64 * 68];
  __shared__ float invq[64], invk[64];
  const unsigned FULL = 0xffffffffu;
  const int h = blockIdx.y;
  const int t0 = blockIdx.x << 6;
  const int tid = threadIdx.x;

#pragma unroll
  for (int it = 0; it < 4; ++it) {
    int idx = tid + it * 256;
    int r = idx >> 4, c4 = (idx & 15) << 2;
    size_t base = (size_t)(t0 + r) * K3 + h * HD + c4;
    *(float4*)&Qs[r * 68 + c4] = *(const float4*)&qkv[base];
    *(float4*)&Ks[r * 68 + c4] = *(const float4*)&qkv[base + CDIM];
  }
  __syncthreads();

  {
    int row = tid >> 2, seg = tid & 3;
    float sq = 0.f, sk = 0.f;
#pragma unroll
    for (int i = 0; i < 16; ++i) {
      float a = Qs[row * 68 + seg * 16 + i];
      float b = Ks[row * 68 + seg * 16 + i];
      sq = fmaf(a, a, sq);
      sk = fmaf(b, b, sk);
    }
    sq += __shfl_xor_sync(FULL, sq, 1);
    sq += __shfl_xor_sync(FULL, sq, 2);
    sk += __shfl_xor_sync(FULL, sk, 1);
    sk += __shfl_xor_sync(FULL, sk, 2);
    if (seg == 0) {
      invq[row] = 1.0f / fmaxf(sqrtf(sq), 1e-12f);
      invk[row] = 1.0f / fmaxf(sqrtf(sk), 1e-12f);
    }
  }
  __syncthreads();

  {
    int r = tid >> 2, cseg = (tid & 3) << 4;
    float iq = invq[r], ik = invk[r];
    size_t ob = ((size_t)h * T_SEQ + t0 + r) * HD + cseg;
#pragma unroll
    for (int j = 0; j < 4; ++j) {
      float4 qv = *(float4*)&Qs[r * 68 + cseg + 4 * j];
      float4 kv = *(float4*)&Ks[r * 68 + cseg + 4 * j];
      float4 qh4, ql4, kh4, kl4;
      split1(qv.x * iq, qh4.x, ql4.x); split1(qv.y * iq, qh4.y, ql4.y);
      split1(qv.z * iq, qh4.z, ql4.z); split1(qv.w * iq, qh4.w, ql4.w);
      split1(kv.x * ik, kh4.x, kl4.x); split1(kv.y * ik, kh4.y, kl4.y);
      split1(kv.z * ik, kh4.z, kl4.z); split1(kv.w * ik, kh4.w, kl4.w);
      *(float4*)&Qh[ob + 4 * j] = qh4;
      *(float4*)&Ql[ob + 4 * j] = ql4;
      *(float4*)&Kh[ob + 4 * j] = kh4;
      *(float4*)&Kl[ob + 4 * j] = kl4;
    }
  }
  __syncthreads();

  // Stage V, then write transposed bf16 hi/lo [h][d][t]
#pragma unroll
  for (int it = 0; it < 4; ++it) {
    int idx = tid + it * 256;
    int r = idx >> 4, c4 = (idx & 15) << 2;
    size_t base = (size_t)(t0 + r) * K3 + h * HD + 2 * CDIM + c4;
    *(float4*)&Qs[r * 68 + c4] = *(const float4*)&qkv[base];
  }
  __syncthreads();
  {
    int d = tid >> 2, tseg = (tid & 3) << 4;
    size_t vb = ((size_t)h * HD + d) * T_SEQ + t0 + tseg;
#pragma unroll
    for (int j = 0; j < 4; ++j) {
      float v0 = Qs[(tseg + 4 * j + 0) * 68 + d];
      float v1 = Qs[(tseg + 4 * j + 1) * 68 + d];
      float v2 = Qs[(tseg + 4 * j + 2) * 68 + d];
      float v3 = Qs[(tseg + 4 * j + 3) * 68 + d];
      __nv_bfloat162 h01, h23, l01, l23;
      h01.x = __float2bfloat16(v0); l01.x = __float2bfloat16(v0 - __bfloat162float(h01.x));
      h01.y = __float2bfloat16(v1); l01.y = __float2bfloat16(v1 - __bfloat162float(h01.y));
      h23.x = __float2bfloat16(v2); l23.x = __float2bfloat16(v2 - __bfloat162float(h23.x));
      h23.y = __float2bfloat16(v3); l23.y = __float2bfloat16(v3 - __bfloat162float(h23.y));
      *(__nv_bfloat162*)&Vbh[vb + 4 * j]     = h01;
      *(__nv_bfloat162*)&Vbh[vb + 4 * j + 2] = h23;
      *(__nv_bfloat162*)&Vbl[vb + 4 * j]     = l01;
      *(__nv_bfloat162*)&Vbl[vb + 4 * j + 2] = l23;
    }
  }
}

// ---------------------------------------------------------------------------
// Tensorized cumulative linear attention.
// Grid (T/64, H), 128 thr (4 warps x 16 q-rows). 32-key tiles, double buffer.
// Phase A: S = QK^T in 3xTF32 mma; fragment-level quad scan w/ carries;
// W split bf16 -> warp-private smem; Phase B: Y += W@V in bf16x3 mma.
// smem stage: Kh(32x272B) Kl Vh(64x80B bf16) Vl = 27648B x2; W: 4w x 2560B.
// ---------------------------------------------------------------------------
#define ATT_STAGE 27648
#define ATT_SMEM  (2 * ATT_STAGE + 4 * 2560)   // 65536

__global__ __launch_bounds__(128, 3) void attn_mma(
    const float* __restrict__ Qh_, const float* __restrict__ Ql_,
    const float* __restrict__ Kh_, const float* __restrict__ Kl_,
    const __nv_bfloat16* __restrict__ Vh_, const __nv_bfloat16* __restrict__ Vl_,
    __nv_bfloat16* __restrict__ Yh_, __nv_bfloat16* __restrict__ Yl_)
{
  extern __shared__ char smem[];
  const u32 sb = smem_u32(smem);
  const unsigned FULL = 0xffffffffu;
  const int h = blockIdx.y, q0 = blockIdx.x << 6;
  const int tid = threadIdx.x, lane = tid & 31, w = tid >> 5;
  const int g = lane >> 2, qd = lane & 3;

  // ---- Q fragments (one-time, tf32 layout direct from gmem) ----
  const u32* Qhp = (const u32*)Qh_ + ((size_t)h * T_SEQ + q0 + w * 16) * HD;
  const u32* Qlp = (const u32*)Ql_ + ((size_t)h * T_SEQ + q0 + w * 16) * HD;
  u32 qfh[8][4], qfl[8][4];
#pragma unroll
  for (int kc = 0; kc < 8; ++kc) {
    int c0 = kc * 8 + qd;
    qfh[kc][0] = Qhp[g * HD + c0];       qfh[kc][1] = Qhp[(g + 8) * HD + c0];
    qfh[kc][2] = Qhp[g * HD + c0 + 4];   qfh[kc][3] = Qhp[(g + 8) * HD + c0 + 4];
    qfl[kc][0] = Qlp[g * HD + c0];       qfl[kc][1] = Qlp[(g + 8) * HD + c0];
    qfl[kc][2] = Qlp[g * HD + c0 + 4];   qfl[kc][3] = Qlp[(g + 8) * HD + c0 + 4];
  }

  auto load_stage = [&](int st, int k0) {
    u32 base = sb + st * ATT_STAGE;
#pragma unroll
    for (int i = 0; i < 4; ++i) {
      int idx = tid + (i << 7);            // 0..511
      int row = idx >> 4, u = idx & 15;
      const float* kh = Kh_ + ((size_t)h * T_SEQ + k0 + row) * HD + u * 4;
      const float* kl = Kl_ + ((size_t)h * T_SEQ + k0 + row) * HD + u * 4;
      cpasync16(base + row * 272 + u * 16, kh);
      cpasync16(base + 8704 + row * 272 + u * 16, kl);
    }
#pragma unroll
    for (int i = 0; i < 2; ++i) {
      int idx = tid + (i << 7);            // 0..255
      int row = idx >> 2, u = idx & 3;
      const __nv_bfloat16* vh = Vh_ + ((size_t)h * HD + row) * T_SEQ + k0 + u * 8;
      const __nv_bfloat16* vl = Vl_ + ((size_t)h * HD + row) * T_SEQ + k0 + u * 8;
      cpasync16(base + 17408 + row * 80 + u * 16, vh);
      cpasync16(base + 22528 + row * 80 + u * 16, vl);
    }
    CP_COMMIT();
  };

  // lane-dependent ldmatrix offsets
  const u32 k_lane = (u32)((((lane >> 4) & 1) * 8 + (lane & 7)) * 272
                           + ((lane >> 3) & 1) * 16);
  const u32 v_lane = (u32)(((lane & 7) + ((lane >> 4) & 1) * 8) * 80
                           + ((lane >> 3) & 1) * 16);
  const u32 wa_lane = (u32)((lane & 15) * 80 + (lane >> 4) * 16);
  const u32 Wh_base = sb + 2 * ATT_STAGE + w * 2560;
  const int Wh_off = 2 * ATT_STAGE + w * 2560;

  float Yacc[8][4] = {};
  float carry0 = 0.f, carry1 = 0.f;

  load_stage(0, 0);

  for (int c = 0; c < T_SEQ / 32; ++c) {
    if (c + 1 < T_SEQ / 32) {
      load_stage((c + 1) & 1, (c + 1) * 32);
      asm volatile("cp.async.wait_group 1;" ::: "memory");
    } else {
      asm volatile("cp.async.wait_group 0;" ::: "memory");
    }
    __syncthreads();
    const u32 st = sb + (c & 1) * ATT_STAGE;

    // ---- Phase A: S = Q K^T (3xTF32) ----
    float S[4][4] = {};
#pragma unroll
    for (int kc = 0; kc < 8; ++kc) {
      u32 kh0[4], kh1[4], kl0[4], kl1[4];
      u32 ka = st + kc * 32 + k_lane;
      LDSM4(kh0, ka);
      LDSM4(kh1, ka + 4352);
      LDSM4(kl0, ka + 8704);
      LDSM4(kl1, ka + 8704 + 4352);
      mma_tf32(S[0], qfh[kc], kh0[0], kh0[1]);
      mma_tf32(S[1], qfh[kc], kh0[2], kh0[3]);
      mma_tf32(S[2], qfh[kc], kh1[0], kh1[1]);
      mma_tf32(S[3], qfh[kc], kh1[2], kh1[3]);
      mma_tf32(S[0], qfh[kc], kl0[0], kl0[1]);
      mma_tf32(S[1], qfh[kc], kl0[2], kl0[3]);
      mma_tf32(S[2], qfh[kc], kl1[0], kl1[1]);
      mma_tf32(S[3], qfh[kc], kl1[2], kl1[3]);
      mma_tf32(S[0], qfl[kc], kh0[0], kh0[1]);
      mma_tf32(S[1], qfl[kc], kh0[2], kh0[3]);
      mma_tf32(S[2], qfl[kc], kh1[0], kh1[1]);
      mma_tf32(S[3], qfl[kc], kh1[2], kh1[3]);
    }

    // ---- Scan on fragments (quad-wide), divide, split W to smem ----
#pragma unroll
    for (int half = 0; half < 2; ++half) {
      float bb = half ? carry1 : carry0;
      int wrow = g + half * 8;
#pragma unroll
      for (int nf = 0; nf < 4; ++nf) {
        float s0 = S[nf][half * 2], s1 = S[nf][half * 2 + 1];
        float run = s0 + s1;
        float n1 = __shfl_up_sync(FULL, run, 1, 4); if (qd >= 1) run += n1;
        float n2 = __shfl_up_sync(FULL, run, 2, 4); if (qd >= 2) run += n2;
        float cum1 = bb + run;
        float cum0 = cum1 - s1;
        float w0 = __fdividef(s0, fmaxf(cum0, 1e-6f));
        float w1 = __fdividef(s1, fmaxf(cum1, 1e-6f));
        bb += __shfl_sync(FULL, run, 3, 4);
        __nv_bfloat162 h2, l2;
        h2.x = __float2bfloat16(w0); l2.x = __float2bfloat16(w0 - __bfloat162float(h2.x));
        h2.y = __float2bfloat16(w1); l2.y = __float2bfloat16(w1 - __bfloat162float(h2.y));
        int woff = Wh_off + wrow * 80 + nf * 16 + qd * 4;
        *(__nv_bfloat162*)(smem + woff)        = h2;
        *(__nv_bfloat162*)(smem + woff + 1280) = l2;
      }
      if (half) carry1 = bb; else carry0 = bb;
    }
    __syncwarp();

    // ---- Phase B: Y += W @ V (bf16x3) ----
    const u32 vst = st + 17408;
#pragma unroll
    for (int ks = 0; ks < 2; ++ks) {
      u32 wah[4], wal[4];
      u32 wa = Wh_base + wa_lane + ks * 32;
      LDSM4(wah, wa);
      LDSM4(wal, wa + 1280);
#pragma unroll
      for (int ng = 0; ng < 4; ++ng) {
        u32 vh[4], vl[4];
        u32 va = vst + ng * 1280 + v_lane + ks * 32;
        LDSM4(vh, va);
        LDSM4(vl, va + 5120);
#pragma unroll
        for (int s = 0; s < 2; ++s) {
          int nf = ng * 2 + s;
          mma16816(Yacc[nf], wah, vh[s * 2], vh[s * 2 + 1]);
          mma16816(Yacc[nf], wah, vl[s * 2], vl[s * 2 + 1]);
          mma16816(Yacc[nf], wal, vh[s * 2], vh[s * 2 + 1]);
        }
      }
    }
    __syncthreads();
  }

  // ---- Epilogue: split Y to bf16 hi/lo, store [t][C] ----
  const int row0 = q0 + w * 16 + g;
  const int colb = h * HD + 2 * qd;
#pragma unroll
  for (int nf = 0; nf < 8; ++nf) {
    int col = colb + nf * 8;
    size_t o0 = (size_t)row0 * CDIM + col;
    size_t o1 = (size_t)(row0 + 8) * CDIM + col;
    __nv_bfloat162 h2, l2;
    h2.x = __float2bfloat16(Yacc[nf][0]);
    l2.x = __float2bfloat16(Yacc[nf][0] - __bfloat162float(h2.x));
    h2.y = __float2bfloat16(Yacc[nf][1]);
    l2.y = __float2bfloat16(Yacc[nf][1] - __bfloat162float(h2.y));
    *(__nv_bfloat162*)&Yh_[o0] = h2;
    *(__nv_bfloat162*)&Yl_[o0] = l2;
    h2.x = __float2bfloat16(Yacc[nf][2]);
    l2.x = __float2bfloat16(Yacc[nf][2] - __bfloat162float(h2.x));
    h2.y = __float2bfloat16(Yacc[nf][3]);
    l2.y = __float2bfloat16(Yacc[nf][3] - __bfloat162float(h2.y));
    *(__nv_bfloat162*)&Yh_[o1] = h2;
    *(__nv_bfloat162*)&Yl_[o1] = l2;
  }
}

// ---------------------------------------------------------------------------
extern "C" void kernel_launch(void* const* d_in, const int* in_sizes, int n_in,
                              void* d_out, int out_size)
{
  const float* x      = (const float*)d_in[0];
  const float* w_attn = (const float*)d_in[1];
  const float* b_attn = (const float*)d_in[2];
  const float* w_proj = (const float*)d_in[3];
  const float* b_proj = (const float*)d_in[4];
  float* out = (float*)d_out;

  float *qkv, *xh, *xl, *wah, *wal, *qh, *ql, *kh, *kl;
  __nv_bfloat16 *wph, *wpl, *vbh, *vbl, *yh, *yl;
  cudaGetSymbolAddress((void**)&qkv, g_qkv);
  cudaGetSymbolAddress((void**)&xh,  g_xh);
  cudaGetSymbolAddress((void**)&xl,  g_xl);
  cudaGetSymbolAddress((void**)&wah, g_wah);
  cudaGetSymbolAddress((void**)&wal, g_wal);
  cudaGetSymbolAddress((void**)&wph, g_wph);
  cudaGetSymbolAddress((void**)&wpl, g_wpl);
  cudaGetSymbolAddress((void**)&qh,  g_qh);
  cudaGetSymbolAddress((void**)&ql,  g_ql);
  cudaGetSymbolAddress((void**)&kh,  g_kh);
  cudaGetSymbolAddress((void**)&kl,  g_kl);
  cudaGetSymbolAddress((void**)&vbh, g_vbh);
  cudaGetSymbolAddress((void**)&vbl, g_vbl);
  cudaGetSymbolAddress((void**)&yh,  g_yh);
  cudaGetSymbolAddress((void**)&yl,  g_yl);

  cudaFuncSetAttribute(gemm_tf32,
                       cudaFuncAttributeMaxDynamicSharedMemorySize, TG_SMEM);
  cudaFuncSetAttribute(gemm_mma,
                       cudaFuncAttributeMaxDynamicSharedMemorySize, GEMM_SMEM);
  cudaFuncSetAttribute(attn_mma,
                       cudaFuncAttributeMaxDynamicSharedMemorySize, ATT_SMEM);

  const int n4 = T_SEQ * CDIM / 4;

  // 0) conversions
  split_pair<<<(n4 + 255) / 256, 256>>>(x, xh, xl, n4);
  transpose_split_pair<<<dim3(K3 / 32, CDIM / 32), dim3(32, 8)>>>(
      w_attn, wah, wal, CDIM, K3);
  transpose_split_bf16<<<dim3(CDIM / 32, CDIM / 32), dim3(32, 8)>>>(
      w_proj, wph, wpl, CDIM, CDIM);

  // 1) qkv = x @ w_attn + b_attn   (3xTF32 — precision-critical)
  gemm_tf32<<<dim3(K3 / 128, T_SEQ / 128), 256, TG_SMEM>>>(
      xh, xl, wah, wal, b_attn, qkv, T_SEQ, K3, CDIM);

  // 2) normalize + split q,k (tf32) and v (bf16, transposed)
  norm_split<<<dim3(T_SEQ / 64, NHEAD), 256>>>(qkv, qh, ql, kh, kl, vbh, vbl);

  // 3) tensorized cumulative linear attention -> yh/yl bf16
  attn_mma<<<dim3(T_SEQ / 64, NHEAD), 128, ATT_SMEM>>>(
      qh, ql, kh, kl, vbh, vbl, yh, yl);

  // 4) out = y @ w_proj + b_proj  (bf16x3)
  gemm_mma<<<dim3(CDIM / 128, T_SEQ / 128), 256, GEMM_SMEM>>>(
      yh, yl, wph, wpl, b_proj, out, T_SEQ, CDIM, CDIM);
}

// round 12
// speedup vs baseline: 3.1078x; 1.3951x over previous
#include <cuda_runtime.h>
#include <cuda_bf16.h>
#include <cuda_fp16.h>
#include <cstdint>

#define T_SEQ 4096
#define NHEAD 12
#define HD    64
#define CDIM  768
#define K3    (3*CDIM)

typedef unsigned int u32;

// ---- base-target helpers (sm_80+ PTX, no 'a' suffix) ----------------------
__device__ __forceinline__ u32 smem_u32(const void* p) {
  u32 a;
  asm("{ .reg .u64 t; cvta.to.shared.u64 t, %1; cvt.u32.u64 %0, t; }"
      : "=r"(a) : "l"(p));
  return a;
}
__device__ __forceinline__ void cpasync16(u32 dst, const void* src) {
  asm volatile("cp.async.ca.shared.global [%0], [%1], 16;"
               :: "r"(dst), "l"(src) : "memory");
}
#define CP_COMMIT() asm volatile("cp.async.commit_group;" ::: "memory")
#define LDSM4(R, addr)                                                        \
  asm volatile("ldmatrix.sync.aligned.m8n8.x4.shared.b16 {%0,%1,%2,%3}, [%4];"\
               : "=r"((R)[0]), "=r"((R)[1]), "=r"((R)[2]), "=r"((R)[3])       \
               : "r"(addr))
__device__ __forceinline__ void mma_bf16(float* c, const u32* a, u32 b0, u32 b1) {
  asm volatile(
      "mma.sync.aligned.m16n8k16.row.col.f32.bf16.bf16.f32 "
      "{%0,%1,%2,%3}, {%4,%5,%6,%7}, {%8,%9}, {%0,%1,%2,%3};"
      : "+f"(c[0]), "+f"(c[1]), "+f"(c[2]), "+f"(c[3])
      : "r"(a[0]), "r"(a[1]), "r"(a[2]), "r"(a[3]), "r"(b0), "r"(b1));
}
__device__ __forceinline__ void mma_f16(float* c, const u32* a, u32 b0, u32 b1) {
  asm volatile(
      "mma.sync.aligned.m16n8k16.row.col.f32.f16.f16.f32 "
      "{%0,%1,%2,%3}, {%4,%5,%6,%7}, {%8,%9}, {%0,%1,%2,%3};"
      : "+f"(c[0]), "+f"(c[1]), "+f"(c[2]), "+f"(c[3])
      : "r"(a[0]), "r"(a[1]), "r"(a[2]), "r"(a[3]), "r"(b0), "r"(b1));
}

// ---- scratch --------------------------------------------------------------
__device__ float g_qkv[T_SEQ * K3];
__device__ __half g_xh[T_SEQ * CDIM], g_xl[T_SEQ * CDIM];
__device__ __half g_wah[K3 * CDIM],  g_wal[K3 * CDIM];            // [N][K] fp16
__device__ __nv_bfloat16 g_wph[CDIM * CDIM], g_wpl[CDIM * CDIM];  // [N][K] bf16
__device__ __half g_qh[NHEAD * T_SEQ * HD], g_ql[NHEAD * T_SEQ * HD];  // [h][t][d]
__device__ __half g_kh[NHEAD * T_SEQ * HD], g_kl[NHEAD * T_SEQ * HD];  // [h][t][d]
__device__ __nv_bfloat16 g_vbh[NHEAD * HD * T_SEQ], g_vbl[NHEAD * HD * T_SEQ]; // [h][d][t]
__device__ __nv_bfloat16 g_yh[T_SEQ * CDIM], g_yl[T_SEQ * CDIM];

// ---------------------------------------------------------------------------
// split fp32 -> (hi, lo) fp16
// ---------------------------------------------------------------------------
__global__ __launch_bounds__(256) void split_f16(
    const float* __restrict__ in, __half* __restrict__ oh,
    __half* __restrict__ ol, int n4)
{
  int i = blockIdx.x * 256 + threadIdx.x;
  if (i >= n4) return;
  float4 v = ((const float4*)in)[i];
  __half h0 = __float2half(v.x), h1 = __float2half(v.y);
  __half h2 = __float2half(v.z), h3 = __float2half(v.w);
  __half l0 = __float2half(v.x - __half2float(h0));
  __half l1 = __float2half(v.y - __half2float(h1));
  __half l2 = __float2half(v.z - __half2float(h2));
  __half l3 = __float2half(v.w - __half2float(h3));
  ((__half2*)oh)[2 * i + 0] = __half2(h0, h1);
  ((__half2*)oh)[2 * i + 1] = __half2(h2, h3);
  ((__half2*)ol)[2 * i + 0] = __half2(l0, l1);
  ((__half2*)ol)[2 * i + 1] = __half2(l2, l3);
}

// ---------------------------------------------------------------------------
// transpose + split fp16: w[K][N] -> out[N][K] (hi, lo)
// ---------------------------------------------------------------------------
__global__ __launch_bounds__(256) void transpose_split_f16(
    const float* __restrict__ w, __half* __restrict__ oh,
    __half* __restrict__ ol, int K, int N)
{
  __shared__ float t[32][33];
  int n0 = blockIdx.x * 32, k0 = blockIdx.y * 32;
  int tx = threadIdx.x, ty = threadIdx.y;
#pragma unroll
  for (int i = ty; i < 32; i += 8)
    t[i][tx] = w[(size_t)(k0 + i) * N + n0 + tx];
  __syncthreads();
#pragma unroll
  for (int i = ty; i < 32; i += 8) {
    float v = t[tx][i];
    __half h = __float2half(v);
    __half l = __float2half(v - __half2float(h));
    oh[(size_t)(n0 + i) * K + k0 + tx] = h;
    ol[(size_t)(n0 + i) * K + k0 + tx] = l;
  }
}

// ---------------------------------------------------------------------------
// transpose + split bf16: w[K][N] -> out[N][K] (hi, lo) bf16
// ---------------------------------------------------------------------------
__global__ __launch_bounds__(256) void transpose_split_bf16(
    const float* __restrict__ w, __nv_bfloat16* __restrict__ oh,
    __nv_bfloat16* __restrict__ ol, int K, int N)
{
  __shared__ float t[32][33];
  int n0 = blockIdx.x * 32, k0 = blockIdx.y * 32;
  int tx = threadIdx.x, ty = threadIdx.y;
#pragma unroll
  for (int i = ty; i < 32; i += 8)
    t[i][tx] = w[(size_t)(k0 + i) * N + n0 + tx];
  __syncthreads();
#pragma unroll
  for (int i = ty; i < 32; i += 8) {
    float v = t[tx][i];
    __nv_bfloat16 h = __float2bfloat16(v);
    __nv_bfloat16 l = __float2bfloat16(v - __bfloat162float(h));
    oh[(size_t)(n0 + i) * K + k0 + tx] = h;
    ol[(size_t)(n0 + i) * K + k0 + tx] = l;
  }
}

// ---------------------------------------------------------------------------
// 16-bit 3-term GEMM skeleton (hi/lo operands, [N][K] B, bias epilogue).
// CTA 128x128, 8 warps (32x64), BK=32, cp.async double buffer, 80B rows.
// Instantiated for f16 (qkv) and bf16 (proj) via MMA macro parameter.
// ---------------------------------------------------------------------------
#define GSTAGE 40960
#define GEMM_SMEM (2 * GSTAGE)

#define GEMM_BODY(T16, MMA)                                                   \
  extern __shared__ char smem[];                                              \
  const u32 sb = smem_u32(smem);                                              \
  const int tid = threadIdx.x, lane = tid & 31, wid = tid >> 5;               \
  const int m0 = blockIdx.y << 7, n0 = blockIdx.x << 7;                       \
  const int wm = wid >> 1, wn = wid & 1;                                      \
  const T16* srcs[4] = {Ah, Al, Bh, Bl};                                      \
  float acc[2][8][4] = {};                                                    \
  const int nchunks = K >> 5;                                                 \
  auto load_stage = [&](int st, int k0) {                                     \
    u32 base = sb + st * GSTAGE;                                              \
    _Pragma("unroll")                                                         \
    for (int i = 0; i < 8; ++i) {                                             \
      int idx = tid + (i << 8);                                               \
      int ten = idx >> 9, u = idx & 511;                                      \
      int row = u >> 2, q = u & 3;                                            \
      int gr = (ten < 2 ? m0 : n0) + row;                                     \
      cpasync16(base + ten * 10240 + row * 80 + q * 16,                       \
                &srcs[ten][(size_t)gr * K + k0 + q * 8]);                     \
    }                                                                         \
    CP_COMMIT();                                                              \
  };                                                                          \
  load_stage(0, 0);                                                           \
  for (int c = 0; c < nchunks; ++c) {                                         \
    const bool pf = (c + 1 < nchunks);                                        \
    if (pf) load_stage((c + 1) & 1, (c + 1) << 5);                            \
    if (pf) asm volatile("cp.async.wait_group 1;" ::: "memory");              \
    else    asm volatile("cp.async.wait_group 0;" ::: "memory");              \
    __syncthreads();                                                          \
    const u32 base = sb + (c & 1) * GSTAGE;                                   \
    const u32 aA = base, aAl = base + 10240, aB = base + 20480,               \
              aBl = base + 30720;                                             \
    _Pragma("unroll")                                                         \
    for (int ks = 0; ks < 32; ks += 16) {                                     \
      const int arow = lane & 15, asel = lane >> 4;                           \
      u32 ah[2][4], al[2][4];                                                 \
      _Pragma("unroll")                                                       \
      for (int mt = 0; mt < 2; ++mt) {                                        \
        u32 off = (u32)((wm * 32 + mt * 16 + arow) * 80 +                     \
                        (ks + asel * 8) * 2);                                 \
        LDSM4(ah[mt], aA + off);                                              \
        LDSM4(al[mt], aAl + off);                                             \
      }                                                                       \
      const int nrow = (lane & 7) + ((lane >> 4) << 3);                       \
      const int koff = ks + (((lane >> 3) & 1) << 3);                         \
      u32 bh[4][4], bl[4][4];                                                 \
      _Pragma("unroll")                                                       \
      for (int ng = 0; ng < 4; ++ng) {                                        \
        u32 off = (u32)((wn * 64 + ng * 16 + nrow) * 80 + koff * 2);          \
        LDSM4(bh[ng], aB + off);                                              \
        LDSM4(bl[ng], aBl + off);                                             \
      }                                                                       \
      _Pragma("unroll")                                                       \
      for (int mt = 0; mt < 2; ++mt)                                          \
        _Pragma("unroll")                                                     \
        for (int nt = 0; nt < 8; ++nt) {                                      \
          const int ng = nt >> 1, sel = (nt & 1) << 1;                        \
          MMA(acc[mt][nt], ah[mt], bh[ng][sel], bh[ng][sel + 1]);             \
          MMA(acc[mt][nt], ah[mt], bl[ng][sel], bl[ng][sel + 1]);             \
          MMA(acc[mt][nt], al[mt], bh[ng][sel], bh[ng][sel + 1]);             \
        }                                                                     \
    }                                                                         \
    __syncthreads();                                                          \
  }                                                                           \
  const int rbase = m0 + wm * 32 + (lane >> 2);                               \
  const int cbase = n0 + wn * 64 + ((lane & 3) << 1);                         \
  _Pragma("unroll")                                                           \
  for (int mt = 0; mt < 2; ++mt)                                              \
    _Pragma("unroll")                                                         \
    for (int nt = 0; nt < 8; ++nt) {                                          \
      int row = rbase + mt * 16;                                              \
      int col = cbase + nt * 8;                                               \
      float b0 = bias[col], b1 = bias[col + 1];                               \
      *(float2*)&C[(size_t)row * N + col] =                                   \
          make_float2(acc[mt][nt][0] + b0, acc[mt][nt][1] + b1);              \
      *(float2*)&C[(size_t)(row + 8) * N + col] =                             \
          make_float2(acc[mt][nt][2] + b0, acc[mt][nt][3] + b1);              \
    }

__global__ __launch_bounds__(256, 1) void gemm_f16(
    const __half* __restrict__ Ah, const __half* __restrict__ Al,
    const __half* __restrict__ Bh, const __half* __restrict__ Bl,
    const float* __restrict__ bias, float* __restrict__ C,
    int M, int N, int K)
{
  GEMM_BODY(__half, mma_f16)
}

__global__ __launch_bounds__(256, 1) void gemm_bf16(
    const __nv_bfloat16* __restrict__ Ah, const __nv_bfloat16* __restrict__ Al,
    const __nv_bfloat16* __restrict__ Bh, const __nv_bfloat16* __restrict__ Bl,
    const float* __restrict__ bias, float* __restrict__ C,
    int M, int N, int K)
{
  GEMM_BODY(__nv_bfloat16, mma_bf16)
}

// ---------------------------------------------------------------------------
// Normalize q,k + split:
//   qkv[t][3C] -> Qh/Ql, Kh/Kl [h][t][d] fp16; Vbh/Vbl [h][d][t] bf16
// ---------------------------------------------------------------------------
__global__ __launch_bounds__(256) void norm_split(
    const float* __restrict__ qkv,
    __half* __restrict__ Qh, __half* __restrict__ Ql,
    __half* __restrict__ Kh, __half* __restrict__ Kl,
    __nv_bfloat16* __restrict__ Vbh, __nv_bfloat16* __restrict__ Vbl)
{
  __shared__ float Qs[64 * 68];
  __shared__ float Ks[64 * 68];
  __shared__ float invq[64], invk[64];
  const unsigned FULL = 0xffffffffu;
  const int h = blockIdx.y;
  const int t0 = blockIdx.x << 6;
  const int tid = threadIdx.x;

#pragma unroll
  for (int it = 0; it < 4; ++it) {
    int idx = tid + it * 256;
    int r = idx >> 4, c4 = (idx & 15) << 2;
    size_t base = (size_t)(t0 + r) * K3 + h * HD + c4;
    *(float4*)&Qs[r * 68 + c4] = *(const float4*)&qkv[base];
    *(float4*)&Ks[r * 68 + c4] = *(const float4*)&qkv[base + CDIM];
  }
  __syncthreads();

  {
    int row = tid >> 2, seg = tid & 3;
    float sq = 0.f, sk = 0.f;
#pragma unroll
    for (int i = 0; i < 16; ++i) {
      float a = Qs[row * 68 + seg * 16 + i];
      float b = Ks[row * 68 + seg * 16 + i];
      sq = fmaf(a, a, sq);
      sk = fmaf(b, b, sk);
    }
    sq += __shfl_xor_sync(FULL, sq, 1);
    sq += __shfl_xor_sync(FULL, sq, 2);
    sk += __shfl_xor_sync(FULL, sk, 1);
    sk += __shfl_xor_sync(FULL, sk, 2);
    if (seg == 0) {
      invq[row] = 1.0f / fmaxf(sqrtf(sq), 1e-12f);
      invk[row] = 1.0f / fmaxf(sqrtf(sk), 1e-12f);
    }
  }
  __syncthreads();

  {
    int r = tid >> 2, cseg = (tid & 3) << 4;
    float iq = invq[r], ik = invk[r];
    size_t ob = ((size_t)h * T_SEQ + t0 + r) * HD + cseg;
#pragma unroll
    for (int j = 0; j < 4; ++j) {
      float4 qv = *(float4*)&Qs[r * 68 + cseg + 4 * j];
      float4 kv = *(float4*)&Ks[r * 68 + cseg + 4 * j];
      float q0 = qv.x * iq, q1 = qv.y * iq, q2 = qv.z * iq, q3 = qv.w * iq;
      float k0 = kv.x * ik, k1 = kv.y * ik, k2 = kv.z * ik, k3 = kv.w * ik;
      __half2 qh2a(__float2half(q0), __float2half(q1));
      __half2 qh2b(__float2half(q2), __float2half(q3));
      __half2 ql2a(__float2half(q0 - __half2float(qh2a.x)),
                   __float2half(q1 - __half2float(qh2a.y)));
      __half2 ql2b(__float2half(q2 - __half2float(qh2b.x)),
                   __float2half(q3 - __half2float(qh2b.y)));
      __half2 kh2a(__float2half(k0), __float2half(k1));
      __half2 kh2b(__float2half(k2), __float2half(k3));
      __half2 kl2a(__float2half(k0 - __half2float(kh2a.x)),
                   __float2half(k1 - __half2float(kh2a.y)));
      __half2 kl2b(__float2half(k2 - __half2float(kh2b.x)),
                   __float2half(k3 - __half2float(kh2b.y)));
      *(__half2*)&Qh[ob + 4 * j]     = qh2a;
      *(__half2*)&Qh[ob + 4 * j + 2] = qh2b;
      *(__half2*)&Ql[ob + 4 * j]     = ql2a;
      *(__half2*)&Ql[ob + 4 * j + 2] = ql2b;
      *(__half2*)&Kh[ob + 4 * j]     = kh2a;
      *(__half2*)&Kh[ob + 4 * j + 2] = kh2b;
      *(__half2*)&Kl[ob + 4 * j]     = kl2a;
      *(__half2*)&Kl[ob + 4 * j + 2] = kl2b;
    }
  }
  __syncthreads();

  // Stage V, then write transposed bf16 hi/lo [h][d][t]
#pragma unroll
  for (int it = 0; it < 4; ++it) {
    int idx = tid + it * 256;
    int r = idx >> 4, c4 = (idx & 15) << 2;
    size_t base = (size_t)(t0 + r) * K3 + h * HD + 2 * CDIM + c4;
    *(float4*)&Qs[r * 68 + c4] = *(const float4*)&qkv[base];
  }
  __syncthreads();
  {
    int d = tid >> 2, tseg = (tid & 3) << 4;
    size_t vb = ((size_t)h * HD + d) * T_SEQ + t0 + tseg;
#pragma unroll
    for (int j = 0; j < 4; ++j) {
      float v0 = Qs[(tseg + 4 * j + 0) * 68 + d];
      float v1 = Qs[(tseg + 4 * j + 1) * 68 + d];
      float v2 = Qs[(tseg + 4 * j + 2) * 68 + d];
      float v3 = Qs[(tseg + 4 * j + 3) * 68 + d];
      __nv_bfloat162 h01, h23, l01, l23;
      h01.x = __float2bfloat16(v0); l01.x = __float2bfloat16(v0 - __bfloat162float(h01.x));
      h01.y = __float2bfloat16(v1); l01.y = __float2bfloat16(v1 - __bfloat162float(h01.y));
      h23.x = __float2bfloat16(v2); l23.x = __float2bfloat16(v2 - __bfloat162float(h23.x));
      h23.y = __float2bfloat16(v3); l23.y = __float2bfloat16(v3 - __bfloat162float(h23.y));
      *(__nv_bfloat162*)&Vbh[vb + 4 * j]     = h01;
      *(__nv_bfloat162*)&Vbh[vb + 4 * j + 2] = h23;
      *(__nv_bfloat162*)&Vbl[vb + 4 * j]     = l01;
      *(__nv_bfloat162*)&Vbl[vb + 4 * j + 2] = l23;
    }
  }
}

// ---------------------------------------------------------------------------
// Tensorized cumulative linear attention (fp16x3 S-phase).
// Grid (T/64, H), 128 thr (4 warps x 16 q-rows). 32-key tiles, double buffer.
// Phase A: S = QK^T in fp16x3 m16n8k16; quad scan w/ carries;
// W split bf16 -> warp-private smem; Phase B: Y += W@V in bf16x3.
// Stage: Kh/Kl 32x144B fp16, Vh/Vl 64x80B bf16 = 19456B x2; W: 4 x 2560B.
// ---------------------------------------------------------------------------
#define ATT_STAGE 19456
#define ATT_SMEM  (2 * ATT_STAGE + 4 * 2560)   // 49152

__global__ __launch_bounds__(128, 4) void attn_mma(
    const __half* __restrict__ Qh_, const __half* __restrict__ Ql_,
    const __half* __restrict__ Kh_, const __half* __restrict__ Kl_,
    const __nv_bfloat16* __restrict__ Vh_, const __nv_bfloat16* __restrict__ Vl_,
    __nv_bfloat16* __restrict__ Yh_, __nv_bfloat16* __restrict__ Yl_)
{
  extern __shared__ char smem[];
  const u32 sb = smem_u32(smem);
  const unsigned FULL = 0xffffffffu;
  const int h = blockIdx.y, q0 = blockIdx.x << 6;
  const int tid = threadIdx.x, lane = tid & 31, w = tid >> 5;
  const int g = lane >> 2, qd = lane & 3;

  // ---- Q fragments (one-time, fp16 m16n8k16 A layout from gmem) ----
  const u32* Qh32 = (const u32*)(Qh_ + ((size_t)h * T_SEQ + q0 + w * 16) * HD);
  const u32* Ql32 = (const u32*)(Ql_ + ((size_t)h * T_SEQ + q0 + w * 16) * HD);
  u32 qfh[4][4], qfl[4][4];
#pragma unroll
  for (int kc = 0; kc < 4; ++kc) {
    int c0 = kc * 8 + qd;
    qfh[kc][0] = Qh32[g * 32 + c0];       qfh[kc][1] = Qh32[(g + 8) * 32 + c0];
    qfh[kc][2] = Qh32[g * 32 + c0 + 4];   qfh[kc][3] = Qh32[(g + 8) * 32 + c0 + 4];
    qfl[kc][0] = Ql32[g * 32 + c0];       qfl[kc][1] = Ql32[(g + 8) * 32 + c0];
    qfl[kc][2] = Ql32[g * 32 + c0 + 4];   qfl[kc][3] = Ql32[(g + 8) * 32 + c0 + 4];
  }

  auto load_stage = [&](int st, int k0) {
    u32 base = sb + st * ATT_STAGE;
#pragma unroll
    for (int i = 0; i < 2; ++i) {
      int idx = tid + (i << 7);            // 0..255
      int row = idx >> 3, u = idx & 7;     // 32 rows x 8 x 16B (fp16)
      const __half* kh = Kh_ + ((size_t)h * T_SEQ + k0 + row) * HD + u * 8;
      const __half* kl = Kl_ + ((size_t)h * T_SEQ + k0 + row) * HD + u * 8;
      cpasync16(base + row * 144 + u * 16, kh);
      cpasync16(base + 4608 + row * 144 + u * 16, kl);
    }
#pragma unroll
    for (int i = 0; i < 2; ++i) {
      int idx = tid + (i << 7);            // 0..255
      int row = idx >> 2, u = idx & 3;     // 64 rows x 4 x 16B (bf16)
      const __nv_bfloat16* vh = Vh_ + ((size_t)h * HD + row) * T_SEQ + k0 + u * 8;
      const __nv_bfloat16* vl = Vl_ + ((size_t)h * HD + row) * T_SEQ + k0 + u * 8;
      cpasync16(base + 9216 + row * 80 + u * 16, vh);
      cpasync16(base + 14336 + row * 80 + u * 16, vl);
    }
    CP_COMMIT();
  };

  // lane-dependent ldmatrix offsets
  const u32 k_lane = (u32)(((lane & 7) + ((lane >> 4) << 3)) * 144
                           + ((lane >> 3) & 1) * 16);
  const u32 v_lane = (u32)(((lane & 7) + ((lane >> 4) & 1) * 8) * 80
                           + ((lane >> 3) & 1) * 16);
  const u32 wa_lane = (u32)((lane & 15) * 80 + (lane >> 4) * 16);
  const u32 Wh_base = sb + 2 * ATT_STAGE + w * 2560;
  const int Wh_off = 2 * ATT_STAGE + w * 2560;

  float Yacc[8][4] = {};
  float carry0 = 0.f, carry1 = 0.f;

  load_stage(0, 0);

  for (int c = 0; c < T_SEQ / 32; ++c) {
    if (c + 1 < T_SEQ / 32) {
      load_stage((c + 1) & 1, (c + 1) * 32);
      asm volatile("cp.async.wait_group 1;" ::: "memory");
    } else {
      asm volatile("cp.async.wait_group 0;" ::: "memory");
    }
    __syncthreads();
    const u32 st = sb + (c & 1) * ATT_STAGE;

    // ---- Phase A: S = Q K^T (fp16x3, k16) ----
    float S[4][4] = {};
#pragma unroll
    for (int kc = 0; kc < 4; ++kc) {
      u32 kh0[4], kh1[4], kl0[4], kl1[4];
      u32 ka = st + kc * 32 + k_lane;
      LDSM4(kh0, ka);                       // keys 0-15
      LDSM4(kh1, ka + 16 * 144);            // keys 16-31
      LDSM4(kl0, ka + 4608);
      LDSM4(kl1, ka + 4608 + 16 * 144);
      mma_f16(S[0], qfh[kc], kh0[0], kh0[1]);
      mma_f16(S[1], qfh[kc], kh0[2], kh0[3]);
      mma_f16(S[2], qfh[kc], kh1[0], kh1[1]);
      mma_f16(S[3], qfh[kc], kh1[2], kh1[3]);
      mma_f16(S[0], qfh[kc], kl0[0], kl0[1]);
      mma_f16(S[1], qfh[kc], kl0[2], kl0[3]);
      mma_f16(S[2], qfh[kc], kl1[0], kl1[1]);
      mma_f16(S[3], qfh[kc], kl1[2], kl1[3]);
      mma_f16(S[0], qfl[kc], kh0[0], kh0[1]);
      mma_f16(S[1], qfl[kc], kh0[2], kh0[3]);
      mma_f16(S[2], qfl[kc], kh1[0], kh1[1]);
      mma_f16(S[3], qfl[kc], kh1[2], kh1[3]);
    }

    // ---- Scan on fragments (quad-wide), divide, split W to smem ----
#pragma unroll
    for (int half = 0; half < 2; ++half) {
      float bb = half ? carry1 : carry0;
      int wrow = g + half * 8;
#pragma unroll
      for (int nf = 0; nf < 4; ++nf) {
        float s0 = S[nf][half * 2], s1 = S[nf][half * 2 + 1];
        float run = s0 + s1;
        float n1 = __shfl_up_sync(FULL, run, 1, 4); if (qd >= 1) run += n1;
        float n2 = __shfl_up_sync(FULL, run, 2, 4); if (qd >= 2) run += n2;
        float cum1 = bb + run;
        float cum0 = cum1 - s1;
        float w0 = __fdividef(s0, fmaxf(cum0, 1e-6f));
        float w1 = __fdividef(s1, fmaxf(cum1, 1e-6f));
        bb += __shfl_sync(FULL, run, 3, 4);
        __nv_bfloat162 h2, l2;
        h2.x = __float2bfloat16(w0); l2.x = __float2bfloat16(w0 - __bfloat162float(h2.x));
        h2.y = __float2bfloat16(w1); l2.y = __float2bfloat16(w1 - __bfloat162float(h2.y));
        int woff = Wh_off + wrow * 80 + nf * 16 + qd * 4;
        *(__nv_bfloat162*)(smem + woff)        = h2;
        *(__nv_bfloat162*)(smem + woff + 1280) = l2;
      }
      if (half) carry1 = bb; else carry0 = bb;
    }
    __syncwarp();

    // ---- Phase B: Y += W @ V (bf16x3) ----
    const u32 vst = st + 9216;
#pragma unroll
    for (int ks = 0; ks < 2; ++ks) {
      u32 wah[4], wal[4];
      u32 wa = Wh_base + wa_lane + ks * 32;
      LDSM4(wah, wa);
      LDSM4(wal, wa + 1280);
#pragma unroll
      for (int ng = 0; ng < 4; ++ng) {
        u32 vh[4], vl[4];
        u32 va = vst + ng * 1280 + v_lane + ks * 32;
        LDSM4(vh, va);
        LDSM4(vl, va + 5120);
#pragma unroll
        for (int s = 0; s < 2; ++s) {
          int nf = ng * 2 + s;
          mma_bf16(Yacc[nf], wah, vh[s * 2], vh[s * 2 + 1]);
          mma_bf16(Yacc[nf], wah, vl[s * 2], vl[s * 2 + 1]);
          mma_bf16(Yacc[nf], wal, vh[s * 2], vh[s * 2 + 1]);
        }
      }
    }
    __syncthreads();
  }

  // ---- Epilogue: split Y to bf16 hi/lo, store [t][C] ----
  const int row0 = q0 + w * 16 + g;
  const int colb = h * HD + 2 * qd;
#pragma unroll
  for (int nf = 0; nf < 8; ++nf) {
    int col = colb + nf * 8;
    size_t o0 = (size_t)row0 * CDIM + col;
    size_t o1 = (size_t)(row0 + 8) * CDIM + col;
    __nv_bfloat162 h2, l2;
    h2.x = __float2bfloat16(Yacc[nf][0]);
    l2.x = __float2bfloat16(Yacc[nf][0] - __bfloat162float(h2.x));
    h2.y = __float2bfloat16(Yacc[nf][1]);
    l2.y = __float2bfloat16(Yacc[nf][1] - __bfloat162float(h2.y));
    *(__nv_bfloat162*)&Yh_[o0] = h2;
    *(__nv_bfloat162*)&Yl_[o0] = l2;
    h2.x = __float2bfloat16(Yacc[nf][2]);
    l2.x = __float2bfloat16(Yacc[nf][2] - __bfloat162float(h2.x));
    h2.y = __float2bfloat16(Yacc[nf][3]);
    l2.y = __float2bfloat16(Yacc[nf][3] - __bfloat162float(h2.y));
    *(__nv_bfloat162*)&Yh_[o1] = h2;
    *(__nv_bfloat162*)&Yl_[o1] = l2;
  }
}

// ---------------------------------------------------------------------------
extern "C" void kernel_launch(void* const* d_in, const int* in_sizes, int n_in,
                              void* d_out, int out_size)
{
  const float* x      = (const float*)d_in[0];
  const float* w_attn = (const float*)d_in[1];
  const float* b_attn = (const float*)d_in[2];
  const float* w_proj = (const float*)d_in[3];
  const float* b_proj = (const float*)d_in[4];
  float* out = (float*)d_out;

  float* qkv;
  __half *xh, *xl, *wah, *wal, *qh, *ql, *kh, *kl;
  __nv_bfloat16 *wph, *wpl, *vbh, *vbl, *yh, *yl;
  cudaGetSymbolAddress((void**)&qkv, g_qkv);
  cudaGetSymbolAddress((void**)&xh,  g_xh);
  cudaGetSymbolAddress((void**)&xl,  g_xl);
  cudaGetSymbolAddress((void**)&wah, g_wah);
  cudaGetSymbolAddress((void**)&wal, g_wal);
  cudaGetSymbolAddress((void**)&wph, g_wph);
  cudaGetSymbolAddress((void**)&wpl, g_wpl);
  cudaGetSymbolAddress((void**)&qh,  g_qh);
  cudaGetSymbolAddress((void**)&ql,  g_ql);
  cudaGetSymbolAddress((void**)&kh,  g_kh);
  cudaGetSymbolAddress((void**)&kl,  g_kl);
  cudaGetSymbolAddress((void**)&vbh, g_vbh);
  cudaGetSymbolAddress((void**)&vbl, g_vbl);
  cudaGetSymbolAddress((void**)&yh,  g_yh);
  cudaGetSymbolAddress((void**)&yl,  g_yl);

  cudaFuncSetAttribute(gemm_f16,
                       cudaFuncAttributeMaxDynamicSharedMemorySize, GEMM_SMEM);
  cudaFuncSetAttribute(gemm_bf16,
                       cudaFuncAttributeMaxDynamicSharedMemorySize, GEMM_SMEM);
  cudaFuncSetAttribute(attn_mma,
                       cudaFuncAttributeMaxDynamicSharedMemorySize, ATT_SMEM);

  const int n4 = T_SEQ * CDIM / 4;

  // 0) conversions
  split_f16<<<(n4 + 255) / 256, 256>>>(x, xh, xl, n4);
  transpose_split_f16<<<dim3(K3 / 32, CDIM / 32), dim3(32, 8)>>>(
      w_attn, wah, wal, CDIM, K3);
  transpose_split_bf16<<<dim3(CDIM / 32, CDIM / 32), dim3(32, 8)>>>(
      w_proj, wph, wpl, CDIM, CDIM);

  // 1) qkv = x @ w_attn + b_attn   (fp16x3, k16 — same mantissa as tf32x3)
  gemm_f16<<<dim3(K3 / 128, T_SEQ / 128), 256, GEMM_SMEM>>>(
      xh, xl, wah, wal, b_attn, qkv, T_SEQ, K3, CDIM);

  // 2) normalize + split q,k (fp16) and v (bf16, transposed)
  norm_split<<<dim3(T_SEQ / 64, NHEAD), 256>>>(qkv, qh, ql, kh, kl, vbh, vbl);

  // 3) tensorized cumulative linear attention -> yh/yl bf16
  attn_mma<<<dim3(T_SEQ / 64, NHEAD), 128, ATT_SMEM>>>(
      qh, ql, kh, kl, vbh, vbl, yh, yl);

  // 4) out = y @ w_proj + b_proj  (bf16x3 — y range needs bf16 exponent)
  gemm_bf16<<<dim3(CDIM / 128, T_SEQ / 128), 256, GEMM_SMEM>>>(
      yh, yl, wph, wpl, b_proj, out, T_SEQ, CDIM, CDIM);
}

// round 13
// speedup vs baseline: 3.1825x; 1.0240x over previous
#include <cuda_runtime.h>
#include <cuda_bf16.h>
#include <cuda_fp16.h>
#include <cstdint>

#define T_SEQ 4096
#define NHEAD 12
#define HD    64
#define CDIM  768
#define K3    (3*CDIM)

typedef unsigned int u32;

// ---- base-target helpers (sm_80+ PTX, no 'a' suffix) ----------------------
__device__ __forceinline__ u32 smem_u32(const void* p) {
  u32 a;
  asm("{ .reg .u64 t; cvta.to.shared.u64 t, %1; cvt.u32.u64 %0, t; }"
      : "=r"(a) : "l"(p));
  return a;
}
__device__ __forceinline__ void cpasync16(u32 dst, const void* src) {
  asm volatile("cp.async.ca.shared.global [%0], [%1], 16;"
               :: "r"(dst), "l"(src) : "memory");
}
#define CP_COMMIT() asm volatile("cp.async.commit_group;" ::: "memory")
#define LDSM4(R, addr)                                                        \
  asm volatile("ldmatrix.sync.aligned.m8n8.x4.shared.b16 {%0,%1,%2,%3}, [%4];"\
               : "=r"((R)[0]), "=r"((R)[1]), "=r"((R)[2]), "=r"((R)[3])       \
               : "r"(addr))
__device__ __forceinline__ void mma_bf16(float* c, const u32* a, u32 b0, u32 b1) {
  asm volatile(
      "mma.sync.aligned.m16n8k16.row.col.f32.bf16.bf16.f32 "
      "{%0,%1,%2,%3}, {%4,%5,%6,%7}, {%8,%9}, {%0,%1,%2,%3};"
      : "+f"(c[0]), "+f"(c[1]), "+f"(c[2]), "+f"(c[3])
      : "r"(a[0]), "r"(a[1]), "r"(a[2]), "r"(a[3]), "r"(b0), "r"(b1));
}
__device__ __forceinline__ void mma_f16(float* c, const u32* a, u32 b0, u32 b1) {
  asm volatile(
      "mma.sync.aligned.m16n8k16.row.col.f32.f16.f16.f32 "
      "{%0,%1,%2,%3}, {%4,%5,%6,%7}, {%8,%9}, {%0,%1,%2,%3};"
      : "+f"(c[0]), "+f"(c[1]), "+f"(c[2]), "+f"(c[3])
      : "r"(a[0]), "r"(a[1]), "r"(a[2]), "r"(a[3]), "r"(b0), "r"(b1));
}

// ---- scratch --------------------------------------------------------------
__device__ float g_qkv[T_SEQ * K3];
__device__ __half g_xh[T_SEQ * CDIM], g_xl[T_SEQ * CDIM];
__device__ __half g_wah[K3 * CDIM],  g_wal[K3 * CDIM];            // [N][K] fp16
__device__ __nv_bfloat16 g_wph[CDIM * CDIM], g_wpl[CDIM * CDIM];  // [N][K] bf16
__device__ __half g_qh[NHEAD * T_SEQ * HD], g_ql[NHEAD * T_SEQ * HD];  // [h][t][d]
__device__ __half g_kh[NHEAD * T_SEQ * HD], g_kl[NHEAD * T_SEQ * HD];  // [h][t][d]
__device__ __nv_bfloat16 g_vbh[NHEAD * HD * T_SEQ], g_vbl[NHEAD * HD * T_SEQ]; // [h][d][t]
__device__ __nv_bfloat16 g_yh[T_SEQ * CDIM], g_yl[T_SEQ * CDIM];

// ---------------------------------------------------------------------------
// split fp32 -> (hi, lo) fp16
// ---------------------------------------------------------------------------
__global__ __launch_bounds__(256) void split_f16(
    const float* __restrict__ in, __half* __restrict__ oh,
    __half* __restrict__ ol, int n4)
{
  int i = blockIdx.x * 256 + threadIdx.x;
  if (i >= n4) return;
  float4 v = ((const float4*)in)[i];
  __half h0 = __float2half(v.x), h1 = __float2half(v.y);
  __half h2 = __float2half(v.z), h3 = __float2half(v.w);
  __half l0 = __float2half(v.x - __half2float(h0));
  __half l1 = __float2half(v.y - __half2float(h1));
  __half l2 = __float2half(v.z - __half2float(h2));
  __half l3 = __float2half(v.w - __half2float(h3));
  ((__half2*)oh)[2 * i + 0] = __half2(h0, h1);
  ((__half2*)oh)[2 * i + 1] = __half2(h2, h3);
  ((__half2*)ol)[2 * i + 0] = __half2(l0, l1);
  ((__half2*)ol)[2 * i + 1] = __half2(l2, l3);
}

// ---------------------------------------------------------------------------
// transpose + split fp16: w[K][N] -> out[N][K] (hi, lo)
// ---------------------------------------------------------------------------
__global__ __launch_bounds__(256) void transpose_split_f16(
    const float* __restrict__ w, __half* __restrict__ oh,
    __half* __restrict__ ol, int K, int N)
{
  __shared__ float t[32][33];
  int n0 = blockIdx.x * 32, k0 = blockIdx.y * 32;
  int tx = threadIdx.x, ty = threadIdx.y;
#pragma unroll
  for (int i = ty; i < 32; i += 8)
    t[i][tx] = w[(size_t)(k0 + i) * N + n0 + tx];
  __syncthreads();
#pragma unroll
  for (int i = ty; i < 32; i += 8) {
    float v = t[tx][i];
    __half h = __float2half(v);
    __half l = __float2half(v - __half2float(h));
    oh[(size_t)(n0 + i) * K + k0 + tx] = h;
    ol[(size_t)(n0 + i) * K + k0 + tx] = l;
  }
}

// ---------------------------------------------------------------------------
// transpose + split bf16: w[K][N] -> out[N][K] (hi, lo) bf16
// ---------------------------------------------------------------------------
__global__ __launch_bounds__(256) void transpose_split_bf16(
    const float* __restrict__ w, __nv_bfloat16* __restrict__ oh,
    __nv_bfloat16* __restrict__ ol, int K, int N)
{
  __shared__ float t[32][33];
  int n0 = blockIdx.x * 32, k0 = blockIdx.y * 32;
  int tx = threadIdx.x, ty = threadIdx.y;
#pragma unroll
  for (int i = ty; i < 32; i += 8)
    t[i][tx] = w[(size_t)(k0 + i) * N + n0 + tx];
  __syncthreads();
#pragma unroll
  for (int i = ty; i < 32; i += 8) {
    float v = t[tx][i];
    __nv_bfloat16 h = __float2bfloat16(v);
    __nv_bfloat16 l = __float2bfloat16(v - __bfloat162float(h));
    oh[(size_t)(n0 + i) * K + k0 + tx] = h;
    ol[(size_t)(n0 + i) * K + k0 + tx] = l;
  }
}

// ---------------------------------------------------------------------------
// 16-bit 3-term GEMM skeleton: 3-stage cp.async pipeline, ONE sync per chunk.
// CTA 128x128, 8 warps (32x64), BK=32, 80B rows.
// ---------------------------------------------------------------------------
#define GSTAGE 40960
#define GEMM_SMEM (3 * GSTAGE)

#define GEMM_BODY(T16, MMA)                                                   \
  extern __shared__ char smem[];                                              \
  const u32 sb = smem_u32(smem);                                              \
  const int tid = threadIdx.x, lane = tid & 31, wid = tid >> 5;               \
  const int m0 = blockIdx.y << 7, n0 = blockIdx.x << 7;                       \
  const int wm = wid >> 1, wn = wid & 1;                                      \
  const T16* srcs[4] = {Ah, Al, Bh, Bl};                                      \
  float acc[2][8][4] = {};                                                    \
  const int nchunks = K >> 5;                                                 \
  auto load_stage = [&](int st, int k0) {                                     \
    u32 base = sb + st * GSTAGE;                                              \
    _Pragma("unroll")                                                         \
    for (int i = 0; i < 8; ++i) {                                             \
      int idx = tid + (i << 8);                                               \
      int ten = idx >> 9, u = idx & 511;                                      \
      int row = u >> 2, q = u & 3;                                            \
      int gr = (ten < 2 ? m0 : n0) + row;                                     \
      cpasync16(base + ten * 10240 + row * 80 + q * 16,                       \
                &srcs[ten][(size_t)gr * K + k0 + q * 8]);                     \
    }                                                                         \
    CP_COMMIT();                                                              \
  };                                                                          \
  load_stage(0, 0);                                                           \
  if (nchunks > 1) load_stage(1, 32);                                         \
  int st = 0, st2 = (nchunks > 2) ? 2 : (nchunks > 1 ? 0 : 1);                \
  for (int c = 0; c < nchunks; ++c) {                                         \
    if (c + 1 < nchunks) asm volatile("cp.async.wait_group 1;" ::: "memory"); \
    else                 asm volatile("cp.async.wait_group 0;" ::: "memory"); \
    __syncthreads();                                                          \
    if (c + 2 < nchunks) {                                                    \
      load_stage(st2, (c + 2) << 5);                                          \
    }                                                                         \
    const u32 base = sb + st * GSTAGE;                                        \
    const u32 aA = base, aAl = base + 10240, aB = base + 20480,               \
              aBl = base + 30720;                                             \
    _Pragma("unroll")                                                         \
    for (int ks = 0; ks < 32; ks += 16) {                                     \
      const int arow = lane & 15, asel = lane >> 4;                           \
      u32 ah[2][4], al[2][4];                                                 \
      _Pragma("unroll")                                                       \
      for (int mt = 0; mt < 2; ++mt) {                                        \
        u32 off = (u32)((wm * 32 + mt * 16 + arow) * 80 +                     \
                        (ks + asel * 8) * 2);                                 \
        LDSM4(ah[mt], aA + off);                                              \
        LDSM4(al[mt], aAl + off);                                             \
      }                                                                       \
      const int nrow = (lane & 7) + ((lane >> 4) << 3);                       \
      const int koff = ks + (((lane >> 3) & 1) << 3);                         \
      u32 bh[4][4], bl[4][4];                                                 \
      _Pragma("unroll")                                                       \
      for (int ng = 0; ng < 4; ++ng) {                                        \
        u32 off = (u32)((wn * 64 + ng * 16 + nrow) * 80 + koff * 2);          \
        LDSM4(bh[ng], aB + off);                                              \
        LDSM4(bl[ng], aBl + off);                                             \
      }                                                                       \
      _Pragma("unroll")                                                       \
      for (int mt = 0; mt < 2; ++mt)                                          \
        _Pragma("unroll")                                                     \
        for (int nt = 0; nt < 8; ++nt) {                                      \
          const int ng = nt >> 1, sel = (nt & 1) << 1;                        \
          MMA(acc[mt][nt], ah[mt], bh[ng][sel], bh[ng][sel + 1]);             \
          MMA(acc[mt][nt], ah[mt], bl[ng][sel], bl[ng][sel + 1]);             \
          MMA(acc[mt][nt], al[mt], bh[ng][sel], bh[ng][sel + 1]);             \
        }                                                                     \
    }                                                                         \
    st = (st == 2) ? 0 : st + 1;                                              \
    st2 = (st2 == 2) ? 0 : st2 + 1;                                           \
  }                                                                           \
  const int rbase = m0 + wm * 32 + (lane >> 2);                               \
  const int cbase = n0 + wn * 64 + ((lane & 3) << 1);                         \
  _Pragma("unroll")                                                           \
  for (int mt = 0; mt < 2; ++mt)                                              \
    _Pragma("unroll")                                                         \
    for (int nt = 0; nt < 8; ++nt) {                                          \
      int row = rbase + mt * 16;                                              \
      int col = cbase + nt * 8;                                               \
      float b0 = bias[col], b1 = bias[col + 1];                               \
      *(float2*)&C[(size_t)row * N + col] =                                   \
          make_float2(acc[mt][nt][0] + b0, acc[mt][nt][1] + b1);              \
      *(float2*)&C[(size_t)(row + 8) * N + col] =                             \
          make_float2(acc[mt][nt][2] + b0, acc[mt][nt][3] + b1);              \
    }

__global__ __launch_bounds__(256, 1) void gemm_f16(
    const __half* __restrict__ Ah, const __half* __restrict__ Al,
    const __half* __restrict__ Bh, const __half* __restrict__ Bl,
    const float* __restrict__ bias, float* __restrict__ C,
    int M, int N, int K)
{
  GEMM_BODY(__half, mma_f16)
}

__global__ __launch_bounds__(256, 1) void gemm_bf16(
    const __nv_bfloat16* __restrict__ Ah, const __nv_bfloat16* __restrict__ Al,
    const __nv_bfloat16* __restrict__ Bh, const __nv_bfloat16* __restrict__ Bl,
    const float* __restrict__ bias, float* __restrict__ C,
    int M, int N, int K)
{
  GEMM_BODY(__nv_bfloat16, mma_bf16)
}

// ---------------------------------------------------------------------------
// Normalize q,k + split:
//   qkv[t][3C] -> Qh/Ql, Kh/Kl [h][t][d] fp16; Vbh/Vbl [h][d][t] bf16
// ---------------------------------------------------------------------------
__global__ __launch_bounds__(256) void norm_split(
    const float* __restrict__ qkv,
    __half* __restrict__ Qh, __half* __restrict__ Ql,
    __half* __restrict__ Kh, __half* __restrict__ Kl,
    __nv_bfloat16* __restrict__ Vbh, __nv_bfloat16* __restrict__ Vbl)
{
  __shared__ float Qs[64 * 68];
  __shared__ float Ks[64 * 68];
  __shared__ float invq[64], invk[64];
  const unsigned FULL = 0xffffffffu;
  const int h = blockIdx.y;
  const int t0 = blockIdx.x << 6;
  const int tid = threadIdx.x;

#pragma unroll
  for (int it = 0; it < 4; ++it) {
    int idx = tid + it * 256;
    int r = idx >> 4, c4 = (idx & 15) << 2;
    size_t base = (size_t)(t0 + r) * K3 + h * HD + c4;
    *(float4*)&Qs[r * 68 + c4] = *(const float4*)&qkv[base];
    *(float4*)&Ks[r * 68 + c4] = *(const float4*)&qkv[base + CDIM];
  }
  __syncthreads();

  {
    int row = tid >> 2, seg = tid & 3;
    float sq = 0.f, sk = 0.f;
#pragma unroll
    for (int i = 0; i < 16; ++i) {
      float a = Qs[row * 68 + seg * 16 + i];
      float b = Ks[row * 68 + seg * 16 + i];
      sq = fmaf(a, a, sq);
      sk = fmaf(b, b, sk);
    }
    sq += __shfl_xor_sync(FULL, sq, 1);
    sq += __shfl_xor_sync(FULL, sq, 2);
    sk += __shfl_xor_sync(FULL, sk, 1);
    sk += __shfl_xor_sync(FULL, sk, 2);
    if (seg == 0) {
      invq[row] = 1.0f / fmaxf(sqrtf(sq), 1e-12f);
      invk[row] = 1.0f / fmaxf(sqrtf(sk), 1e-12f);
    }
  }
  __syncthreads();

  {
    int r = tid >> 2, cseg = (tid & 3) << 4;
    float iq = invq[r], ik = invk[r];
    size_t ob = ((size_t)h * T_SEQ + t0 + r) * HD + cseg;
#pragma unroll
    for (int j = 0; j < 4; ++j) {
      float4 qv = *(float4*)&Qs[r * 68 + cseg + 4 * j];
      float4 kv = *(float4*)&Ks[r * 68 + cseg + 4 * j];
      float q0 = qv.x * iq, q1 = qv.y * iq, q2 = qv.z * iq, q3 = qv.w * iq;
      float k0 = kv.x * ik, k1 = kv.y * ik, k2 = kv.z * ik, k3 = kv.w * ik;
      __half2 qh2a(__float2half(q0), __float2half(q1));
      __half2 qh2b(__float2half(q2), __float2half(q3));
      __half2 ql2a(__float2half(q0 - __half2float(qh2a.x)),
                   __float2half(q1 - __half2float(qh2a.y)));
      __half2 ql2b(__float2half(q2 - __half2float(qh2b.x)),
                   __float2half(q3 - __half2float(qh2b.y)));
      __half2 kh2a(__float2half(k0), __float2half(k1));
      __half2 kh2b(__float2half(k2), __float2half(k3));
      __half2 kl2a(__float2half(k0 - __half2float(kh2a.x)),
                   __float2half(k1 - __half2float(kh2a.y)));
      __half2 kl2b(__float2half(k2 - __half2float(kh2b.x)),
                   __float2half(k3 - __half2float(kh2b.y)));
      *(__half2*)&Qh[ob + 4 * j]     = qh2a;
      *(__half2*)&Qh[ob + 4 * j + 2] = qh2b;
      *(__half2*)&Ql[ob + 4 * j]     = ql2a;
      *(__half2*)&Ql[ob + 4 * j + 2] = ql2b;
      *(__half2*)&Kh[ob + 4 * j]     = kh2a;
      *(__half2*)&Kh[ob + 4 * j + 2] = kh2b;
      *(__half2*)&Kl[ob + 4 * j]     = kl2a;
      *(__half2*)&Kl[ob + 4 * j + 2] = kl2b;
    }
  }
  __syncthreads();

  // Stage V, then write transposed bf16 hi/lo [h][d][t]
#pragma unroll
  for (int it = 0; it < 4; ++it) {
    int idx = tid + it * 256;
    int r = idx >> 4, c4 = (idx & 15) << 2;
    size_t base = (size_t)(t0 + r) * K3 + h * HD + 2 * CDIM + c4;
    *(float4*)&Qs[r * 68 + c4] = *(const float4*)&qkv[base];
  }
  __syncthreads();
  {
    int d = tid >> 2, tseg = (tid & 3) << 4;
    size_t vb = ((size_t)h * HD + d) * T_SEQ + t0 + tseg;
#pragma unroll
    for (int j = 0; j < 4; ++j) {
      float v0 = Qs[(tseg + 4 * j + 0) * 68 + d];
      float v1 = Qs[(tseg + 4 * j + 1) * 68 + d];
      float v2 = Qs[(tseg + 4 * j + 2) * 68 + d];
      float v3 = Qs[(tseg + 4 * j + 3) * 68 + d];
      __nv_bfloat162 h01, h23, l01, l23;
      h01.x = __float2bfloat16(v0); l01.x = __float2bfloat16(v0 - __bfloat162float(h01.x));
      h01.y = __float2bfloat16(v1); l01.y = __float2bfloat16(v1 - __bfloat162float(h01.y));
      h23.x = __float2bfloat16(v2); l23.x = __float2bfloat16(v2 - __bfloat162float(h23.x));
      h23.y = __float2bfloat16(v3); l23.y = __float2bfloat16(v3 - __bfloat162float(h23.y));
      *(__nv_bfloat162*)&Vbh[vb + 4 * j]     = h01;
      *(__nv_bfloat162*)&Vbh[vb + 4 * j + 2] = h23;
      *(__nv_bfloat162*)&Vbl[vb + 4 * j]     = l01;
      *(__nv_bfloat162*)&Vbl[vb + 4 * j + 2] = l23;
    }
  }
}

// ---------------------------------------------------------------------------
// Tensorized cumulative linear attention (fp16x3 S-phase).
// Grid (T/128, H), 256 thr (8 warps x 16 q-rows) — q-tile 128 halves K/V
// traffic per key. 32-key tiles, 2-stage cp.async, ONE syncthreads per tile.
// Stage: Kh/Kl 32x144B fp16, Vh/Vl 64x80B bf16 = 19456B x2; W: 8 x 2560B.
// ---------------------------------------------------------------------------
#define ATT_STAGE 19456
#define ATT_SMEM  (2 * ATT_STAGE + 8 * 2560)   // 59392

__global__ __launch_bounds__(256, 2) void attn_mma(
    const __half* __restrict__ Qh_, const __half* __restrict__ Ql_,
    const __half* __restrict__ Kh_, const __half* __restrict__ Kl_,
    const __nv_bfloat16* __restrict__ Vh_, const __nv_bfloat16* __restrict__ Vl_,
    __nv_bfloat16* __restrict__ Yh_, __nv_bfloat16* __restrict__ Yl_)
{
  extern __shared__ char smem[];
  const u32 sb = smem_u32(smem);
  const unsigned FULL = 0xffffffffu;
  const int h = blockIdx.y, q0 = blockIdx.x << 7;
  const int tid = threadIdx.x, lane = tid & 31, w = tid >> 5;
  const int g = lane >> 2, qd = lane & 3;

  // ---- Q fragments (one-time, fp16 m16n8k16 A layout from gmem) ----
  const u32* Qh32 = (const u32*)(Qh_ + ((size_t)h * T_SEQ + q0 + w * 16) * HD);
  const u32* Ql32 = (const u32*)(Ql_ + ((size_t)h * T_SEQ + q0 + w * 16) * HD);
  u32 qfh[4][4], qfl[4][4];
#pragma unroll
  for (int kc = 0; kc < 4; ++kc) {
    int c0 = kc * 8 + qd;
    qfh[kc][0] = Qh32[g * 32 + c0];       qfh[kc][1] = Qh32[(g + 8) * 32 + c0];
    qfh[kc][2] = Qh32[g * 32 + c0 + 4];   qfh[kc][3] = Qh32[(g + 8) * 32 + c0 + 4];
    qfl[kc][0] = Ql32[g * 32 + c0];       qfl[kc][1] = Ql32[(g + 8) * 32 + c0];
    qfl[kc][2] = Ql32[g * 32 + c0 + 4];   qfl[kc][3] = Ql32[(g + 8) * 32 + c0 + 4];
  }

  // 256-thread stage loader: K 512 chunks + V 512 chunks, 4 per thread
  auto load_stage = [&](int st, int k0) {
    u32 base = sb + st * ATT_STAGE;
#pragma unroll
    for (int i = 0; i < 2; ++i) {
      int idx = tid + (i << 8);            // 0..511
      int ten = idx >> 8, u = idx & 255;   // 32 rows x 8 x 16B per tensor
      int row = u >> 3, q8 = u & 7;
      const __half* src = (ten ? Kl_ : Kh_) +
          ((size_t)h * T_SEQ + k0 + row) * HD + q8 * 8;
      cpasync16(base + ten * 4608 + row * 144 + q8 * 16, src);
    }
#pragma unroll
    for (int i = 0; i < 2; ++i) {
      int idx = tid + (i << 8);            // 0..511
      int ten = idx >> 8, u = idx & 255;   // 64 rows x 4 x 16B per tensor
      int row = u >> 2, q4 = u & 3;
      const __nv_bfloat16* src = (ten ? Vl_ : Vh_) +
          ((size_t)h * HD + row) * T_SEQ + k0 + q4 * 8;
      cpasync16(base + 9216 + ten * 5120 + row * 80 + q4 * 16, src);
    }
    CP_COMMIT();
  };

  // lane-dependent ldmatrix offsets
  const u32 k_lane = (u32)(((lane & 7) + ((lane >> 4) << 3)) * 144
                           + ((lane >> 3) & 1) * 16);
  const u32 v_lane = (u32)(((lane & 7) + ((lane >> 4) & 1) * 8) * 80
                           + ((lane >> 3) & 1) * 16);
  const u32 wa_lane = (u32)((lane & 15) * 80 + (lane >> 4) * 16);
  const u32 Wh_base = sb + 2 * ATT_STAGE + w * 2560;
  const int Wh_off = 2 * ATT_STAGE + w * 2560;

  float Yacc[8][4] = {};
  float carry0 = 0.f, carry1 = 0.f;

  load_stage(0, 0);

  for (int c = 0; c < T_SEQ / 32; ++c) {
    asm volatile("cp.async.wait_group 0;" ::: "memory");
    __syncthreads();
    // Issue next load AFTER the barrier: the buffer being overwritten was
    // last read in iteration c-1, which all warps completed before this sync.
    if (c + 1 < T_SEQ / 32) load_stage((c + 1) & 1, (c + 1) * 32);

    const u32 st = sb + (c & 1) * ATT_STAGE;

    // ---- Phase A: S = Q K^T (fp16x3, k16) ----
    float S[4][4] = {};
#pragma unroll
    for (int kc = 0; kc < 4; ++kc) {
      u32 kh0[4], kh1[4], kl0[4], kl1[4];
      u32 ka = st + kc * 32 + k_lane;
      LDSM4(kh0, ka);                       // keys 0-15
      LDSM4(kh1, ka + 16 * 144);            // keys 16-31
      LDSM4(kl0, ka + 4608);
      LDSM4(kl1, ka + 4608 + 16 * 144);
      mma_f16(S[0], qfh[kc], kh0[0], kh0[1]);
      mma_f16(S[1], qfh[kc], kh0[2], kh0[3]);
      mma_f16(S[2], qfh[kc], kh1[0], kh1[1]);
      mma_f16(S[3], qfh[kc], kh1[2], kh1[3]);
      mma_f16(S[0], qfh[kc], kl0[0], kl0[1]);
      mma_f16(S[1], qfh[kc], kl0[2], kl0[3]);
      mma_f16(S[2], qfh[kc], kl1[0], kl1[1]);
      mma_f16(S[3], qfh[kc], kl1[2], kl1[3]);
      mma_f16(S[0], qfl[kc], kh0[0], kh0[1]);
      mma_f16(S[1], qfl[kc], kh0[2], kh0[3]);
      mma_f16(S[2], qfl[kc], kh1[0], kh1[1]);
      mma_f16(S[3], qfl[kc], kh1[2], kh1[3]);
    }

    // ---- Scan on fragments (quad-wide), divide, split W to smem ----
#pragma unroll
    for (int half = 0; half < 2; ++half) {
      float bb = half ? carry1 : carry0;
      int wrow = g + half * 8;
#pragma unroll
      for (int nf = 0; nf < 4; ++nf) {
        float s0 = S[nf][half * 2], s1 = S[nf][half * 2 + 1];
        float run = s0 + s1;
        float n1 = __shfl_up_sync(FULL, run, 1, 4); if (qd >= 1) run += n1;
        float n2 = __shfl_up_sync(FULL, run, 2, 4); if (qd >= 2) run += n2;
        float cum1 = bb + run;
        float cum0 = cum1 - s1;
        float w0 = __fdividef(s0, fmaxf(cum0, 1e-6f));
        float w1 = __fdividef(s1, fmaxf(cum1, 1e-6f));
        bb += __shfl_sync(FULL, run, 3, 4);
        __nv_bfloat162 h2, l2;
        h2.x = __float2bfloat16(w0); l2.x = __float2bfloat16(w0 - __bfloat162float(h2.x));
        h2.y = __float2bfloat16(w1); l2.y = __float2bfloat16(w1 - __bfloat162float(h2.y));
        int woff = Wh_off + wrow * 80 + nf * 16 + qd * 4;
        *(__nv_bfloat162*)(smem + woff)        = h2;
        *(__nv_bfloat162*)(smem + woff + 1280) = l2;
      }
      if (half) carry1 = bb; else carry0 = bb;
    }
    __syncwarp();

    // ---- Phase B: Y += W @ V (bf16x3) ----
    const u32 vst = st + 9216;
#pragma unroll
    for (int ks = 0; ks < 2; ++ks) {
      u32 wah[4], wal[4];
      u32 wa = Wh_base + wa_lane + ks * 32;
      LDSM4(wah, wa);
      LDSM4(wal, wa + 1280);
#pragma unroll
      for (int ng = 0; ng < 4; ++ng) {
        u32 vh[4], vl[4];
        u32 va = vst + ng * 1280 + v_lane + ks * 32;
        LDSM4(vh, va);
        LDSM4(vl, va + 5120);
#pragma unroll
        for (int s = 0; s < 2; ++s) {
          int nf = ng * 2 + s;
          mma_bf16(Yacc[nf], wah, vh[s * 2], vh[s * 2 + 1]);
          mma_bf16(Yacc[nf], wah, vl[s * 2], vl[s * 2 + 1]);
          mma_bf16(Yacc[nf], wal, vh[s * 2], vh[s * 2 + 1]);
        }
      }
    }
    // no trailing barrier: next iteration's top barrier seals stage reuse
  }

  // ---- Epilogue: split Y to bf16 hi/lo, store [t][C] ----
  const int row0 = q0 + w * 16 + g;
  const int colb = h * HD + 2 * qd;
#pragma unroll
  for (int nf = 0; nf < 8; ++nf) {
    int col = colb + nf * 8;
    size_t o0 = (size_t)row0 * CDIM + col;
    size_t o1 = (size_t)(row0 + 8) * CDIM + col;
    __nv_bfloat162 h2, l2;
    h2.x = __float2bfloat16(Yacc[nf][0]);
    l2.x = __float2bfloat16(Yacc[nf][0] - __bfloat162float(h2.x));
    h2.y = __float2bfloat16(Yacc[nf][1]);
    l2.y = __float2bfloat16(Yacc[nf][1] - __bfloat162float(h2.y));
    *(__nv_bfloat162*)&Yh_[o0] = h2;
    *(__nv_bfloat162*)&Yl_[o0] = l2;
    h2.x = __float2bfloat16(Yacc[nf][2]);
    l2.x = __float2bfloat16(Yacc[nf][2] - __bfloat162float(h2.x));
    h2.y = __float2bfloat16(Yacc[nf][3]);
    l2.y = __float2bfloat16(Yacc[nf][3] - __bfloat162float(h2.y));
    *(__nv_bfloat162*)&Yh_[o1] = h2;
    *(__nv_bfloat162*)&Yl_[o1] = l2;
  }
}

// ---------------------------------------------------------------------------
extern "C" void kernel_launch(void* const* d_in, const int* in_sizes, int n_in,
                              void* d_out, int out_size)
{
  const float* x      = (const float*)d_in[0];
  const float* w_attn = (const float*)d_in[1];
  const float* b_attn = (const float*)d_in[2];
  const float* w_proj = (const float*)d_in[3];
  const float* b_proj = (const float*)d_in[4];
  float* out = (float*)d_out;

  float* qkv;
  __half *xh, *xl, *wah, *wal, *qh, *ql, *kh, *kl;
  __nv_bfloat16 *wph, *wpl, *vbh, *vbl, *yh, *yl;
  cudaGetSymbolAddress((void**)&qkv, g_qkv);
  cudaGetSymbolAddress((void**)&xh,  g_xh);
  cudaGetSymbolAddress((void**)&xl,  g_xl);
  cudaGetSymbolAddress((void**)&wah, g_wah);
  cudaGetSymbolAddress((void**)&wal, g_wal);
  cudaGetSymbolAddress((void**)&wph, g_wph);
  cudaGetSymbolAddress((void**)&wpl, g_wpl);
  cudaGetSymbolAddress((void**)&qh,  g_qh);
  cudaGetSymbolAddress((void**)&ql,  g_ql);
  cudaGetSymbolAddress((void**)&kh,  g_kh);
  cudaGetSymbolAddress((void**)&kl,  g_kl);
  cudaGetSymbolAddress((void**)&vbh, g_vbh);
  cudaGetSymbolAddress((void**)&vbl, g_vbl);
  cudaGetSymbolAddress((void**)&yh,  g_yh);
  cudaGetSymbolAddress((void**)&yl,  g_yl);

  cudaFuncSetAttribute(gemm_f16,
                       cudaFuncAttributeMaxDynamicSharedMemorySize, GEMM_SMEM);
  cudaFuncSetAttribute(gemm_bf16,
                       cudaFuncAttributeMaxDynamicSharedMemorySize, GEMM_SMEM);
  cudaFuncSetAttribute(attn_mma,
                       cudaFuncAttributeMaxDynamicSharedMemorySize, ATT_SMEM);

  const int n4 = T_SEQ * CDIM / 4;

  // 0) conversions
  split_f16<<<(n4 + 255) / 256, 256>>>(x, xh, xl, n4);
  transpose_split_f16<<<dim3(K3 / 32, CDIM / 32), dim3(32, 8)>>>(
      w_attn, wah, wal, CDIM, K3);
  transpose_split_bf16<<<dim3(CDIM / 32, CDIM / 32), dim3(32, 8)>>>(
      w_proj, wph, wpl, CDIM, CDIM);

  // 1) qkv = x @ w_attn + b_attn   (fp16x3, 3-stage pipeline)
  gemm_f16<<<dim3(K3 / 128, T_SEQ / 128), 256, GEMM_SMEM>>>(
      xh, xl, wah, wal, b_attn, qkv, T_SEQ, K3, CDIM);

  // 2) normalize + split q,k (fp16) and v (bf16, transposed)
  norm_split<<<dim3(T_SEQ / 64, NHEAD), 256>>>(qkv, qh, ql, kh, kl, vbh, vbl);

  // 3) tensorized cumulative linear attention, q-tile 128 -> yh/yl bf16
  attn_mma<<<dim3(T_SEQ / 128, NHEAD), 256, ATT_SMEM>>>(
      qh, ql, kh, kl, vbh, vbl, yh, yl);

  // 4) out = y @ w_proj + b_proj  (bf16x3, 3-stage pipeline)
  gemm_bf16<<<dim3(CDIM / 128, T_SEQ / 128), 256, GEMM_SMEM>>>(
      yh, yl, wph, wpl, b_proj, out, T_SEQ, CDIM, CDIM);
}

// round 14
// speedup vs baseline: 3.2863x; 1.0326x over previous
#include <cuda_runtime.h>
#include <cuda_bf16.h>
#include <cuda_fp16.h>
#include <cstdint>

#define T_SEQ 4096
#define NHEAD 12
#define HD    64
#define CDIM  768
#define K3    (3*CDIM)

typedef unsigned int u32;

// ---- base-target helpers (sm_80+ PTX, no 'a' suffix) ----------------------
__device__ __forceinline__ u32 smem_u32(const void* p) {
  u32 a;
  asm("{ .reg .u64 t; cvta.to.shared.u64 t, %1; cvt.u32.u64 %0, t; }"
      : "=r"(a) : "l"(p));
  return a;
}
__device__ __forceinline__ void cpasync16(u32 dst, const void* src) {
  asm volatile("cp.async.ca.shared.global [%0], [%1], 16;"
               :: "r"(dst), "l"(src) : "memory");
}
#define CP_COMMIT() asm volatile("cp.async.commit_group;" ::: "memory")
#define LDSM4(R, addr)                                                        \
  asm volatile("ldmatrix.sync.aligned.m8n8.x4.shared.b16 {%0,%1,%2,%3}, [%4];"\
               : "=r"((R)[0]), "=r"((R)[1]), "=r"((R)[2]), "=r"((R)[3])       \
               : "r"(addr))
__device__ __forceinline__ void mma_bf16(float* c, const u32* a, u32 b0, u32 b1) {
  asm volatile(
      "mma.sync.aligned.m16n8k16.row.col.f32.bf16.bf16.f32 "
      "{%0,%1,%2,%3}, {%4,%5,%6,%7}, {%8,%9}, {%0,%1,%2,%3};"
      : "+f"(c[0]), "+f"(c[1]), "+f"(c[2]), "+f"(c[3])
      : "r"(a[0]), "r"(a[1]), "r"(a[2]), "r"(a[3]), "r"(b0), "r"(b1));
}
__device__ __forceinline__ void mma_f16(float* c, const u32* a, u32 b0, u32 b1) {
  asm volatile(
      "mma.sync.aligned.m16n8k16.row.col.f32.f16.f16.f32 "
      "{%0,%1,%2,%3}, {%4,%5,%6,%7}, {%8,%9}, {%0,%1,%2,%3};"
      : "+f"(c[0]), "+f"(c[1]), "+f"(c[2]), "+f"(c[3])
      : "r"(a[0]), "r"(a[1]), "r"(a[2]), "r"(a[3]), "r"(b0), "r"(b1));
}
// pack two fp32 into bf16x2 register (lo = first arg)
__device__ __forceinline__ u32 packbf2(float lo, float hi) {
  u32 r;
  asm("cvt.rn.bf16x2.f32 %0, %1, %2;" : "=r"(r) : "f"(hi), "f"(lo));
  return r;
}

// ---- scratch --------------------------------------------------------------
__device__ float g_qkv[T_SEQ * K3];
__device__ __half g_xh[T_SEQ * CDIM], g_xl[T_SEQ * CDIM];
__device__ __half g_wah[K3 * CDIM],  g_wal[K3 * CDIM];            // [N][K] fp16
__device__ __nv_bfloat16 g_wph[CDIM * CDIM], g_wpl[CDIM * CDIM];  // [N][K] bf16
__device__ __half g_qh[NHEAD * T_SEQ * HD], g_ql[NHEAD * T_SEQ * HD];  // [h][t][d]
__device__ __half g_kh[NHEAD * T_SEQ * HD], g_kl[NHEAD * T_SEQ * HD];  // [h][t][d]
__device__ __nv_bfloat16 g_vbh[NHEAD * HD * T_SEQ], g_vbl[NHEAD * HD * T_SEQ]; // [h][d][t]
__device__ __nv_bfloat16 g_yh[T_SEQ * CDIM], g_yl[T_SEQ * CDIM];

// ---------------------------------------------------------------------------
// split fp32 -> (hi, lo) fp16
// ---------------------------------------------------------------------------
__global__ __launch_bounds__(256) void split_f16(
    const float* __restrict__ in, __half* __restrict__ oh,
    __half* __restrict__ ol, int n4)
{
  int i = blockIdx.x * 256 + threadIdx.x;
  if (i >= n4) return;
  float4 v = ((const float4*)in)[i];
  __half h0 = __float2half(v.x), h1 = __float2half(v.y);
  __half h2 = __float2half(v.z), h3 = __float2half(v.w);
  __half l0 = __float2half(v.x - __half2float(h0));
  __half l1 = __float2half(v.y - __half2float(h1));
  __half l2 = __float2half(v.z - __half2float(h2));
  __half l3 = __float2half(v.w - __half2float(h3));
  ((__half2*)oh)[2 * i + 0] = __half2(h0, h1);
  ((__half2*)oh)[2 * i + 1] = __half2(h2, h3);
  ((__half2*)ol)[2 * i + 0] = __half2(l0, l1);
  ((__half2*)ol)[2 * i + 1] = __half2(l2, l3);
}

// ---------------------------------------------------------------------------
// transpose + split fp16: w[K][N] -> out[N][K] (hi, lo)
// ---------------------------------------------------------------------------
__global__ __launch_bounds__(256) void transpose_split_f16(
    const float* __restrict__ w, __half* __restrict__ oh,
    __half* __restrict__ ol, int K, int N)
{
  __shared__ float t[32][33];
  int n0 = blockIdx.x * 32, k0 = blockIdx.y * 32;
  int tx = threadIdx.x, ty = threadIdx.y;
#pragma unroll
  for (int i = ty; i < 32; i += 8)
    t[i][tx] = w[(size_t)(k0 + i) * N + n0 + tx];
  __syncthreads();
#pragma unroll
  for (int i = ty; i < 32; i += 8) {
    float v = t[tx][i];
    __half h = __float2half(v);
    __half l = __float2half(v - __half2float(h));
    oh[(size_t)(n0 + i) * K + k0 + tx] = h;
    ol[(size_t)(n0 + i) * K + k0 + tx] = l;
  }
}

// ---------------------------------------------------------------------------
// transpose + split bf16: w[K][N] -> out[N][K] (hi, lo) bf16
// ---------------------------------------------------------------------------
__global__ __launch_bounds__(256) void transpose_split_bf16(
    const float* __restrict__ w, __nv_bfloat16* __restrict__ oh,
    __nv_bfloat16* __restrict__ ol, int K, int N)
{
  __shared__ float t[32][33];
  int n0 = blockIdx.x * 32, k0 = blockIdx.y * 32;
  int tx = threadIdx.x, ty = threadIdx.y;
#pragma unroll
  for (int i = ty; i < 32; i += 8)
    t[i][tx] = w[(size_t)(k0 + i) * N + n0 + tx];
  __syncthreads();
#pragma unroll
  for (int i = ty; i < 32; i += 8) {
    float v = t[tx][i];
    __nv_bfloat16 h = __float2bfloat16(v);
    __nv_bfloat16 l = __float2bfloat16(v - __bfloat162float(h));
    oh[(size_t)(n0 + i) * K + k0 + tx] = h;
    ol[(size_t)(n0 + i) * K + k0 + tx] = l;
  }
}

// ---------------------------------------------------------------------------
// 16-bit 3-term GEMM skeleton: 3-stage cp.async pipeline, ONE sync per chunk.
// CTA 128x128, 8 warps (32x64), BK=32, 80B rows.
// ---------------------------------------------------------------------------
#define GSTAGE 40960
#define GEMM_SMEM (3 * GSTAGE)

#define GEMM_BODY(T16, MMA)                                                   \
  extern __shared__ char smem[];                                              \
  const u32 sb = smem_u32(smem);                                              \
  const int tid = threadIdx.x, lane = tid & 31, wid = tid >> 5;               \
  const int m0 = blockIdx.y << 7, n0 = blockIdx.x << 7;                       \
  const int wm = wid >> 1, wn = wid & 1;                                      \
  const T16* srcs[4] = {Ah, Al, Bh, Bl};                                      \
  float acc[2][8][4] = {};                                                    \
  const int nchunks = K >> 5;                                                 \
  auto load_stage = [&](int st, int k0) {                                     \
    u32 base = sb + st * GSTAGE;                                              \
    _Pragma("unroll")                                                         \
    for (int i = 0; i < 8; ++i) {                                             \
      int idx = tid + (i << 8);                                               \
      int ten = idx >> 9, u = idx & 511;                                      \
      int row = u >> 2, q = u & 3;                                            \
      int gr = (ten < 2 ? m0 : n0) + row;                                     \
      cpasync16(base + ten * 10240 + row * 80 + q * 16,                       \
                &srcs[ten][(size_t)gr * K + k0 + q * 8]);                     \
    }                                                                         \
    CP_COMMIT();                                                              \
  };                                                                          \
  load_stage(0, 0);                                                           \
  if (nchunks > 1) load_stage(1, 32);                                         \
  int st = 0, st2 = (nchunks > 2) ? 2 : (nchunks > 1 ? 0 : 1);                \
  for (int c = 0; c < nchunks; ++c) {                                         \
    if (c + 1 < nchunks) asm volatile("cp.async.wait_group 1;" ::: "memory"); \
    else                 asm volatile("cp.async.wait_group 0;" ::: "memory"); \
    __syncthreads();                                                          \
    if (c + 2 < nchunks) {                                                    \
      load_stage(st2, (c + 2) << 5);                                          \
    }                                                                         \
    const u32 base = sb + st * GSTAGE;                                        \
    const u32 aA = base, aAl = base + 10240, aB = base + 20480,               \
              aBl = base + 30720;                                             \
    _Pragma("unroll")                                                         \
    for (int ks = 0; ks < 32; ks += 16) {                                     \
      const int arow = lane & 15, asel = lane >> 4;                           \
      u32 ah[2][4], al[2][4];                                                 \
      _Pragma("unroll")                                                       \
      for (int mt = 0; mt < 2; ++mt) {                                        \
        u32 off = (u32)((wm * 32 + mt * 16 + arow) * 80 +                     \
                        (ks + asel * 8) * 2);                                 \
        LDSM4(ah[mt], aA + off);                                              \
        LDSM4(al[mt], aAl + off);                                             \
      }                                                                       \
      const int nrow = (lane & 7) + ((lane >> 4) << 3);                       \
      const int koff = ks + (((lane >> 3) & 1) << 3);                         \
      u32 bh[4][4], bl[4][4];                                                 \
      _Pragma("unroll")                                                       \
      for (int ng = 0; ng < 4; ++ng) {                                        \
        u32 off = (u32)((wn * 64 + ng * 16 + nrow) * 80 + koff * 2);          \
        LDSM4(bh[ng], aB + off);                                              \
        LDSM4(bl[ng], aBl + off);                                             \
      }                                                                       \
      _Pragma("unroll")                                                       \
      for (int mt = 0; mt < 2; ++mt)                                          \
        _Pragma("unroll")                                                     \
        for (int nt = 0; nt < 8; ++nt) {                                      \
          const int ng = nt >> 1, sel = (nt & 1) << 1;                        \
          MMA(acc[mt][nt], ah[mt], bh[ng][sel], bh[ng][sel + 1]);             \
          MMA(acc[mt][nt], ah[mt], bl[ng][sel], bl[ng][sel + 1]);             \
          MMA(acc[mt][nt], al[mt], bh[ng][sel], bh[ng][sel + 1]);             \
        }                                                                     \
    }                                                                         \
    st = (st == 2) ? 0 : st + 1;                                              \
    st2 = (st2 == 2) ? 0 : st2 + 1;                                           \
  }                                                                           \
  const int rbase = m0 + wm * 32 + (lane >> 2);                               \
  const int cbase = n0 + wn * 64 + ((lane & 3) << 1);                         \
  _Pragma("unroll")                                                           \
  for (int mt = 0; mt < 2; ++mt)                                              \
    _Pragma("unroll")                                                         \
    for (int nt = 0; nt < 8; ++nt) {                                          \
      int row = rbase + mt * 16;                                              \
      int col = cbase + nt * 8;                                               \
      float b0 = bias[col], b1 = bias[col + 1];                               \
      *(float2*)&C[(size_t)row * N + col] =                                   \
          make_float2(acc[mt][nt][0] + b0, acc[mt][nt][1] + b1);              \
      *(float2*)&C[(size_t)(row + 8) * N + col] =                             \
          make_float2(acc[mt][nt][2] + b0, acc[mt][nt][3] + b1);              \
    }

__global__ __launch_bounds__(256, 1) void gemm_f16(
    const __half* __restrict__ Ah, const __half* __restrict__ Al,
    const __half* __restrict__ Bh, const __half* __restrict__ Bl,
    const float* __restrict__ bias, float* __restrict__ C,
    int M, int N, int K)
{
  GEMM_BODY(__half, mma_f16)
}

__global__ __launch_bounds__(256, 1) void gemm_bf16(
    const __nv_bfloat16* __restrict__ Ah, const __nv_bfloat16* __restrict__ Al,
    const __nv_bfloat16* __restrict__ Bh, const __nv_bfloat16* __restrict__ Bl,
    const float* __restrict__ bias, float* __restrict__ C,
    int M, int N, int K)
{
  GEMM_BODY(__nv_bfloat16, mma_bf16)
}

// ---------------------------------------------------------------------------
// Normalize q,k + split:
//   qkv[t][3C] -> Qh/Ql, Kh/Kl [h][t][d] fp16; Vbh/Vbl [h][d][t] bf16
// ---------------------------------------------------------------------------
__global__ __launch_bounds__(256) void norm_split(
    const float* __restrict__ qkv,
    __half* __restrict__ Qh, __half* __restrict__ Ql,
    __half* __restrict__ Kh, __half* __restrict__ Kl,
    __nv_bfloat16* __restrict__ Vbh, __nv_bfloat16* __restrict__ Vbl)
{
  __shared__ float Qs[64 * 68];
  __shared__ float Ks[64 * 68];
  __shared__ float invq[64], invk[64];
  const unsigned FULL = 0xffffffffu;
  const int h = blockIdx.y;
  const int t0 = blockIdx.x << 6;
  const int tid = threadIdx.x;

#pragma unroll
  for (int it = 0; it < 4; ++it) {
    int idx = tid + it * 256;
    int r = idx >> 4, c4 = (idx & 15) << 2;
    size_t base = (size_t)(t0 + r) * K3 + h * HD + c4;
    *(float4*)&Qs[r * 68 + c4] = *(const float4*)&qkv[base];
    *(float4*)&Ks[r * 68 + c4] = *(const float4*)&qkv[base + CDIM];
  }
  __syncthreads();

  {
    int row = tid >> 2, seg = tid & 3;
    float sq = 0.f, sk = 0.f;
#pragma unroll
    for (int i = 0; i < 16; ++i) {
      float a = Qs[row * 68 + seg * 16 + i];
      float b = Ks[row * 68 + seg * 16 + i];
      sq = fmaf(a, a, sq);
      sk = fmaf(b, b, sk);
    }
    sq += __shfl_xor_sync(FULL, sq, 1);
    sq += __shfl_xor_sync(FULL, sq, 2);
    sk += __shfl_xor_sync(FULL, sk, 1);
    sk += __shfl_xor_sync(FULL, sk, 2);
    if (seg == 0) {
      invq[row] = 1.0f / fmaxf(sqrtf(sq), 1e-12f);
      invk[row] = 1.0f / fmaxf(sqrtf(sk), 1e-12f);
    }
  }
  __syncthreads();

  {
    int r = tid >> 2, cseg = (tid & 3) << 4;
    float iq = invq[r], ik = invk[r];
    size_t ob = ((size_t)h * T_SEQ + t0 + r) * HD + cseg;
#pragma unroll
    for (int j = 0; j < 4; ++j) {
      float4 qv = *(float4*)&Qs[r * 68 + cseg + 4 * j];
      float4 kv = *(float4*)&Ks[r * 68 + cseg + 4 * j];
      float q0 = qv.x * iq, q1 = qv.y * iq, q2 = qv.z * iq, q3 = qv.w * iq;
      float k0 = kv.x * ik, k1 = kv.y * ik, k2 = kv.z * ik, k3 = kv.w * ik;
      __half2 qh2a(__float2half(q0), __float2half(q1));
      __half2 qh2b(__float2half(q2), __float2half(q3));
      __half2 ql2a(__float2half(q0 - __half2float(qh2a.x)),
                   __float2half(q1 - __half2float(qh2a.y)));
      __half2 ql2b(__float2half(q2 - __half2float(qh2b.x)),
                   __float2half(q3 - __half2float(qh2b.y)));
      __half2 kh2a(__float2half(k0), __float2half(k1));
      __half2 kh2b(__float2half(k2), __float2half(k3));
      __half2 kl2a(__float2half(k0 - __half2float(kh2a.x)),
                   __float2half(k1 - __half2float(kh2a.y)));
      __half2 kl2b(__float2half(k2 - __half2float(kh2b.x)),
                   __float2half(k3 - __half2float(kh2b.y)));
      *(__half2*)&Qh[ob + 4 * j]     = qh2a;
      *(__half2*)&Qh[ob + 4 * j + 2] = qh2b;
      *(__half2*)&Ql[ob + 4 * j]     = ql2a;
      *(__half2*)&Ql[ob + 4 * j + 2] = ql2b;
      *(__half2*)&Kh[ob + 4 * j]     = kh2a;
      *(__half2*)&Kh[ob + 4 * j + 2] = kh2b;
      *(__half2*)&Kl[ob + 4 * j]     = kl2a;
      *(__half2*)&Kl[ob + 4 * j + 2] = kl2b;
    }
  }
  __syncthreads();

  // Stage V, then write transposed bf16 hi/lo [h][d][t]
#pragma unroll
  for (int it = 0; it < 4; ++it) {
    int idx = tid + it * 256;
    int r = idx >> 4, c4 = (idx & 15) << 2;
    size_t base = (size_t)(t0 + r) * K3 + h * HD + 2 * CDIM + c4;
    *(float4*)&Qs[r * 68 + c4] = *(const float4*)&qkv[base];
  }
  __syncthreads();
  {
    int d = tid >> 2, tseg = (tid & 3) << 4;
    size_t vb = ((size_t)h * HD + d) * T_SEQ + t0 + tseg;
#pragma unroll
    for (int j = 0; j < 4; ++j) {
      float v0 = Qs[(tseg + 4 * j + 0) * 68 + d];
      float v1 = Qs[(tseg + 4 * j + 1) * 68 + d];
      float v2 = Qs[(tseg + 4 * j + 2) * 68 + d];
      float v3 = Qs[(tseg + 4 * j + 3) * 68 + d];
      __nv_bfloat162 h01, h23, l01, l23;
      h01.x = __float2bfloat16(v0); l01.x = __float2bfloat16(v0 - __bfloat162float(h01.x));
      h01.y = __float2bfloat16(v1); l01.y = __float2bfloat16(v1 - __bfloat162float(h01.y));
      h23.x = __float2bfloat16(v2); l23.x = __float2bfloat16(v2 - __bfloat162float(h23.x));
      h23.y = __float2bfloat16(v3); l23.y = __float2bfloat16(v3 - __bfloat162float(h23.y));
      *(__nv_bfloat162*)&Vbh[vb + 4 * j]     = h01;
      *(__nv_bfloat162*)&Vbh[vb + 4 * j + 2] = h23;
      *(__nv_bfloat162*)&Vbl[vb + 4 * j]     = l01;
      *(__nv_bfloat162*)&Vbl[vb + 4 * j + 2] = l23;
    }
  }
}

// ---------------------------------------------------------------------------
// Tensorized cumulative linear attention (fp16x3 S-phase).
// Grid (T/128, H), 256 thr (8 warps x 16 q-rows). 32-key tiles, 2-stage
// cp.async, ONE syncthreads per tile.
// Key change vs R13: NO W smem round-trip — the S C-fragments are rescaled
// and repacked directly into Phase-B A-fragments (C-frag pair == A-frag),
// and the scan's segment carry chain is parallelized (independent quad scans
// + scalar prefix combine; identical add order -> bit-identical results).
// Stage: Kh/Kl 32x144B fp16, Vh/Vl 64x80B bf16 = 19456B x2.
// ---------------------------------------------------------------------------
#define ATT_STAGE 19456
#define ATT_SMEM  (2 * ATT_STAGE)   // 38912

__global__ __launch_bounds__(256, 2) void attn_mma(
    const __half* __restrict__ Qh_, const __half* __restrict__ Ql_,
    const __half* __restrict__ Kh_, const __half* __restrict__ Kl_,
    const __nv_bfloat16* __restrict__ Vh_, const __nv_bfloat16* __restrict__ Vl_,
    __nv_bfloat16* __restrict__ Yh_, __nv_bfloat16* __restrict__ Yl_)
{
  extern __shared__ char smem[];
  const u32 sb = smem_u32(smem);
  const unsigned FULL = 0xffffffffu;
  const int h = blockIdx.y, q0 = blockIdx.x << 7;
  const int tid = threadIdx.x, lane = tid & 31, w = tid >> 5;
  const int g = lane >> 2, qd = lane & 3;

  // ---- Q fragments (one-time, fp16 m16n8k16 A layout from gmem) ----
  const u32* Qh32 = (const u32*)(Qh_ + ((size_t)h * T_SEQ + q0 + w * 16) * HD);
  const u32* Ql32 = (const u32*)(Ql_ + ((size_t)h * T_SEQ + q0 + w * 16) * HD);
  u32 qfh[4][4], qfl[4][4];
#pragma unroll
  for (int kc = 0; kc < 4; ++kc) {
    int c0 = kc * 8 + qd;
    qfh[kc][0] = Qh32[g * 32 + c0];       qfh[kc][1] = Qh32[(g + 8) * 32 + c0];
    qfh[kc][2] = Qh32[g * 32 + c0 + 4];   qfh[kc][3] = Qh32[(g + 8) * 32 + c0 + 4];
    qfl[kc][0] = Ql32[g * 32 + c0];       qfl[kc][1] = Ql32[(g + 8) * 32 + c0];
    qfl[kc][2] = Ql32[g * 32 + c0 + 4];   qfl[kc][3] = Ql32[(g + 8) * 32 + c0 + 4];
  }

  // 256-thread stage loader: K 512 chunks + V 512 chunks, 4 per thread
  auto load_stage = [&](int st, int k0) {
    u32 base = sb + st * ATT_STAGE;
#pragma unroll
    for (int i = 0; i < 2; ++i) {
      int idx = tid + (i << 8);            // 0..511
      int ten = idx >> 8, u = idx & 255;   // 32 rows x 8 x 16B per tensor
      int row = u >> 3, q8 = u & 7;
      const __half* src = (ten ? Kl_ : Kh_) +
          ((size_t)h * T_SEQ + k0 + row) * HD + q8 * 8;
      cpasync16(base + ten * 4608 + row * 144 + q8 * 16, src);
    }
#pragma unroll
    for (int i = 0; i < 2; ++i) {
      int idx = tid + (i << 8);            // 0..511
      int ten = idx >> 8, u = idx & 255;   // 64 rows x 4 x 16B per tensor
      int row = u >> 2, q4 = u & 3;
      const __nv_bfloat16* src = (ten ? Vl_ : Vh_) +
          ((size_t)h * HD + row) * T_SEQ + k0 + q4 * 8;
      cpasync16(base + 9216 + ten * 5120 + row * 80 + q4 * 16, src);
    }
    CP_COMMIT();
  };

  // lane-dependent ldmatrix offsets
  const u32 k_lane = (u32)(((lane & 7) + ((lane >> 4) << 3)) * 144
                           + ((lane >> 3) & 1) * 16);
  const u32 v_lane = (u32)(((lane & 7) + ((lane >> 4) & 1) * 8) * 80
                           + ((lane >> 3) & 1) * 16);

  float Yacc[8][4] = {};
  float carry0 = 0.f, carry1 = 0.f;

  load_stage(0, 0);

  for (int c = 0; c < T_SEQ / 32; ++c) {
    asm volatile("cp.async.wait_group 0;" ::: "memory");
    __syncthreads();
    if (c + 1 < T_SEQ / 32) load_stage((c + 1) & 1, (c + 1) * 32);

    const u32 st = sb + (c & 1) * ATT_STAGE;

    // ---- Phase A: S = Q K^T (fp16x3, k16) ----
    float S[4][4] = {};
#pragma unroll
    for (int kc = 0; kc < 4; ++kc) {
      u32 kh0[4], kh1[4], kl0[4], kl1[4];
      u32 ka = st + kc * 32 + k_lane;
      LDSM4(kh0, ka);                       // keys 0-15
      LDSM4(kh1, ka + 16 * 144);            // keys 16-31
      LDSM4(kl0, ka + 4608);
      LDSM4(kl1, ka + 4608 + 16 * 144);
      mma_f16(S[0], qfh[kc], kh0[0], kh0[1]);
      mma_f16(S[1], qfh[kc], kh0[2], kh0[3]);
      mma_f16(S[2], qfh[kc], kh1[0], kh1[1]);
      mma_f16(S[3], qfh[kc], kh1[2], kh1[3]);
      mma_f16(S[0], qfh[kc], kl0[0], kl0[1]);
      mma_f16(S[1], qfh[kc], kl0[2], kl0[3]);
      mma_f16(S[2], qfh[kc], kl1[0], kl1[1]);
      mma_f16(S[3], qfh[kc], kl1[2], kl1[3]);
      mma_f16(S[0], qfl[kc], kh0[0], kh0[1]);
      mma_f16(S[1], qfl[kc], kh0[2], kh0[3]);
      mma_f16(S[2], qfl[kc], kh1[0], kh1[1]);
      mma_f16(S[3], qfl[kc], kh1[2], kh1[3]);
    }

    // ---- Scan on fragments: independent quad scans + prefix combine.
    //      W packed DIRECTLY into Phase-B A-fragments (C-frag == A-frag). ----
    u32 Wh[2][4], Wl[2][4];
#pragma unroll
    for (int half = 0; half < 2; ++half) {
      float bb = half ? carry1 : carry0;
      // independent per-segment quad scans (4 x 3-deep shuffle chains, parallel)
      float run[4], tot[4];
#pragma unroll
      for (int nf = 0; nf < 4; ++nf) {
        float s0 = S[nf][half * 2], s1 = S[nf][half * 2 + 1];
        float r = s0 + s1;
        float n1 = __shfl_up_sync(FULL, r, 1, 4); if (qd >= 1) r += n1;
        float n2 = __shfl_up_sync(FULL, r, 2, 4); if (qd >= 2) r += n2;
        run[nf] = r;
        tot[nf] = __shfl_sync(FULL, r, 3, 4);
      }
      // scalar prefix combine (same add order as serial version)
      float base[4];
      base[0] = bb;
      base[1] = base[0] + tot[0];
      base[2] = base[1] + tot[1];
      base[3] = base[2] + tot[2];
      bb = base[3] + tot[3];
#pragma unroll
      for (int nf = 0; nf < 4; ++nf) {
        float s1 = S[nf][half * 2 + 1];
        float s0 = S[nf][half * 2];
        float cum1 = base[nf] + run[nf];
        float cum0 = cum1 - s1;
        float w0 = __fdividef(s0, fmaxf(cum0, 1e-6f));
        float w1 = __fdividef(s1, fmaxf(cum1, 1e-6f));
        u32 hw = packbf2(w0, w1);
        __nv_bfloat162 hv = *(__nv_bfloat162*)&hw;
        u32 lw = packbf2(w0 - __bfloat162float(hv.x),
                         w1 - __bfloat162float(hv.y));
        // A-frag slot: ks = nf>>1; slot = ((nf&1)<<1) | half
        Wh[nf >> 1][((nf & 1) << 1) | half] = hw;
        Wl[nf >> 1][((nf & 1) << 1) | half] = lw;
      }
      if (half) carry1 = bb; else carry0 = bb;
    }

    // ---- Phase B: Y += W @ V (bf16x3, W fragments straight from registers) ----
    const u32 vst = st + 9216;
#pragma unroll
    for (int ks = 0; ks < 2; ++ks) {
#pragma unroll
      for (int ng = 0; ng < 4; ++ng) {
        u32 vh[4], vl[4];
        u32 va = vst + ng * 1280 + v_lane + ks * 32;
        LDSM4(vh, va);
        LDSM4(vl, va + 5120);
#pragma unroll
        for (int s = 0; s < 2; ++s) {
          int nf = ng * 2 + s;
          mma_bf16(Yacc[nf], Wh[ks], vh[s * 2], vh[s * 2 + 1]);
          mma_bf16(Yacc[nf], Wh[ks], vl[s * 2], vl[s * 2 + 1]);
          mma_bf16(Yacc[nf], Wl[ks], vh[s * 2], vh[s * 2 + 1]);
        }
      }
    }
    // no trailing barrier: next iteration's top barrier seals stage reuse
  }

  // ---- Epilogue: split Y to bf16 hi/lo, store [t][C] ----
  const int row0 = q0 + w * 16 + g;
  const int colb = h * HD + 2 * qd;
#pragma unroll
  for (int nf = 0; nf < 8; ++nf) {
    int col = colb + nf * 8;
    size_t o0 = (size_t)row0 * CDIM + col;
    size_t o1 = (size_t)(row0 + 8) * CDIM + col;
    __nv_bfloat162 h2, l2;
    h2.x = __float2bfloat16(Yacc[nf][0]);
    l2.x = __float2bfloat16(Yacc[nf][0] - __bfloat162float(h2.x));
    h2.y = __float2bfloat16(Yacc[nf][1]);
    l2.y = __float2bfloat16(Yacc[nf][1] - __bfloat162float(h2.y));
    *(__nv_bfloat162*)&Yh_[o0] = h2;
    *(__nv_bfloat162*)&Yl_[o0] = l2;
    h2.x = __float2bfloat16(Yacc[nf][2]);
    l2.x = __float2bfloat16(Yacc[nf][2] - __bfloat162float(h2.x));
    h2.y = __float2bfloat16(Yacc[nf][3]);
    l2.y = __float2bfloat16(Yacc[nf][3] - __bfloat162float(h2.y));
    *(__nv_bfloat162*)&Yh_[o1] = h2;
    *(__nv_bfloat162*)&Yl_[o1] = l2;
  }
}

// ---------------------------------------------------------------------------
extern "C" void kernel_launch(void* const* d_in, const int* in_sizes, int n_in,
                              void* d_out, int out_size)
{
  const float* x      = (const float*)d_in[0];
  const float* w_attn = (const float*)d_in[1];
  const float* b_attn = (const float*)d_in[2];
  const float* w_proj = (const float*)d_in[3];
  const float* b_proj = (const float*)d_in[4];
  float* out = (float*)d_out;

  float* qkv;
  __half *xh, *xl, *wah, *wal, *qh, *ql, *kh, *kl;
  __nv_bfloat16 *wph, *wpl, *vbh, *vbl, *yh, *yl;
  cudaGetSymbolAddress((void**)&qkv, g_qkv);
  cudaGetSymbolAddress((void**)&xh,  g_xh);
  cudaGetSymbolAddress((void**)&xl,  g_xl);
  cudaGetSymbolAddress((void**)&wah, g_wah);
  cudaGetSymbolAddress((void**)&wal, g_wal);
  cudaGetSymbolAddress((void**)&wph, g_wph);
  cudaGetSymbolAddress((void**)&wpl, g_wpl);
  cudaGetSymbolAddress((void**)&qh,  g_qh);
  cudaGetSymbolAddress((void**)&ql,  g_ql);
  cudaGetSymbolAddress((void**)&kh,  g_kh);
  cudaGetSymbolAddress((void**)&kl,  g_kl);
  cudaGetSymbolAddress((void**)&vbh, g_vbh);
  cudaGetSymbolAddress((void**)&vbl, g_vbl);
  cudaGetSymbolAddress((void**)&yh,  g_yh);
  cudaGetSymbolAddress((void**)&yl,  g_yl);

  cudaFuncSetAttribute(gemm_f16,
                       cudaFuncAttributeMaxDynamicSharedMemorySize, GEMM_SMEM);
  cudaFuncSetAttribute(gemm_bf16,
                       cudaFuncAttributeMaxDynamicSharedMemorySize, GEMM_SMEM);
  cudaFuncSetAttribute(attn_mma,
                       cudaFuncAttributeMaxDynamicSharedMemorySize, ATT_SMEM);

  const int n4 = T_SEQ * CDIM / 4;

  // 0) conversions
  split_f16<<<(n4 + 255) / 256, 256>>>(x, xh, xl, n4);
  transpose_split_f16<<<dim3(K3 / 32, CDIM / 32), dim3(32, 8)>>>(
      w_attn, wah, wal, CDIM, K3);
  transpose_split_bf16<<<dim3(CDIM / 32, CDIM / 32), dim3(32, 8)>>>(
      w_proj, wph, wpl, CDIM, CDIM);

  // 1) qkv = x @ w_attn + b_attn   (fp16x3)
  gemm_f16<<<dim3(K3 / 128, T_SEQ / 128), 256, GEMM_SMEM>>>(
      xh, xl, wah, wal, b_attn, qkv, T_SEQ, K3, CDIM);

  // 2) normalize + split q,k (fp16) and v (bf16, transposed)
  norm_split<<<dim3(T_SEQ / 64, NHEAD), 256>>>(qkv, qh, ql, kh, kl, vbh, vbl);

  // 3) tensorized cumulative linear attention -> yh/yl bf16
  attn_mma<<<dim3(T_SEQ / 128, NHEAD), 256, ATT_SMEM>>>(
      qh, ql, kh, kl, vbh, vbl, yh, yl);

  // 4) out = y @ w_proj + b_proj  (bf16x3)
  gemm_bf16<<<dim3(CDIM / 128, T_SEQ / 128), 256, GEMM_SMEM>>>(
      yh, yl, wph, wpl, b_proj, out, T_SEQ, CDIM, CDIM);
}

// round 15
// speedup vs baseline: 3.3988x; 1.0342x over previous
#include <cuda_runtime.h>
#include <cuda_bf16.h>
#include <cuda_fp16.h>
#include <cstdint>

#define T_SEQ 4096
#define NHEAD 12
#define HD    64
#define CDIM  768
#define K3    (3*CDIM)

typedef unsigned int u32;

// ---- base-target helpers (sm_80+ PTX, no 'a' suffix) ----------------------
__device__ __forceinline__ u32 smem_u32(const void* p) {
  u32 a;
  asm("{ .reg .u64 t; cvta.to.shared.u64 t, %1; cvt.u32.u64 %0, t; }"
      : "=r"(a) : "l"(p));
  return a;
}
__device__ __forceinline__ void cpasync16(u32 dst, const void* src) {
  asm volatile("cp.async.ca.shared.global [%0], [%1], 16;"
               :: "r"(dst), "l"(src) : "memory");
}
#define CP_COMMIT() asm volatile("cp.async.commit_group;" ::: "memory")
#define LDSM4(R, addr)                                                        \
  asm volatile("ldmatrix.sync.aligned.m8n8.x4.shared.b16 {%0,%1,%2,%3}, [%4];"\
               : "=r"((R)[0]), "=r"((R)[1]), "=r"((R)[2]), "=r"((R)[3])       \
               : "r"(addr))
__device__ __forceinline__ void mma_bf16(float* c, const u32* a, u32 b0, u32 b1) {
  asm volatile(
      "mma.sync.aligned.m16n8k16.row.col.f32.bf16.bf16.f32 "
      "{%0,%1,%2,%3}, {%4,%5,%6,%7}, {%8,%9}, {%0,%1,%2,%3};"
      : "+f"(c[0]), "+f"(c[1]), "+f"(c[2]), "+f"(c[3])
      : "r"(a[0]), "r"(a[1]), "r"(a[2]), "r"(a[3]), "r"(b0), "r"(b1));
}
__device__ __forceinline__ void mma_f16(float* c, const u32* a, u32 b0, u32 b1) {
  asm volatile(
      "mma.sync.aligned.m16n8k16.row.col.f32.f16.f16.f32 "
      "{%0,%1,%2,%3}, {%4,%5,%6,%7}, {%8,%9}, {%0,%1,%2,%3};"
      : "+f"(c[0]), "+f"(c[1]), "+f"(c[2]), "+f"(c[3])
      : "r"(a[0]), "r"(a[1]), "r"(a[2]), "r"(a[3]), "r"(b0), "r"(b1));
}
// pack two fp32 into bf16x2 register (lo = first arg)
__device__ __forceinline__ u32 packbf2(float lo, float hi) {
  u32 r;
  asm("cvt.rn.bf16x2.f32 %0, %1, %2;" : "=r"(r) : "f"(hi), "f"(lo));
  return r;
}

// ---- scratch --------------------------------------------------------------
__device__ float g_qkv[T_SEQ * K3];
__device__ __half g_xh[T_SEQ * CDIM], g_xl[T_SEQ * CDIM];
__device__ __half g_wah[K3 * CDIM],  g_wal[K3 * CDIM];            // [N][K] fp16
__device__ __nv_bfloat16 g_wph[CDIM * CDIM], g_wpl[CDIM * CDIM];  // [N][K] bf16
__device__ __half g_qh[NHEAD * T_SEQ * HD], g_ql[NHEAD * T_SEQ * HD];  // [h][t][d]
__device__ __half g_kh[NHEAD * T_SEQ * HD], g_kl[NHEAD * T_SEQ * HD];  // [h][t][d]
__device__ __nv_bfloat16 g_vbh[NHEAD * HD * T_SEQ], g_vbl[NHEAD * HD * T_SEQ]; // [h][d][t]
__device__ __nv_bfloat16 g_yh[T_SEQ * CDIM], g_yl[T_SEQ * CDIM];

// ---------------------------------------------------------------------------
// split fp32 -> (hi, lo) fp16
// ---------------------------------------------------------------------------
__global__ __launch_bounds__(256) void split_f16(
    const float* __restrict__ in, __half* __restrict__ oh,
    __half* __restrict__ ol, int n4)
{
  int i = blockIdx.x * 256 + threadIdx.x;
  if (i >= n4) return;
  float4 v = ((const float4*)in)[i];
  __half h0 = __float2half(v.x), h1 = __float2half(v.y);
  __half h2 = __float2half(v.z), h3 = __float2half(v.w);
  __half l0 = __float2half(v.x - __half2float(h0));
  __half l1 = __float2half(v.y - __half2float(h1));
  __half l2 = __float2half(v.z - __half2float(h2));
  __half l3 = __float2half(v.w - __half2float(h3));
  ((__half2*)oh)[2 * i + 0] = __half2(h0, h1);
  ((__half2*)oh)[2 * i + 1] = __half2(h2, h3);
  ((__half2*)ol)[2 * i + 0] = __half2(l0, l1);
  ((__half2*)ol)[2 * i + 1] = __half2(l2, l3);
}

// ---------------------------------------------------------------------------
// transpose + split fp16: w[K][N] -> out[N][K] (hi, lo)
// ---------------------------------------------------------------------------
__global__ __launch_bounds__(256) void transpose_split_f16(
    const float* __restrict__ w, __half* __restrict__ oh,
    __half* __restrict__ ol, int K, int N)
{
  __shared__ float t[32][33];
  int n0 = blockIdx.x * 32, k0 = blockIdx.y * 32;
  int tx = threadIdx.x, ty = threadIdx.y;
#pragma unroll
  for (int i = ty; i < 32; i += 8)
    t[i][tx] = w[(size_t)(k0 + i) * N + n0 + tx];
  __syncthreads();
#pragma unroll
  for (int i = ty; i < 32; i += 8) {
    float v = t[tx][i];
    __half h = __float2half(v);
    __half l = __float2half(v - __half2float(h));
    oh[(size_t)(n0 + i) * K + k0 + tx] = h;
    ol[(size_t)(n0 + i) * K + k0 + tx] = l;
  }
}

// ---------------------------------------------------------------------------
// transpose + split bf16: w[K][N] -> out[N][K] (hi, lo) bf16
// ---------------------------------------------------------------------------
__global__ __launch_bounds__(256) void transpose_split_bf16(
    const float* __restrict__ w, __nv_bfloat16* __restrict__ oh,
    __nv_bfloat16* __restrict__ ol, int K, int N)
{
  __shared__ float t[32][33];
  int n0 = blockIdx.x * 32, k0 = blockIdx.y * 32;
  int tx = threadIdx.x, ty = threadIdx.y;
#pragma unroll
  for (int i = ty; i < 32; i += 8)
    t[i][tx] = w[(size_t)(k0 + i) * N + n0 + tx];
  __syncthreads();
#pragma unroll
  for (int i = ty; i < 32; i += 8) {
    float v = t[tx][i];
    __nv_bfloat16 h = __float2bfloat16(v);
    __nv_bfloat16 l = __float2bfloat16(v - __bfloat162float(h));
    oh[(size_t)(n0 + i) * K + k0 + tx] = h;
    ol[(size_t)(n0 + i) * K + k0 + tx] = l;
  }
}

// ---------------------------------------------------------------------------
// 16-bit 3-term GEMM: 2-stage cp.async, TERM-MAJOR mma ordering (16
// independent mmas between dependent ones), 2 CTAs/SM (reg cap 128).
// CTA 128x128, 8 warps (32x64), BK=32, 80B rows.
// ---------------------------------------------------------------------------
#define GSTAGE 40960
#define GEMM_SMEM (2 * GSTAGE)

#define GEMM_BODY(T16, MMA)                                                   \
  extern __shared__ char smem[];                                              \
  const u32 sb = smem_u32(smem);                                              \
  const int tid = threadIdx.x, lane = tid & 31, wid = tid >> 5;               \
  const int m0 = blockIdx.y << 7, n0 = blockIdx.x << 7;                       \
  const int wm = wid >> 1, wn = wid & 1;                                      \
  const T16* srcs[4] = {Ah, Al, Bh, Bl};                                      \
  float acc[2][8][4] = {};                                                    \
  const int nchunks = K >> 5;                                                 \
  auto load_stage = [&](int st, int k0) {                                     \
    u32 base = sb + st * GSTAGE;                                              \
    _Pragma("unroll")                                                         \
    for (int i = 0; i < 8; ++i) {                                             \
      int idx = tid + (i << 8);                                               \
      int ten = idx >> 9, u = idx & 511;                                      \
      int row = u >> 2, q = u & 3;                                            \
      int gr = (ten < 2 ? m0 : n0) + row;                                     \
      cpasync16(base + ten * 10240 + row * 80 + q * 16,                       \
                &srcs[ten][(size_t)gr * K + k0 + q * 8]);                     \
    }                                                                         \
    CP_COMMIT();                                                              \
  };                                                                          \
  load_stage(0, 0);                                                           \
  for (int c = 0; c < nchunks; ++c) {                                         \
    const bool pf = (c + 1 < nchunks);                                        \
    if (pf) load_stage((c + 1) & 1, (c + 1) << 5);                            \
    if (pf) asm volatile("cp.async.wait_group 1;" ::: "memory");              \
    else    asm volatile("cp.async.wait_group 0;" ::: "memory");              \
    __syncthreads();                                                          \
    const u32 base = sb + (c & 1) * GSTAGE;                                   \
    const u32 aA = base, aAl = base + 10240, aB = base + 20480,               \
              aBl = base + 30720;                                             \
    _Pragma("unroll")                                                         \
    for (int ks = 0; ks < 32; ks += 16) {                                     \
      const int arow = lane & 15, asel = lane >> 4;                           \
      u32 ah[2][4], al[2][4];                                                 \
      _Pragma("unroll")                                                       \
      for (int mt = 0; mt < 2; ++mt) {                                        \
        u32 off = (u32)((wm * 32 + mt * 16 + arow) * 80 +                     \
                        (ks + asel * 8) * 2);                                 \
        LDSM4(ah[mt], aA + off);                                              \
        LDSM4(al[mt], aAl + off);                                             \
      }                                                                       \
      const int nrow = (lane & 7) + ((lane >> 4) << 3);                       \
      const int koff = ks + (((lane >> 3) & 1) << 3);                         \
      u32 bh[4][4], bl[4][4];                                                 \
      _Pragma("unroll")                                                       \
      for (int ng = 0; ng < 4; ++ng) {                                        \
        u32 off = (u32)((wn * 64 + ng * 16 + nrow) * 80 + koff * 2);          \
        LDSM4(bh[ng], aB + off);                                              \
        LDSM4(bl[ng], aBl + off);                                             \
      }                                                                       \
      /* term-major: all h.h, then all h.l, then all l.h (per-acc order kept) */ \
      _Pragma("unroll")                                                       \
      for (int mt = 0; mt < 2; ++mt)                                          \
        _Pragma("unroll")                                                     \
        for (int nt = 0; nt < 8; ++nt) {                                      \
          const int ng = nt >> 1, sel = (nt & 1) << 1;                        \
          MMA(acc[mt][nt], ah[mt], bh[ng][sel], bh[ng][sel + 1]);             \
        }                                                                     \
      _Pragma("unroll")                                                       \
      for (int mt = 0; mt < 2; ++mt)                                          \
        _Pragma("unroll")                                                     \
        for (int nt = 0; nt < 8; ++nt) {                                      \
          const int ng = nt >> 1, sel = (nt & 1) << 1;                        \
          MMA(acc[mt][nt], ah[mt], bl[ng][sel], bl[ng][sel + 1]);             \
        }                                                                     \
      _Pragma("unroll")                                                       \
      for (int mt = 0; mt < 2; ++mt)                                          \
        _Pragma("unroll")                                                     \
        for (int nt = 0; nt < 8; ++nt) {                                      \
          const int ng = nt >> 1, sel = (nt & 1) << 1;                        \
          MMA(acc[mt][nt], al[mt], bh[ng][sel], bh[ng][sel + 1]);             \
        }                                                                     \
    }                                                                         \
    __syncthreads();                                                          \
  }                                                                           \
  const int rbase = m0 + wm * 32 + (lane >> 2);                               \
  const int cbase = n0 + wn * 64 + ((lane & 3) << 1);                         \
  _Pragma("unroll")                                                           \
  for (int mt = 0; mt < 2; ++mt)                                              \
    _Pragma("unroll")                                                         \
    for (int nt = 0; nt < 8; ++nt) {                                          \
      int row = rbase + mt * 16;                                              \
      int col = cbase + nt * 8;                                               \
      float b0 = bias[col], b1 = bias[col + 1];                               \
      *(float2*)&C[(size_t)row * N + col] =                                   \
          make_float2(acc[mt][nt][0] + b0, acc[mt][nt][1] + b1);              \
      *(float2*)&C[(size_t)(row + 8) * N + col] =                             \
          make_float2(acc[mt][nt][2] + b0, acc[mt][nt][3] + b1);              \
    }

__global__ __launch_bounds__(256, 2) void gemm_f16(
    const __half* __restrict__ Ah, const __half* __restrict__ Al,
    const __half* __restrict__ Bh, const __half* __restrict__ Bl,
    const float* __restrict__ bias, float* __restrict__ C,
    int M, int N, int K)
{
  GEMM_BODY(__half, mma_f16)
}

__global__ __launch_bounds__(256, 2) void gemm_bf16(
    const __nv_bfloat16* __restrict__ Ah, const __nv_bfloat16* __restrict__ Al,
    const __nv_bfloat16* __restrict__ Bh, const __nv_bfloat16* __restrict__ Bl,
    const float* __restrict__ bias, float* __restrict__ C,
    int M, int N, int K)
{
  GEMM_BODY(__nv_bfloat16, mma_bf16)
}

// ---------------------------------------------------------------------------
// Normalize q,k + split:
//   qkv[t][3C] -> Qh/Ql, Kh/Kl [h][t][d] fp16; Vbh/Vbl [h][d][t] bf16
// ---------------------------------------------------------------------------
__global__ __launch_bounds__(256) void norm_split(
    const float* __restrict__ qkv,
    __half* __restrict__ Qh, __half* __restrict__ Ql,
    __half* __restrict__ Kh, __half* __restrict__ Kl,
    __nv_bfloat16* __restrict__ Vbh, __nv_bfloat16* __restrict__ Vbl)
{
  __shared__ float Qs[64 * 68];
  __shared__ float Ks[64 * 68];
  __shared__ float invq[64], invk[64];
  const unsigned FULL = 0xffffffffu;
  const int h = blockIdx.y;
  const int t0 = blockIdx.x << 6;
  const int tid = threadIdx.x;

#pragma unroll
  for (int it = 0; it < 4; ++it) {
    int idx = tid + it * 256;
    int r = idx >> 4, c4 = (idx & 15) << 2;
    size_t base = (size_t)(t0 + r) * K3 + h * HD + c4;
    *(float4*)&Qs[r * 68 + c4] = *(const float4*)&qkv[base];
    *(float4*)&Ks[r * 68 + c4] = *(const float4*)&qkv[base + CDIM];
  }
  __syncthreads();

  {
    int row = tid >> 2, seg = tid & 3;
    float sq = 0.f, sk = 0.f;
#pragma unroll
    for (int i = 0; i < 16; ++i) {
      float a = Qs[row * 68 + seg * 16 + i];
      float b = Ks[row * 68 + seg * 16 + i];
      sq = fmaf(a, a, sq);
      sk = fmaf(b, b, sk);
    }
    sq += __shfl_xor_sync(FULL, sq, 1);
    sq += __shfl_xor_sync(FULL, sq, 2);
    sk += __shfl_xor_sync(FULL, sk, 1);
    sk += __shfl_xor_sync(FULL, sk, 2);
    if (seg == 0) {
      invq[row] = 1.0f / fmaxf(sqrtf(sq), 1e-12f);
      invk[row] = 1.0f / fmaxf(sqrtf(sk), 1e-12f);
    }
  }
  __syncthreads();

  {
    int r = tid >> 2, cseg = (tid & 3) << 4;
    float iq = invq[r], ik = invk[r];
    size_t ob = ((size_t)h * T_SEQ + t0 + r) * HD + cseg;
#pragma unroll
    for (int j = 0; j < 4; ++j) {
      float4 qv = *(float4*)&Qs[r * 68 + cseg + 4 * j];
      float4 kv = *(float4*)&Ks[r * 68 + cseg + 4 * j];
      float q0 = qv.x * iq, q1 = qv.y * iq, q2 = qv.z * iq, q3 = qv.w * iq;
      float k0 = kv.x * ik, k1 = kv.y * ik, k2 = kv.z * ik, k3 = kv.w * ik;
      __half2 qh2a(__float2half(q0), __float2half(q1));
      __half2 qh2b(__float2half(q2), __float2half(q3));
      __half2 ql2a(__float2half(q0 - __half2float(qh2a.x)),
                   __float2half(q1 - __half2float(qh2a.y)));
      __half2 ql2b(__float2half(q2 - __half2float(qh2b.x)),
                   __float2half(q3 - __half2float(qh2b.y)));
      __half2 kh2a(__float2half(k0), __float2half(k1));
      __half2 kh2b(__float2half(k2), __float2half(k3));
      __half2 kl2a(__float2half(k0 - __half2float(kh2a.x)),
                   __float2half(k1 - __half2float(kh2a.y)));
      __half2 kl2b(__float2half(k2 - __half2float(kh2b.x)),
                   __float2half(k3 - __half2float(kh2b.y)));
      *(__half2*)&Qh[ob + 4 * j]     = qh2a;
      *(__half2*)&Qh[ob + 4 * j + 2] = qh2b;
      *(__half2*)&Ql[ob + 4 * j]     = ql2a;
      *(__half2*)&Ql[ob + 4 * j + 2] = ql2b;
      *(__half2*)&Kh[ob + 4 * j]     = kh2a;
      *(__half2*)&Kh[ob + 4 * j + 2] = kh2b;
      *(__half2*)&Kl[ob + 4 * j]     = kl2a;
      *(__half2*)&Kl[ob + 4 * j + 2] = kl2b;
    }
  }
  __syncthreads();

  // Stage V, then write transposed bf16 hi/lo [h][d][t]
#pragma unroll
  for (int it = 0; it < 4; ++it) {
    int idx = tid + it * 256;
    int r = idx >> 4, c4 = (idx & 15) << 2;
    size_t base = (size_t)(t0 + r) * K3 + h * HD + 2 * CDIM + c4;
    *(float4*)&Qs[r * 68 + c4] = *(const float4*)&qkv[base];
  }
  __syncthreads();
  {
    int d = tid >> 2, tseg = (tid & 3) << 4;
    size_t vb = ((size_t)h * HD + d) * T_SEQ + t0 + tseg;
#pragma unroll
    for (int j = 0; j < 4; ++j) {
      float v0 = Qs[(tseg + 4 * j + 0) * 68 + d];
      float v1 = Qs[(tseg + 4 * j + 1) * 68 + d];
      float v2 = Qs[(tseg + 4 * j + 2) * 68 + d];
      float v3 = Qs[(tseg + 4 * j + 3) * 68 + d];
      __nv_bfloat162 h01, h23, l01, l23;
      h01.x = __float2bfloat16(v0); l01.x = __float2bfloat16(v0 - __bfloat162float(h01.x));
      h01.y = __float2bfloat16(v1); l01.y = __float2bfloat16(v1 - __bfloat162float(h01.y));
      h23.x = __float2bfloat16(v2); l23.x = __float2bfloat16(v2 - __bfloat162float(h23.x));
      h23.y = __float2bfloat16(v3); l23.y = __float2bfloat16(v3 - __bfloat162float(h23.y));
      *(__nv_bfloat162*)&Vbh[vb + 4 * j]     = h01;
      *(__nv_bfloat162*)&Vbh[vb + 4 * j + 2] = h23;
      *(__nv_bfloat162*)&Vbl[vb + 4 * j]     = l01;
      *(__nv_bfloat162*)&Vbl[vb + 4 * j + 2] = l23;
    }
  }
}

// ---------------------------------------------------------------------------
// Tensorized cumulative linear attention (fp16x3 S-phase).
// Grid (T/128, H), 256 thr (8 warps x 16 q-rows). 32-key tiles, 2-stage
// cp.async, one syncthreads per tile, register-only W repack.
// Phase A now uses SPLIT accumulators (S_a: h.h; S_b: h.l + l.h) for 8-way
// mma ILP; combined after the kc loop.
// Stage: Kh/Kl 32x144B fp16, Vh/Vl 64x80B bf16 = 19456B x2.
// ---------------------------------------------------------------------------
#define ATT_STAGE 19456
#define ATT_SMEM  (2 * ATT_STAGE)   // 38912

__global__ __launch_bounds__(256, 2) void attn_mma(
    const __half* __restrict__ Qh_, const __half* __restrict__ Ql_,
    const __half* __restrict__ Kh_, const __half* __restrict__ Kl_,
    const __nv_bfloat16* __restrict__ Vh_, const __nv_bfloat16* __restrict__ Vl_,
    __nv_bfloat16* __restrict__ Yh_, __nv_bfloat16* __restrict__ Yl_)
{
  extern __shared__ char smem[];
  const u32 sb = smem_u32(smem);
  const unsigned FULL = 0xffffffffu;
  const int h = blockIdx.y, q0 = blockIdx.x << 7;
  const int tid = threadIdx.x, lane = tid & 31, w = tid >> 5;
  const int g = lane >> 2, qd = lane & 3;

  // ---- Q fragments (one-time, fp16 m16n8k16 A layout from gmem) ----
  const u32* Qh32 = (const u32*)(Qh_ + ((size_t)h * T_SEQ + q0 + w * 16) * HD);
  const u32* Ql32 = (const u32*)(Ql_ + ((size_t)h * T_SEQ + q0 + w * 16) * HD);
  u32 qfh[4][4], qfl[4][4];
#pragma unroll
  for (int kc = 0; kc < 4; ++kc) {
    int c0 = kc * 8 + qd;
    qfh[kc][0] = Qh32[g * 32 + c0];       qfh[kc][1] = Qh32[(g + 8) * 32 + c0];
    qfh[kc][2] = Qh32[g * 32 + c0 + 4];   qfh[kc][3] = Qh32[(g + 8) * 32 + c0 + 4];
    qfl[kc][0] = Ql32[g * 32 + c0];       qfl[kc][1] = Ql32[(g + 8) * 32 + c0];
    qfl[kc][2] = Ql32[g * 32 + c0 + 4];   qfl[kc][3] = Ql32[(g + 8) * 32 + c0 + 4];
  }

  // 256-thread stage loader: K 512 chunks + V 512 chunks, 4 per thread
  auto load_stage = [&](int st, int k0) {
    u32 base = sb + st * ATT_STAGE;
#pragma unroll
    for (int i = 0; i < 2; ++i) {
      int idx = tid + (i << 8);            // 0..511
      int ten = idx >> 8, u = idx & 255;   // 32 rows x 8 x 16B per tensor
      int row = u >> 3, q8 = u & 7;
      const __half* src = (ten ? Kl_ : Kh_) +
          ((size_t)h * T_SEQ + k0 + row) * HD + q8 * 8;
      cpasync16(base + ten * 4608 + row * 144 + q8 * 16, src);
    }
#pragma unroll
    for (int i = 0; i < 2; ++i) {
      int idx = tid + (i << 8);            // 0..511
      int ten = idx >> 8, u = idx & 255;   // 64 rows x 4 x 16B per tensor
      int row = u >> 2, q4 = u & 3;
      const __nv_bfloat16* src = (ten ? Vl_ : Vh_) +
          ((size_t)h * HD + row) * T_SEQ + k0 + q4 * 8;
      cpasync16(base + 9216 + ten * 5120 + row * 80 + q4 * 16, src);
    }
    CP_COMMIT();
  };

  // lane-dependent ldmatrix offsets
  const u32 k_lane = (u32)(((lane & 7) + ((lane >> 4) << 3)) * 144
                           + ((lane >> 3) & 1) * 16);
  const u32 v_lane = (u32)(((lane & 7) + ((lane >> 4) & 1) * 8) * 80
                           + ((lane >> 3) & 1) * 16);

  float Yacc[8][4] = {};
  float carry0 = 0.f, carry1 = 0.f;

  load_stage(0, 0);

  for (int c = 0; c < T_SEQ / 32; ++c) {
    asm volatile("cp.async.wait_group 0;" ::: "memory");
    __syncthreads();
    if (c + 1 < T_SEQ / 32) load_stage((c + 1) & 1, (c + 1) * 32);

    const u32 st = sb + (c & 1) * ATT_STAGE;

    // ---- Phase A: S = Q K^T (fp16x3, split accumulators, 8-way ILP) ----
    float Sa[4][4] = {};   // Qh*Kh
    float Sb[4][4] = {};   // Qh*Kl + Ql*Kh
#pragma unroll
    for (int kc = 0; kc < 4; ++kc) {
      u32 kh0[4], kh1[4], kl0[4], kl1[4];
      u32 ka = st + kc * 32 + k_lane;
      LDSM4(kh0, ka);                       // keys 0-15
      LDSM4(kh1, ka + 16 * 144);            // keys 16-31
      LDSM4(kl0, ka + 4608);
      LDSM4(kl1, ka + 4608 + 16 * 144);
      mma_f16(Sa[0], qfh[kc], kh0[0], kh0[1]);
      mma_f16(Sa[1], qfh[kc], kh0[2], kh0[3]);
      mma_f16(Sa[2], qfh[kc], kh1[0], kh1[1]);
      mma_f16(Sa[3], qfh[kc], kh1[2], kh1[3]);
      mma_f16(Sb[0], qfh[kc], kl0[0], kl0[1]);
      mma_f16(Sb[1], qfh[kc], kl0[2], kl0[3]);
      mma_f16(Sb[2], qfh[kc], kl1[0], kl1[1]);
      mma_f16(Sb[3], qfh[kc], kl1[2], kl1[3]);
      mma_f16(Sb[0], qfl[kc], kh0[0], kh0[1]);
      mma_f16(Sb[1], qfl[kc], kh0[2], kh0[3]);
      mma_f16(Sb[2], qfl[kc], kh1[0], kh1[1]);
      mma_f16(Sb[3], qfl[kc], kh1[2], kh1[3]);
    }
#pragma unroll
    for (int i = 0; i < 4; ++i)
#pragma unroll
      for (int e = 0; e < 4; ++e) Sa[i][e] += Sb[i][e];

    // ---- Scan on fragments: independent quad scans + prefix combine.
    //      W packed DIRECTLY into Phase-B A-fragments (C-frag == A-frag). ----
    u32 Wh[2][4], Wl[2][4];
#pragma unroll
    for (int half = 0; half < 2; ++half) {
      float bb = half ? carry1 : carry0;
      float run[4], tot[4];
#pragma unroll
      for (int nf = 0; nf < 4; ++nf) {
        float s0 = Sa[nf][half * 2], s1 = Sa[nf][half * 2 + 1];
        float r = s0 + s1;
        float n1 = __shfl_up_sync(FULL, r, 1, 4); if (qd >= 1) r += n1;
        float n2 = __shfl_up_sync(FULL, r, 2, 4); if (qd >= 2) r += n2;
        run[nf] = r;
        tot[nf] = __shfl_sync(FULL, r, 3, 4);
      }
      float base[4];
      base[0] = bb;
      base[1] = base[0] + tot[0];
      base[2] = base[1] + tot[1];
      base[3] = base[2] + tot[2];
      bb = base[3] + tot[3];
#pragma unroll
      for (int nf = 0; nf < 4; ++nf) {
        float s1 = Sa[nf][half * 2 + 1];
        float s0 = Sa[nf][half * 2];
        float cum1 = base[nf] + run[nf];
        float cum0 = cum1 - s1;
        float w0 = __fdividef(s0, fmaxf(cum0, 1e-6f));
        float w1 = __fdividef(s1, fmaxf(cum1, 1e-6f));
        u32 hw = packbf2(w0, w1);
        __nv_bfloat162 hv = *(__nv_bfloat162*)&hw;
        u32 lw = packbf2(w0 - __bfloat162float(hv.x),
                         w1 - __bfloat162float(hv.y));
        Wh[nf >> 1][((nf & 1) << 1) | half] = hw;
        Wl[nf >> 1][((nf & 1) << 1) | half] = lw;
      }
      if (half) carry1 = bb; else carry0 = bb;
    }

    // ---- Phase B: Y += W @ V (bf16x3, W fragments straight from registers) ----
    const u32 vst = st + 9216;
#pragma unroll
    for (int ks = 0; ks < 2; ++ks) {
#pragma unroll
      for (int ng = 0; ng < 4; ++ng) {
        u32 vh[4], vl[4];
        u32 va = vst + ng * 1280 + v_lane + ks * 32;
        LDSM4(vh, va);
        LDSM4(vl, va + 5120);
#pragma unroll
        for (int s = 0; s < 2; ++s) {
          int nf = ng * 2 + s;
          mma_bf16(Yacc[nf], Wh[ks], vh[s * 2], vh[s * 2 + 1]);
          mma_bf16(Yacc[nf], Wh[ks], vl[s * 2], vl[s * 2 + 1]);
          mma_bf16(Yacc[nf], Wl[ks], vh[s * 2], vh[s * 2 + 1]);
        }
      }
    }
  }

  // ---- Epilogue: split Y to bf16 hi/lo, store [t][C] ----
  const int row0 = q0 + w * 16 + g;
  const int colb = h * HD + 2 * qd;
#pragma unroll
  for (int nf = 0; nf < 8; ++nf) {
    int col = colb + nf * 8;
    size_t o0 = (size_t)row0 * CDIM + col;
    size_t o1 = (size_t)(row0 + 8) * CDIM + col;
    __nv_bfloat162 h2, l2;
    h2.x = __float2bfloat16(Yacc[nf][0]);
    l2.x = __float2bfloat16(Yacc[nf][0] - __bfloat162float(h2.x));
    h2.y = __float2bfloat16(Yacc[nf][1]);
    l2.y = __float2bfloat16(Yacc[nf][1] - __bfloat162float(h2.y));
    *(__nv_bfloat162*)&Yh_[o0] = h2;
    *(__nv_bfloat162*)&Yl_[o0] = l2;
    h2.x = __float2bfloat16(Yacc[nf][2]);
    l2.x = __float2bfloat16(Yacc[nf][2] - __bfloat162float(h2.x));
    h2.y = __float2bfloat16(Yacc[nf][3]);
    l2.y = __float2bfloat16(Yacc[nf][3] - __bfloat162float(h2.y));
    *(__nv_bfloat162*)&Yh_[o1] = h2;
    *(__nv_bfloat162*)&Yl_[o1] = l2;
  }
}

// ---------------------------------------------------------------------------
extern "C" void kernel_launch(void* const* d_in, const int* in_sizes, int n_in,
                              void* d_out, int out_size)
{
  const float* x      = (const float*)d_in[0];
  const float* w_attn = (const float*)d_in[1];
  const float* b_attn = (const float*)d_in[2];
  const float* w_proj = (const float*)d_in[3];
  const float* b_proj = (const float*)d_in[4];
  float* out = (float*)d_out;

  float* qkv;
  __half *xh, *xl, *wah, *wal, *qh, *ql, *kh, *kl;
  __nv_bfloat16 *wph, *wpl, *vbh, *vbl, *yh, *yl;
  cudaGetSymbolAddress((void**)&qkv, g_qkv);
  cudaGetSymbolAddress((void**)&xh,  g_xh);
  cudaGetSymbolAddress((void**)&xl,  g_xl);
  cudaGetSymbolAddress((void**)&wah, g_wah);
  cudaGetSymbolAddress((void**)&wal, g_wal);
  cudaGetSymbolAddress((void**)&wph, g_wph);
  cudaGetSymbolAddress((void**)&wpl, g_wpl);
  cudaGetSymbolAddress((void**)&qh,  g_qh);
  cudaGetSymbolAddress((void**)&ql,  g_ql);
  cudaGetSymbolAddress((void**)&kh,  g_kh);
  cudaGetSymbolAddress((void**)&kl,  g_kl);
  cudaGetSymbolAddress((void**)&vbh, g_vbh);
  cudaGetSymbolAddress((void**)&vbl, g_vbl);
  cudaGetSymbolAddress((void**)&yh,  g_yh);
  cudaGetSymbolAddress((void**)&yl,  g_yl);

  cudaFuncSetAttribute(gemm_f16,
                       cudaFuncAttributeMaxDynamicSharedMemorySize, GEMM_SMEM);
  cudaFuncSetAttribute(gemm_bf16,
                       cudaFuncAttributeMaxDynamicSharedMemorySize, GEMM_SMEM);
  cudaFuncSetAttribute(attn_mma,
                       cudaFuncAttributeMaxDynamicSharedMemorySize, ATT_SMEM);

  const int n4 = T_SEQ * CDIM / 4;

  // 0) conversions
  split_f16<<<(n4 + 255) / 256, 256>>>(x, xh, xl, n4);
  transpose_split_f16<<<dim3(K3 / 32, CDIM / 32), dim3(32, 8)>>>(
      w_attn, wah, wal, CDIM, K3);
  transpose_split_bf16<<<dim3(CDIM / 32, CDIM / 32), dim3(32, 8)>>>(
      w_proj, wph, wpl, CDIM, CDIM);

  // 1) qkv = x @ w_attn + b_attn   (fp16x3, term-major, 2 CTAs/SM)
  gemm_f16<<<dim3(K3 / 128, T_SEQ / 128), 256, GEMM_SMEM>>>(
      xh, xl, wah, wal, b_attn, qkv, T_SEQ, K3, CDIM);

  // 2) normalize + split q,k (fp16) and v (bf16, transposed)
  norm_split<<<dim3(T_SEQ / 64, NHEAD), 256>>>(qkv, qh, ql, kh, kl, vbh, vbl);

  // 3) tensorized cumulative linear attention -> yh/yl bf16
  attn_mma<<<dim3(T_SEQ / 128, NHEAD), 256, ATT_SMEM>>>(
      qh, ql, kh, kl, vbh, vbl, yh, yl);

  // 4) out = y @ w_proj + b_proj  (bf16x3, term-major, 2 CTAs/SM)
  gemm_bf16<<<dim3(CDIM / 128, T_SEQ / 128), 256, GEMM_SMEM>>>(
      yh, yl, wph, wpl, b_proj, out, T_SEQ, CDIM, CDIM);
}